// round 1
// baseline (speedup 1.0000x reference)
#include <cuda_runtime.h>
#include <math.h>

#define NB 64      // images (B)
#define NR 36      // regions
#define ND 1024    // D
#define NCAP 32    // captions
#define NWD 40     // words
#define NS 256     // S
#define NPART 5
#define EPSL 1e-8f
#define BNEPS 1e-5f
#define LNEPS 1e-5f
#define SMOOTHF 9.0f

// ---------------- scratch (device globals; no allocation allowed) ----------------
__device__ float g_h[NB*NR*ND];
__device__ float g_imgave[NB*ND];
__device__ float g_bnmu[NR];
__device__ float g_bnvar[NR];
__device__ float g_g[NB*ND];                 // g -> g_emb in place
__device__ float g_wraw[NB*NR];
__device__ float g_imgglo[NB*ND];
__device__ float g_normglo[NB];
__device__ float g_imgpar[NB*NR*ND];
__device__ float g_capave[NCAP*ND];
__device__ float g_le[NCAP*NWD*ND];
__device__ float g_ge[NCAP*ND];
__device__ float g_capglo[NCAP*ND];
__device__ float g_attnraw[(size_t)NCAP*NWD*NB*NR];  // [c][n][b*36+r]
__device__ float g_attnT[(size_t)NCAP*NB*NR*NWD];    // [c][b][r][n]
__device__ float g_ctx[(size_t)NCAP*NB*NR*ND];       // 302 MB
__device__ float g_simpar[(size_t)NCAP*NB*NR*NS];    // 75 MB

// ---------------- helpers ----------------
__device__ __forceinline__ float blockReduceSum256(float v, float* red) {
    int tid = threadIdx.x;
    red[tid] = v; __syncthreads();
    #pragma unroll
    for (int s = 128; s > 0; s >>= 1) {
        if (tid < s) red[tid] += red[tid + s];
        __syncthreads();
    }
    float r = red[0]; __syncthreads();
    return r;
}

// ---------------- generic tiled SGEMM: C = act(A[MxK] @ W[KxN] + bias) ----------------
template<int ACT>
__global__ void sgemm_rr(const float* __restrict__ A, const float* __restrict__ W,
                         const float* __restrict__ bias, float* __restrict__ C,
                         int M, int N, int K)
{
    const int BM = 64, BN = 64, BK = 16;
    __shared__ float As[BK][BM];
    __shared__ float Bs[BK][BN];
    int tid = threadIdx.x;
    int tr = tid >> 4, tc = tid & 15;
    int m0 = blockIdx.y * BM, n0 = blockIdx.x * BN;
    float acc[4][4] = {};
    for (int k0 = 0; k0 < K; k0 += BK) {
        #pragma unroll
        for (int i = tid; i < BM*BK; i += 256) {
            int m = i >> 4, k = i & 15;
            As[k][m] = (m0 + m < M) ? A[(size_t)(m0+m)*K + k0 + k] : 0.f;
        }
        #pragma unroll
        for (int i = tid; i < BK*BN; i += 256) {
            int k = i >> 6, n = i & 63;
            Bs[k][n] = (n0 + n < N) ? W[(size_t)(k0+k)*N + n0 + n] : 0.f;
        }
        __syncthreads();
        #pragma unroll
        for (int k = 0; k < BK; k++) {
            float a[4], b[4];
            #pragma unroll
            for (int i = 0; i < 4; i++) a[i] = As[k][tr*4+i];
            #pragma unroll
            for (int j = 0; j < 4; j++) b[j] = Bs[k][tc*4+j];
            #pragma unroll
            for (int i = 0; i < 4; i++)
                #pragma unroll
                for (int j = 0; j < 4; j++) acc[i][j] += a[i]*b[j];
        }
        __syncthreads();
    }
    #pragma unroll
    for (int i = 0; i < 4; i++) {
        int m = m0 + tr*4 + i;
        if (m >= M) continue;
        #pragma unroll
        for (int j = 0; j < 4; j++) {
            int n = n0 + tc*4 + j;
            if (n >= N) continue;
            float v = acc[i][j] + bias[n];
            if (ACT == 1) v = tanhf(v);
            C[(size_t)m*N + n] = v;
        }
    }
}

// ---------------- batched NT GEMM: C[c] = A[c][MxK] @ B[NxK]^T (attn) ----------------
__global__ void sgemm_nt_batched(const float* __restrict__ Aall, const float* __restrict__ Bmat,
                                 float* __restrict__ Call, int M, int N, int K)
{
    const int BM = 64, BN = 64, BK = 16;
    int c = blockIdx.z;
    const float* A = Aall + (size_t)c*M*K;
    float* C = Call + (size_t)c*M*N;
    __shared__ float As[BK][BM];
    __shared__ float Bs[BK][BN];
    int tid = threadIdx.x;
    int tr = tid >> 4, tc = tid & 15;
    int m0 = blockIdx.y * BM, n0 = blockIdx.x * BN;
    float acc[4][4] = {};
    for (int k0 = 0; k0 < K; k0 += BK) {
        #pragma unroll
        for (int i = tid; i < BM*BK; i += 256) {
            int m = i >> 4, k = i & 15;
            As[k][m] = (m0 + m < M) ? A[(size_t)(m0+m)*K + k0 + k] : 0.f;
        }
        #pragma unroll
        for (int i = tid; i < BN*BK; i += 256) {
            int n = i >> 4, k = i & 15;
            Bs[k][n] = (n0 + n < N) ? Bmat[(size_t)(n0+n)*K + k0 + k] : 0.f;
        }
        __syncthreads();
        #pragma unroll
        for (int k = 0; k < BK; k++) {
            float a[4], b[4];
            #pragma unroll
            for (int i = 0; i < 4; i++) a[i] = As[k][tr*4+i];
            #pragma unroll
            for (int j = 0; j < 4; j++) b[j] = Bs[k][tc*4+j];
            #pragma unroll
            for (int i = 0; i < 4; i++)
                #pragma unroll
                for (int j = 0; j < 4; j++) acc[i][j] += a[i]*b[j];
        }
        __syncthreads();
    }
    #pragma unroll
    for (int i = 0; i < 4; i++) {
        int m = m0 + tr*4 + i;
        if (m >= M) continue;
        #pragma unroll
        for (int j = 0; j < 4; j++) {
            int n = n0 + tc*4 + j;
            if (n >= N) continue;
            C[(size_t)m*N + n] = acc[i][j];
        }
    }
}

// ---------------- diff-square GEMM: C = relu((X - Y)^2 @ W + bias) ----------------
// MODE 0: X batched per c (g_ctx), Y per-row (img_emb), store into out (c,b,1+r,s)
// MODE 1: X shared, Y per-c vector (cap_glo), store C + c*M*N
template<int MODE>
__global__ void gemm_diffsq(const float* __restrict__ X, const float* __restrict__ Y,
                            const float* __restrict__ W, const float* __restrict__ bias,
                            float* __restrict__ Cbase, int M, int N, int K)
{
    const int BM = 64, BN = 64, BK = 16;
    int c = blockIdx.z;
    const float* Xp = (MODE == 0) ? X + (size_t)c*M*K : X;
    const float* Yp = (MODE == 0) ? Y : Y + (size_t)c*K;
    __shared__ float As[BK][BM];
    __shared__ float Bs[BK][BN];
    int tid = threadIdx.x;
    int tr = tid >> 4, tc = tid & 15;
    int m0 = blockIdx.y * BM, n0 = blockIdx.x * BN;
    float acc[4][4] = {};
    for (int k0 = 0; k0 < K; k0 += BK) {
        #pragma unroll
        for (int i = tid; i < BM*BK; i += 256) {
            int m = i >> 4, k = i & 15;
            float v = 0.f;
            if (m0 + m < M) {
                size_t xi = (size_t)(m0+m)*K + k0 + k;
                float d;
                if (MODE == 0) d = Xp[xi] - Yp[xi];
                else           d = Xp[xi] - Yp[k0 + k];
                v = d * d;
            }
            As[k][m] = v;
        }
        #pragma unroll
        for (int i = tid; i < BK*BN; i += 256) {
            int k = i >> 6, n = i & 63;
            Bs[k][n] = (n0 + n < N) ? W[(size_t)(k0+k)*N + n0 + n] : 0.f;
        }
        __syncthreads();
        #pragma unroll
        for (int k = 0; k < BK; k++) {
            float a[4], b[4];
            #pragma unroll
            for (int i = 0; i < 4; i++) a[i] = As[k][tr*4+i];
            #pragma unroll
            for (int j = 0; j < 4; j++) b[j] = Bs[k][tc*4+j];
            #pragma unroll
            for (int i = 0; i < 4; i++)
                #pragma unroll
                for (int j = 0; j < 4; j++) acc[i][j] += a[i]*b[j];
        }
        __syncthreads();
    }
    #pragma unroll
    for (int i = 0; i < 4; i++) {
        int m = m0 + tr*4 + i;
        if (m >= M) continue;
        #pragma unroll
        for (int j = 0; j < 4; j++) {
            int n = n0 + tc*4 + j;
            if (n >= N) continue;
            float v = fmaxf(acc[i][j] + bias[n], 0.f);
            if (MODE == 0) {
                int b = m / NR, r = m % NR;
                Cbase[(((size_t)c*NB + b)*37 + 1 + r)*NS + n] = v;
            } else {
                Cbase[(size_t)c*M*N + (size_t)m*N + n] = v;
            }
        }
    }
}

// ---------------- small kernels ----------------
__global__ void k_imgave(const float* __restrict__ img) {
    int i = blockIdx.x*blockDim.x + threadIdx.x;   // (b,d), 65536 threads
    int b = i >> 10, d = i & 1023;
    float s = 0.f;
    for (int r = 0; r < NR; r++) s += img[((size_t)b*NR + r)*ND + d];
    g_imgave[i] = s * (1.f / NR);
}

__global__ void k_bnstats() {
    int r = blockIdx.x;
    __shared__ float red[256], red2[256];
    float s = 0.f, ss = 0.f;
    for (int i = threadIdx.x; i < NB*ND; i += 256) {
        int b = i >> 10, d = i & 1023;
        float v = g_h[((size_t)b*NR + r)*ND + d];
        s += v; ss += v*v;
    }
    red[threadIdx.x] = s; red2[threadIdx.x] = ss; __syncthreads();
    for (int st = 128; st > 0; st >>= 1) {
        if (threadIdx.x < st) { red[threadIdx.x] += red[threadIdx.x+st]; red2[threadIdx.x] += red2[threadIdx.x+st]; }
        __syncthreads();
    }
    if (threadIdx.x == 0) {
        float mu = red[0] / (float)(NB*ND);
        g_bnmu[r] = mu;
        g_bnvar[r] = red2[0] / (float)(NB*ND) - mu*mu;
    }
}

__global__ void k_gbn(const float* __restrict__ gamma, const float* __restrict__ beta) {
    int d = blockIdx.x*blockDim.x + threadIdx.x;    // 1024 threads
    float s = 0.f, ss = 0.f;
    for (int b = 0; b < NB; b++) { float v = g_g[(size_t)b*ND + d]; s += v; ss += v*v; }
    float mu = s / NB;
    float var = ss / NB - mu*mu;
    float inv = rsqrtf(var + BNEPS);
    float ga = gamma[d], be = beta[d];
    for (int b = 0; b < NB; b++) {
        float v = g_g[(size_t)b*ND + d];
        g_g[(size_t)b*ND + d] = tanhf((v - mu)*inv*ga + be);
    }
}

__global__ void k_wraw(const float* __restrict__ vcw, const float* __restrict__ vcb,
                       const float* __restrict__ lg, const float* __restrict__ lb) {
    int br = blockIdx.x;
    int b = br / NR, r = br % NR;
    __shared__ float red[256];
    float mu = g_bnmu[r], inv = rsqrtf(g_bnvar[r] + BNEPS);
    float ga = lg[r], be = lb[r];
    float s = 0.f;
    for (int d = threadIdx.x; d < ND; d += 256) {
        float le = tanhf((g_h[(size_t)br*ND + d] - mu)*inv*ga + be);
        s += le * g_g[(size_t)b*ND + d] * vcw[d];
    }
    float tot = blockReduceSum256(s, red);
    if (threadIdx.x == 0) g_wraw[br] = tot + vcb[0];
}

__global__ void k_newglobal(const float* __restrict__ img) {
    int b = blockIdx.x;
    __shared__ float w[NR];
    __shared__ float red[256];
    __shared__ float invn;
    if (threadIdx.x == 0) {
        float mx = -1e30f;
        for (int r = 0; r < NR; r++) mx = fmaxf(mx, g_wraw[b*NR + r]);
        float sum = 0.f;
        for (int r = 0; r < NR; r++) { w[r] = expf(g_wraw[b*NR + r] - mx); sum += w[r]; }
        float is = 1.f / sum;
        for (int r = 0; r < NR; r++) w[r] *= is;
    }
    __syncthreads();
    float ssq = 0.f;
    for (int d = threadIdx.x; d < ND; d += 256) {
        float s = 0.f;
        for (int r = 0; r < NR; r++) s += w[r] * img[((size_t)b*NR + r)*ND + d];
        g_imgglo[(size_t)b*ND + d] = s;
        ssq += s*s;
    }
    float tot = blockReduceSum256(ssq, red);
    if (threadIdx.x == 0) {
        float nrm = sqrtf(tot) + EPSL;
        g_normglo[b] = nrm;
        invn = 1.f / nrm;
    }
    __syncthreads();
    for (int d = threadIdx.x; d < ND; d += 256) g_imgglo[(size_t)b*ND + d] *= invn;
}

__global__ void k_imgpar(const float* __restrict__ img, const int* __restrict__ adjs) {
    int br = blockIdx.x;
    int b = br / NR, r = br % NR;
    __shared__ int eff[NPART];
    __shared__ float wg[NPART];
    if (threadIdx.x == 0) {
        int cnt = 0;
        const int* row = adjs + (size_t)b*NR*NR + (size_t)r*NR;
        for (int j = 0; j < NR && cnt < NPART; j++)
            if (row[j] == 1) eff[cnt++] = j;
        for (; cnt < NPART; cnt++) eff[cnt] = r;
        float v[NPART], mx = -1e30f;
        for (int k = 0; k < NPART; k++) { v[k] = g_wraw[b*NR + eff[k]]; mx = fmaxf(mx, v[k]); }
        float sum = 0.f;
        for (int k = 0; k < NPART; k++) { v[k] = expf(v[k] - mx); sum += v[k]; }
        float is = 1.f / sum;
        for (int k = 0; k < NPART; k++) wg[k] = v[k]*is;
    }
    __syncthreads();
    float invn = 1.f / g_normglo[b];
    for (int d = threadIdx.x; d < ND; d += 256) {
        float s = 0.f;
        #pragma unroll
        for (int k = 0; k < NPART; k++) s += wg[k] * img[((size_t)b*NR + eff[k])*ND + d];
        g_imgpar[(size_t)br*ND + d] = s * invn;
    }
}

__global__ void k_capave(const float* __restrict__ cap) {
    int i = blockIdx.x*blockDim.x + threadIdx.x;  // (c,d), 32768 threads
    int c = i >> 10, d = i & 1023;
    float s = 0.f;
    for (int n = 0; n < NWD; n++) s += cap[((size_t)c*NWD + n)*ND + d];
    g_capave[i] = s * (1.f / NWD);
}

__global__ void k_capglo(const float* __restrict__ cap, const float* __restrict__ tsacw,
                         const float* __restrict__ tsacb) {
    int c = blockIdx.x;
    __shared__ float red[256];
    __shared__ float cw[NWD];
    __shared__ float invn;
    float gw[4];
    #pragma unroll
    for (int i = 0; i < 4; i++) {
        int d = threadIdx.x + i*256;
        gw[i] = g_ge[(size_t)c*ND + d] * tsacw[d];
    }
    for (int n = 0; n < NWD; n++) {
        float s = 0.f;
        #pragma unroll
        for (int i = 0; i < 4; i++) {
            int d = threadIdx.x + i*256;
            s += g_le[((size_t)c*NWD + n)*ND + d] * gw[i];
        }
        float tot = blockReduceSum256(s, red);
        if (threadIdx.x == 0) cw[n] = tot + tsacb[0];
    }
    __syncthreads();
    if (threadIdx.x == 0) {
        float mx = -1e30f;
        for (int n = 0; n < NWD; n++) mx = fmaxf(mx, cw[n]);
        float sum = 0.f;
        for (int n = 0; n < NWD; n++) { cw[n] = expf(cw[n] - mx); sum += cw[n]; }
        float is = 1.f / sum;
        for (int n = 0; n < NWD; n++) cw[n] *= is;
    }
    __syncthreads();
    float ssq = 0.f;
    #pragma unroll
    for (int i = 0; i < 4; i++) {
        int d = threadIdx.x + i*256;
        float s = 0.f;
        for (int n = 0; n < NWD; n++) s += cw[n] * cap[((size_t)c*NWD + n)*ND + d];
        g_capglo[(size_t)c*ND + d] = s;
        ssq += s*s;
    }
    float tot = blockReduceSum256(ssq, red);
    if (threadIdx.x == 0) invn = 1.f / (sqrtf(tot) + EPSL);
    __syncthreads();
    #pragma unroll
    for (int i = 0; i < 4; i++) {
        int d = threadIdx.x + i*256;
        g_capglo[(size_t)c*ND + d] *= invn;
    }
}

// leaky-relu, l2norm over r per (n), softmax over n per (r); raw[c][n][b*36+r] -> attnT[c][b][r][n]
__global__ void k_attnfuse() {
    int cb = blockIdx.x;
    int c = cb / NB, b = cb % NB;
    __shared__ float sA[NWD*NR];   // [n][r]
    __shared__ float nrm[NWD];
    const float* raw = g_attnraw + (size_t)c*NWD*NB*NR;
    for (int i = threadIdx.x; i < NWD*NR; i += 256) {
        int n = i / NR, r = i % NR;
        float v = raw[(size_t)n*NB*NR + (size_t)b*NR + r];
        v = (v > 0.f) ? v : 0.1f*v;
        sA[i] = v;
    }
    __syncthreads();
    if (threadIdx.x < NWD) {
        int n = threadIdx.x;
        float s = 0.f;
        for (int r = 0; r < NR; r++) { float v = sA[n*NR + r]; s += v*v; }
        nrm[n] = 1.f / (sqrtf(s) + EPSL);
    }
    __syncthreads();
    if (threadIdx.x < NR) {
        int r = threadIdx.x;
        float vals[NWD];
        float mx = -1e30f;
        for (int n = 0; n < NWD; n++) {
            float v = SMOOTHF * sA[n*NR + r] * nrm[n];
            vals[n] = v;
            mx = fmaxf(mx, v);
        }
        float sum = 0.f;
        for (int n = 0; n < NWD; n++) { vals[n] = expf(vals[n] - mx); sum += vals[n]; }
        float is = 1.f / sum;
        float* outp = g_attnT + ((size_t)cb*NR + r)*NWD;
        for (int n = 0; n < NWD; n++) outp[n] = vals[n]*is;
    }
}

// ctx[c,b,r,:] = attnT[c,b,r,:] @ cap[c]
__global__ void k_ctx(const float* __restrict__ cap) {
    int cb = blockIdx.x;
    int c = cb / NB;
    __shared__ float sT[NR*NWD];    // [r][n]
    const float* at = g_attnT + (size_t)cb*NR*NWD;
    for (int i = threadIdx.x; i < NR*NWD; i += 256) sT[i] = at[i];
    __syncthreads();
    float* outp = g_ctx + (size_t)cb*NR*ND;
    for (int it = 0; it < 4; it++) {
        int d = threadIdx.x + it*256;
        float acc[NR];
        #pragma unroll
        for (int r = 0; r < NR; r++) acc[r] = 0.f;
        for (int n = 0; n < NWD; n++) {
            float cv = cap[((size_t)c*NWD + n)*ND + d];
            #pragma unroll
            for (int r = 0; r < NR; r++) acc[r] += sT[r*NWD + n] * cv;
        }
        for (int r = 0; r < NR; r++) outp[(size_t)r*ND + d] = acc[r];
    }
}

__global__ void k_rownorm(float* __restrict__ X, int L) {
    size_t row = blockIdx.x;
    float* p = X + row*(size_t)L;
    __shared__ float red[256];
    __shared__ float invn;
    float s = 0.f;
    for (int i = threadIdx.x; i < L; i += 256) { float v = p[i]; s += v*v; }
    float tot = blockReduceSum256(s, red);
    if (threadIdx.x == 0) invn = 1.f / (sqrtf(tot) + EPSL);
    __syncthreads();
    for (int i = threadIdx.x; i < L; i += 256) p[i] *= invn;
}

__global__ void k_rownorm_simloc(float* __restrict__ out) {
    int row = blockIdx.x;               // c*NB*NR + b*NR + r
    int cb = row / NR, r = row % NR;
    float* p = out + ((size_t)cb*37 + 1 + r)*NS;
    __shared__ float red[256];
    __shared__ float invn;
    float v = p[threadIdx.x];
    float tot = blockReduceSum256(v*v, red);
    if (threadIdx.x == 0) invn = 1.f / (sqrtf(tot) + EPSL);
    __syncthreads();
    p[threadIdx.x] = v * invn;
}

__global__ void k_finalize(const float* __restrict__ simw, const float* __restrict__ simb,
                           const float* __restrict__ lng, const float* __restrict__ lnb,
                           float* __restrict__ out, size_t out2off) {
    int cb = blockIdx.x;
    int tid = threadIdx.x;
    const float* sg = out + out2off + (size_t)cb*NS;
    __shared__ float red[256];
    __shared__ float wv[NR];
    __shared__ float mv[2];
    float sgv = sg[tid];
    float sgw = sgv * simw[tid];
    const float* sp = g_simpar + (size_t)cb*NR*NS;
    for (int r = 0; r < NR; r++) {
        float tot = blockReduceSum256(sp[(size_t)r*NS + tid] * sgw, red);
        if (tid == 0) wv[r] = tot + simb[0];
    }
    __syncthreads();
    if (tid == 0) {
        float m = 0.f;
        for (int r = 0; r < NR; r++) m += wv[r];
        m /= NR;
        float v = 0.f;
        for (int r = 0; r < NR; r++) { float d = wv[r] - m; v += d*d; }
        v /= NR;
        mv[0] = m; mv[1] = rsqrtf(v + LNEPS);
    }
    __syncthreads();
    if (tid < NR) {
        int r = tid;
        float z = (wv[r] - mv[0])*mv[1]*lng[r] + lnb[r];
        wv[r] = 1.f / (1.f + expf(-z));
    }
    __syncthreads();
    float* ob = out + (size_t)cb*37*NS;
    ob[tid] = sgv;                                   // sim_emb[...,0,:] = sim_glo
    for (int r = 0; r < NR; r++) ob[(size_t)(1+r)*NS + tid] *= wv[r];
}

// ---------------- host ----------------
extern "C" void kernel_launch(void* const* d_in, const int* in_sizes, int n_in,
                              void* d_out, int out_size) {
    (void)in_sizes; (void)n_in; (void)out_size;
    const float* img    = (const float*)d_in[0];
    const float* cap    = (const float*)d_in[1];
    const int*   adjs   = (const int*)d_in[3];
    const float* tsa_lw = (const float*)d_in[5];
    const float* tsa_lb = (const float*)d_in[6];
    const float* tsa_gw = (const float*)d_in[7];
    const float* tsa_gb = (const float*)d_in[8];
    const float* tsa_cw = (const float*)d_in[9];
    const float* tsa_cb = (const float*)d_in[10];
    const float* vl_w   = (const float*)d_in[11];
    const float* vl_b   = (const float*)d_in[12];
    const float* vbn_lg = (const float*)d_in[13];
    const float* vbn_lb = (const float*)d_in[14];
    const float* vg_w   = (const float*)d_in[15];
    const float* vg_b   = (const float*)d_in[16];
    const float* vbn_gg = (const float*)d_in[17];
    const float* vbn_gb = (const float*)d_in[18];
    const float* vc_w   = (const float*)d_in[19];
    const float* vc_b   = (const float*)d_in[20];
    const float* loc_w  = (const float*)d_in[21];
    const float* loc_b  = (const float*)d_in[22];
    const float* par_w  = (const float*)d_in[23];
    const float* par_b  = (const float*)d_in[24];
    const float* glo_w  = (const float*)d_in[25];
    const float* glo_b  = (const float*)d_in[26];
    const float* sim_w  = (const float*)d_in[27];
    const float* sim_b  = (const float*)d_in[28];
    const float* ln_g   = (const float*)d_in[29];
    const float* ln_b   = (const float*)d_in[30];
    float* out = (float*)d_out;

    static bool inited = false;
    static float *p_h, *p_imgave, *p_g, *p_capave, *p_le, *p_ge, *p_attnraw,
                 *p_ctx, *p_imgpar, *p_imgglo, *p_capglo, *p_simpar;
    if (!inited) {
        cudaGetSymbolAddress((void**)&p_h, g_h);
        cudaGetSymbolAddress((void**)&p_imgave, g_imgave);
        cudaGetSymbolAddress((void**)&p_g, g_g);
        cudaGetSymbolAddress((void**)&p_capave, g_capave);
        cudaGetSymbolAddress((void**)&p_le, g_le);
        cudaGetSymbolAddress((void**)&p_ge, g_ge);
        cudaGetSymbolAddress((void**)&p_attnraw, g_attnraw);
        cudaGetSymbolAddress((void**)&p_ctx, g_ctx);
        cudaGetSymbolAddress((void**)&p_imgpar, g_imgpar);
        cudaGetSymbolAddress((void**)&p_imgglo, g_imgglo);
        cudaGetSymbolAddress((void**)&p_capglo, g_capglo);
        cudaGetSymbolAddress((void**)&p_simpar, g_simpar);
        inited = true;
    }

    const size_t out2off = (size_t)NCAP*NB*37*NS;
    float* out2 = out + out2off;

    // ---- caption-independent ----
    k_imgave<<<256, 256>>>(img);
    sgemm_rr<0><<<dim3(16, 36), 256>>>(img, vl_w, vl_b, p_h, NB*NR, ND, ND);
    k_bnstats<<<NR, 256>>>();
    sgemm_rr<0><<<dim3(16, 1), 256>>>(p_imgave, vg_w, vg_b, p_g, NB, ND, ND);
    k_gbn<<<4, 256>>>(vbn_gg, vbn_gb);
    k_wraw<<<NB*NR, 256>>>(vc_w, vc_b, vbn_lg, vbn_lb);
    k_newglobal<<<NB, 256>>>(img);
    k_imgpar<<<NB*NR, 256>>>(img, adjs);

    // ---- caption side ----
    k_capave<<<128, 256>>>(cap);
    sgemm_rr<1><<<dim3(16, 20), 256>>>(cap, tsa_lw, tsa_lb, p_le, NCAP*NWD, ND, ND);
    sgemm_rr<1><<<dim3(16, 1), 256>>>(p_capave, tsa_gw, tsa_gb, p_ge, NCAP, ND, ND);
    k_capglo<<<NCAP, 256>>>(cap, tsa_cw, tsa_cb);

    sgemm_nt_batched<<<dim3(36, 1, NCAP), 256>>>(cap, img, p_attnraw, NWD, NB*NR, ND);
    k_attnfuse<<<NCAP*NB, 256>>>();
    k_ctx<<<NCAP*NB, 256>>>(cap);
    k_rownorm<<<NCAP*NB*NR, 256>>>(p_ctx, ND);

    // ---- heavy diff-square GEMMs ----
    gemm_diffsq<0><<<dim3(4, 36, NCAP), 256>>>(p_ctx, img, loc_w, loc_b, out, NB*NR, NS, ND);
    k_rownorm_simloc<<<NCAP*NB*NR, 256>>>(out);
    gemm_diffsq<1><<<dim3(4, 36, NCAP), 256>>>(p_imgpar, p_capglo, par_w, par_b, p_simpar, NB*NR, NS, ND);
    k_rownorm<<<NCAP*NB*NR, 256>>>(p_simpar, NS);
    gemm_diffsq<1><<<dim3(4, 1, NCAP), 256>>>(p_imgglo, p_capglo, glo_w, glo_b, out2, NB, NS, ND);
    k_rownorm<<<NCAP*NB, 256>>>(out2, NS);

    // ---- wts + layernorm + sigmoid + scale + assemble ----
    k_finalize<<<NCAP*NB, 256>>>(sim_w, sim_b, ln_g, ln_b, out, out2off);
}

// round 2
// speedup vs baseline: 1.8479x; 1.8479x over previous
#include <cuda_runtime.h>
#include <math.h>

#define NB 64      // images (B)
#define NR 36      // regions
#define ND 1024    // D
#define NCAP 32    // captions
#define NWD 40     // words
#define NS 256     // S
#define NPART 5
#define EPSL 1e-8f
#define BNEPS 1e-5f
#define LNEPS 1e-5f
#define SMOOTHF 9.0f

typedef unsigned long long ull;

// ---------------- scratch (device globals; no allocation allowed) ----------------
__device__ float g_h[NB*NR*ND];
__device__ float g_imgave[NB*ND];
__device__ float g_bnmu[NR];
__device__ float g_bnvar[NR];
__device__ float g_g[NB*ND];
__device__ float g_wraw[NB*NR];
__device__ float g_imgglo[NB*ND];
__device__ float g_normglo[NB];
__device__ float g_imgpar[NB*NR*ND];
__device__ float g_capave[NCAP*ND];
__device__ float g_le[NCAP*NWD*ND];
__device__ float g_ge[NCAP*ND];
__device__ float g_capglo[NCAP*ND];
__device__ float g_attnraw[(size_t)NCAP*NWD*NB*NR];  // [(c*40+n)][b*36+r]
__device__ float g_attnT[(size_t)NCAP*NB*NR*NWD];    // [c][b][r][n]
__device__ float g_ctx[(size_t)NCAP*NB*NR*ND];
__device__ float g_simpar[(size_t)NCAP*NB*NR*NS];
__device__ float g_part[8*64*1024];                  // split-K partials

// ---------------- helpers ----------------
__device__ __forceinline__ float blockReduceSum256(float v, float* red) {
    int tid = threadIdx.x;
    red[tid] = v; __syncthreads();
    #pragma unroll
    for (int s = 128; s > 0; s >>= 1) {
        if (tid < s) red[tid] += red[tid + s];
        __syncthreads();
    }
    float r = red[0]; __syncthreads();
    return r;
}

__device__ __forceinline__ void ffma2(ull &c, ull a, ull b) {
    asm("fma.rn.f32x2 %0, %1, %2, %0;" : "+l"(c) : "l"(a), "l"(b));
}

__device__ __forceinline__ float2 unpack2(ull u) {
    float2 f;
    f.x = __int_as_float((int)(u & 0xffffffffull));
    f.y = __int_as_float((int)(u >> 32));
    return f;
}

// ============ high-throughput f32x2 GEMM: 128x128 tile, 8x8/thread ============
// C = act(transformA(A) @ B + bias)
// TRANSA: 0 plain; 1 (A[z]-Y)^2 with Y same-indexed (unbatched); 2 (A - Yv[z][k])^2
// BTRANS: 0 B is [K,N] row-major; 1 B is [N,K] row-major (C = A @ B^T)
// ACT: 0 none, 1 tanh, 2 relu
// SCATTER: 1 -> write to out[(((z*64+b)*37)+1+r)*256 + n] with m = b*36+r
// Requires M%128==0, N%128==0, K%16==0.
template<int TRANSA, int BTRANS, int ACT, int SCATTER>
__global__ void __launch_bounds__(256, 2)
gemm128(const float* __restrict__ A, const float* __restrict__ Y,
        const float* __restrict__ Bmat, const float* __restrict__ bias,
        float* __restrict__ C, int M, int N, int K)
{
    __shared__ float2 As[16][128];   // duplicated values (a,a)
    __shared__ float  Bs[16][128];
    int tid = threadIdx.x;
    int tr = tid >> 4, tc = tid & 15;
    int m0 = blockIdx.y * 128, n0 = blockIdx.x * 128;
    int z = blockIdx.z;
    const float* Ap = A;
    const float* Yp = Y;
    if (TRANSA == 1) Ap = A + (size_t)z*M*K;
    if (TRANSA == 2) Yp = Y + (size_t)z*K;

    ull acc[8][4];
    #pragma unroll
    for (int i = 0; i < 8; i++)
        #pragma unroll
        for (int j = 0; j < 4; j++) acc[i][j] = 0ull;

    for (int k0 = 0; k0 < K; k0 += 16) {
        // ---- load A chunk (with transform), store duplicated ----
        #pragma unroll
        for (int i = 0; i < 2; i++) {
            int idx = tid + i*256;            // 0..511
            int m  = idx >> 2;
            int kq = (idx & 3) << 2;
            size_t off = (size_t)(m0+m)*K + k0 + kq;
            float4 v = *(const float4*)(Ap + off);
            if (TRANSA == 1) {
                float4 y = *(const float4*)(Y + off);
                v.x -= y.x; v.y -= y.y; v.z -= y.z; v.w -= y.w;
            } else if (TRANSA == 2) {
                const float* yv = Yp + k0 + kq;
                v.x -= yv[0]; v.y -= yv[1]; v.z -= yv[2]; v.w -= yv[3];
            }
            if (TRANSA) { v.x *= v.x; v.y *= v.y; v.z *= v.z; v.w *= v.w; }
            As[kq+0][m] = make_float2(v.x, v.x);
            As[kq+1][m] = make_float2(v.y, v.y);
            As[kq+2][m] = make_float2(v.z, v.z);
            As[kq+3][m] = make_float2(v.w, v.w);
        }
        // ---- load B chunk ----
        #pragma unroll
        for (int i = 0; i < 2; i++) {
            int idx = tid + i*256;
            if (BTRANS == 0) {
                int k = idx >> 5, n = (idx & 31) << 2;
                *(float4*)&Bs[k][n] = *(const float4*)(Bmat + (size_t)(k0+k)*N + n0 + n);
            } else {
                int n  = idx >> 2;
                int kq = (idx & 3) << 2;
                float4 v = *(const float4*)(Bmat + (size_t)(n0+n)*K + k0 + kq);
                Bs[kq+0][n] = v.x; Bs[kq+1][n] = v.y; Bs[kq+2][n] = v.z; Bs[kq+3][n] = v.w;
            }
        }
        __syncthreads();
        #pragma unroll
        for (int k = 0; k < 16; k++) {
            ull a[8], b[4];
            {
                ulonglong2 t0 = *(const ulonglong2*)&As[k][tr*8 + 0];
                ulonglong2 t1 = *(const ulonglong2*)&As[k][tr*8 + 2];
                ulonglong2 t2 = *(const ulonglong2*)&As[k][tr*8 + 4];
                ulonglong2 t3 = *(const ulonglong2*)&As[k][tr*8 + 6];
                a[0]=t0.x; a[1]=t0.y; a[2]=t1.x; a[3]=t1.y;
                a[4]=t2.x; a[5]=t2.y; a[6]=t3.x; a[7]=t3.y;
            }
            {
                ulonglong2 u0 = *(const ulonglong2*)&Bs[k][tc*8 + 0];
                ulonglong2 u1 = *(const ulonglong2*)&Bs[k][tc*8 + 4];
                b[0]=u0.x; b[1]=u0.y; b[2]=u1.x; b[3]=u1.y;
            }
            #pragma unroll
            for (int i = 0; i < 8; i++)
                #pragma unroll
                for (int j = 0; j < 4; j++) ffma2(acc[i][j], a[i], b[j]);
        }
        __syncthreads();
    }
    // ---- epilogue ----
    #pragma unroll
    for (int i = 0; i < 8; i++) {
        int m = m0 + tr*8 + i;
        #pragma unroll
        for (int j = 0; j < 4; j++) {
            int n = n0 + tc*8 + j*2;
            float2 v = unpack2(acc[i][j]);
            if (bias) { v.x += bias[n]; v.y += bias[n+1]; }
            if (ACT == 1) { v.x = tanhf(v.x); v.y = tanhf(v.y); }
            if (ACT == 2) { v.x = fmaxf(v.x, 0.f); v.y = fmaxf(v.y, 0.f); }
            if (SCATTER) {
                int bb = m / NR, r = m % NR;
                *(float2*)&C[(((size_t)z*NB + bb)*37 + 1 + r)*NS + n] = v;
            } else if (TRANSA == 2) {
                *(float2*)&C[(size_t)z*M*N + (size_t)m*N + n] = v;
            } else {
                *(float2*)&C[(size_t)m*N + n] = v;
            }
        }
    }
}

// ============ small-M GEMM via split-K (M<=64) ============
__global__ void gemm_small_part(const float* __restrict__ A, const float* __restrict__ W,
                                float* __restrict__ part, int M, int N, int K)
{
    const int BK = 16;
    __shared__ float As[BK][64];
    __shared__ float Bs[BK][64];
    int tid = threadIdx.x, tr = tid >> 4, tc = tid & 15;
    int n0 = blockIdx.x * 64;
    int KS = gridDim.y;
    int Kc = K / KS;
    int kz = blockIdx.y;
    float acc[4][4] = {};
    for (int k0 = kz*Kc; k0 < (kz+1)*Kc; k0 += BK) {
        for (int i = tid; i < 64*BK; i += 256) {
            int m = i >> 4, k = i & 15;
            As[k][m] = (m < M) ? A[(size_t)m*K + k0 + k] : 0.f;
        }
        for (int i = tid; i < BK*64; i += 256) {
            int k = i >> 6, n = i & 63;
            Bs[k][n] = W[(size_t)(k0+k)*N + n0 + n];
        }
        __syncthreads();
        #pragma unroll
        for (int k = 0; k < BK; k++) {
            float a[4], b[4];
            #pragma unroll
            for (int i = 0; i < 4; i++) a[i] = As[k][tr*4+i];
            #pragma unroll
            for (int j = 0; j < 4; j++) b[j] = Bs[k][tc*4+j];
            #pragma unroll
            for (int i = 0; i < 4; i++)
                #pragma unroll
                for (int j = 0; j < 4; j++) acc[i][j] += a[i]*b[j];
        }
        __syncthreads();
    }
    #pragma unroll
    for (int i = 0; i < 4; i++) {
        int m = tr*4 + i;
        if (m >= M) continue;
        #pragma unroll
        for (int j = 0; j < 4; j++)
            part[((size_t)kz*M + m)*N + n0 + tc*4 + j] = acc[i][j];
    }
}

template<int ACT>
__global__ void k_small_epi(const float* __restrict__ part, const float* __restrict__ bias,
                            float* __restrict__ C, int M, int N, int KS)
{
    int idx = blockIdx.x*256 + threadIdx.x;
    if (idx >= M*N) return;
    int n = idx % N;
    float s = 0.f;
    for (int kz = 0; kz < KS; kz++) s += part[(size_t)kz*M*N + idx];
    s += bias[n];
    if (ACT == 1) s = tanhf(s);
    C[idx] = s;
}

// ---------------- diff-square GEMM (64-tile, kept for the tiny glo case) ----------------
__global__ void gemm_diffsq_glo(const float* __restrict__ X, const float* __restrict__ Y,
                                const float* __restrict__ W, const float* __restrict__ bias,
                                float* __restrict__ Cbase, int M, int N, int K)
{
    const int BM = 64, BN = 64, BK = 16;
    int c = blockIdx.z;
    const float* Yp = Y + (size_t)c*K;
    __shared__ float As[BK][BM];
    __shared__ float Bs[BK][BN];
    int tid = threadIdx.x;
    int tr = tid >> 4, tc = tid & 15;
    int m0 = blockIdx.y * BM, n0 = blockIdx.x * BN;
    float acc[4][4] = {};
    for (int k0 = 0; k0 < K; k0 += BK) {
        #pragma unroll
        for (int i = tid; i < BM*BK; i += 256) {
            int m = i >> 4, k = i & 15;
            float v = 0.f;
            if (m0 + m < M) {
                float d = X[(size_t)(m0+m)*K + k0 + k] - Yp[k0 + k];
                v = d * d;
            }
            As[k][m] = v;
        }
        #pragma unroll
        for (int i = tid; i < BK*BN; i += 256) {
            int k = i >> 6, n = i & 63;
            Bs[k][n] = W[(size_t)(k0+k)*N + n0 + n];
        }
        __syncthreads();
        #pragma unroll
        for (int k = 0; k < BK; k++) {
            float a[4], b[4];
            #pragma unroll
            for (int i = 0; i < 4; i++) a[i] = As[k][tr*4+i];
            #pragma unroll
            for (int j = 0; j < 4; j++) b[j] = Bs[k][tc*4+j];
            #pragma unroll
            for (int i = 0; i < 4; i++)
                #pragma unroll
                for (int j = 0; j < 4; j++) acc[i][j] += a[i]*b[j];
        }
        __syncthreads();
    }
    #pragma unroll
    for (int i = 0; i < 4; i++) {
        int m = m0 + tr*4 + i;
        if (m >= M) continue;
        #pragma unroll
        for (int j = 0; j < 4; j++) {
            int n = n0 + tc*4 + j;
            float v = fmaxf(acc[i][j] + bias[n], 0.f);
            Cbase[(size_t)c*M*N + (size_t)m*N + n] = v;
        }
    }
}

// ---------------- small kernels (unchanged from R1) ----------------
__global__ void k_imgave(const float* __restrict__ img) {
    int i = blockIdx.x*blockDim.x + threadIdx.x;
    int b = i >> 10, d = i & 1023;
    float s = 0.f;
    for (int r = 0; r < NR; r++) s += img[((size_t)b*NR + r)*ND + d];
    g_imgave[i] = s * (1.f / NR);
}

__global__ void k_bnstats() {
    int r = blockIdx.x;
    __shared__ float red[256], red2[256];
    float s = 0.f, ss = 0.f;
    for (int i = threadIdx.x; i < NB*ND; i += 256) {
        int b = i >> 10, d = i & 1023;
        float v = g_h[((size_t)b*NR + r)*ND + d];
        s += v; ss += v*v;
    }
    red[threadIdx.x] = s; red2[threadIdx.x] = ss; __syncthreads();
    for (int st = 128; st > 0; st >>= 1) {
        if (threadIdx.x < st) { red[threadIdx.x] += red[threadIdx.x+st]; red2[threadIdx.x] += red2[threadIdx.x+st]; }
        __syncthreads();
    }
    if (threadIdx.x == 0) {
        float mu = red[0] / (float)(NB*ND);
        g_bnmu[r] = mu;
        g_bnvar[r] = red2[0] / (float)(NB*ND) - mu*mu;
    }
}

__global__ void k_gbn(const float* __restrict__ gamma, const float* __restrict__ beta) {
    int d = blockIdx.x*blockDim.x + threadIdx.x;
    float s = 0.f, ss = 0.f;
    for (int b = 0; b < NB; b++) { float v = g_g[(size_t)b*ND + d]; s += v; ss += v*v; }
    float mu = s / NB;
    float var = ss / NB - mu*mu;
    float inv = rsqrtf(var + BNEPS);
    float ga = gamma[d], be = beta[d];
    for (int b = 0; b < NB; b++) {
        float v = g_g[(size_t)b*ND + d];
        g_g[(size_t)b*ND + d] = tanhf((v - mu)*inv*ga + be);
    }
}

__global__ void k_wraw(const float* __restrict__ vcw, const float* __restrict__ vcb,
                       const float* __restrict__ lg, const float* __restrict__ lb) {
    int br = blockIdx.x;
    int b = br / NR, r = br % NR;
    __shared__ float red[256];
    float mu = g_bnmu[r], inv = rsqrtf(g_bnvar[r] + BNEPS);
    float ga = lg[r], be = lb[r];
    float s = 0.f;
    for (int d = threadIdx.x; d < ND; d += 256) {
        float le = tanhf((g_h[(size_t)br*ND + d] - mu)*inv*ga + be);
        s += le * g_g[(size_t)b*ND + d] * vcw[d];
    }
    float tot = blockReduceSum256(s, red);
    if (threadIdx.x == 0) g_wraw[br] = tot + vcb[0];
}

__global__ void k_newglobal(const float* __restrict__ img) {
    int b = blockIdx.x;
    __shared__ float w[NR];
    __shared__ float red[256];
    __shared__ float invn;
    if (threadIdx.x == 0) {
        float mx = -1e30f;
        for (int r = 0; r < NR; r++) mx = fmaxf(mx, g_wraw[b*NR + r]);
        float sum = 0.f;
        for (int r = 0; r < NR; r++) { w[r] = expf(g_wraw[b*NR + r] - mx); sum += w[r]; }
        float is = 1.f / sum;
        for (int r = 0; r < NR; r++) w[r] *= is;
    }
    __syncthreads();
    float ssq = 0.f;
    for (int d = threadIdx.x; d < ND; d += 256) {
        float s = 0.f;
        for (int r = 0; r < NR; r++) s += w[r] * img[((size_t)b*NR + r)*ND + d];
        g_imgglo[(size_t)b*ND + d] = s;
        ssq += s*s;
    }
    float tot = blockReduceSum256(ssq, red);
    if (threadIdx.x == 0) {
        float nrm = sqrtf(tot) + EPSL;
        g_normglo[b] = nrm;
        invn = 1.f / nrm;
    }
    __syncthreads();
    for (int d = threadIdx.x; d < ND; d += 256) g_imgglo[(size_t)b*ND + d] *= invn;
}

__global__ void k_imgpar(const float* __restrict__ img, const int* __restrict__ adjs) {
    int br = blockIdx.x;
    int b = br / NR, r = br % NR;
    __shared__ int eff[NPART];
    __shared__ float wg[NPART];
    if (threadIdx.x == 0) {
        int cnt = 0;
        const int* row = adjs + (size_t)b*NR*NR + (size_t)r*NR;
        for (int j = 0; j < NR && cnt < NPART; j++)
            if (row[j] == 1) eff[cnt++] = j;
        for (; cnt < NPART; cnt++) eff[cnt] = r;
        float v[NPART], mx = -1e30f;
        for (int k = 0; k < NPART; k++) { v[k] = g_wraw[b*NR + eff[k]]; mx = fmaxf(mx, v[k]); }
        float sum = 0.f;
        for (int k = 0; k < NPART; k++) { v[k] = expf(v[k] - mx); sum += v[k]; }
        float is = 1.f / sum;
        for (int k = 0; k < NPART; k++) wg[k] = v[k]*is;
    }
    __syncthreads();
    float invn = 1.f / g_normglo[b];
    for (int d = threadIdx.x; d < ND; d += 256) {
        float s = 0.f;
        #pragma unroll
        for (int k = 0; k < NPART; k++) s += wg[k] * img[((size_t)b*NR + eff[k])*ND + d];
        g_imgpar[(size_t)br*ND + d] = s * invn;
    }
}

__global__ void k_capave(const float* __restrict__ cap) {
    int i = blockIdx.x*blockDim.x + threadIdx.x;
    int c = i >> 10, d = i & 1023;
    float s = 0.f;
    for (int n = 0; n < NWD; n++) s += cap[((size_t)c*NWD + n)*ND + d];
    g_capave[i] = s * (1.f / NWD);
}

__global__ void k_capglo(const float* __restrict__ cap, const float* __restrict__ tsacw,
                         const float* __restrict__ tsacb) {
    int c = blockIdx.x;
    __shared__ float red[256];
    __shared__ float cw[NWD];
    __shared__ float invn;
    float gw[4];
    #pragma unroll
    for (int i = 0; i < 4; i++) {
        int d = threadIdx.x + i*256;
        gw[i] = g_ge[(size_t)c*ND + d] * tsacw[d];
    }
    for (int n = 0; n < NWD; n++) {
        float s = 0.f;
        #pragma unroll
        for (int i = 0; i < 4; i++) {
            int d = threadIdx.x + i*256;
            s += g_le[((size_t)c*NWD + n)*ND + d] * gw[i];
        }
        float tot = blockReduceSum256(s, red);
        if (threadIdx.x == 0) cw[n] = tot + tsacb[0];
    }
    __syncthreads();
    if (threadIdx.x == 0) {
        float mx = -1e30f;
        for (int n = 0; n < NWD; n++) mx = fmaxf(mx, cw[n]);
        float sum = 0.f;
        for (int n = 0; n < NWD; n++) { cw[n] = expf(cw[n] - mx); sum += cw[n]; }
        float is = 1.f / sum;
        for (int n = 0; n < NWD; n++) cw[n] *= is;
    }
    __syncthreads();
    float ssq = 0.f;
    #pragma unroll
    for (int i = 0; i < 4; i++) {
        int d = threadIdx.x + i*256;
        float s = 0.f;
        for (int n = 0; n < NWD; n++) s += cw[n] * cap[((size_t)c*NWD + n)*ND + d];
        g_capglo[(size_t)c*ND + d] = s;
        ssq += s*s;
    }
    float tot = blockReduceSum256(ssq, red);
    if (threadIdx.x == 0) invn = 1.f / (sqrtf(tot) + EPSL);
    __syncthreads();
    #pragma unroll
    for (int i = 0; i < 4; i++) {
        int d = threadIdx.x + i*256;
        g_capglo[(size_t)c*ND + d] *= invn;
    }
}

__global__ void k_attnfuse() {
    int cb = blockIdx.x;
    int c = cb / NB, b = cb % NB;
    __shared__ float sA[NWD*NR];
    __shared__ float nrm[NWD];
    const float* raw = g_attnraw + (size_t)c*NWD*NB*NR;
    for (int i = threadIdx.x; i < NWD*NR; i += 256) {
        int n = i / NR, r = i % NR;
        float v = raw[(size_t)n*NB*NR + (size_t)b*NR + r];
        v = (v > 0.f) ? v : 0.1f*v;
        sA[i] = v;
    }
    __syncthreads();
    if (threadIdx.x < NWD) {
        int n = threadIdx.x;
        float s = 0.f;
        for (int r = 0; r < NR; r++) { float v = sA[n*NR + r]; s += v*v; }
        nrm[n] = 1.f / (sqrtf(s) + EPSL);
    }
    __syncthreads();
    if (threadIdx.x < NR) {
        int r = threadIdx.x;
        float vals[NWD];
        float mx = -1e30f;
        for (int n = 0; n < NWD; n++) {
            float v = SMOOTHF * sA[n*NR + r] * nrm[n];
            vals[n] = v;
            mx = fmaxf(mx, v);
        }
        float sum = 0.f;
        for (int n = 0; n < NWD; n++) { vals[n] = expf(vals[n] - mx); sum += vals[n]; }
        float is = 1.f / sum;
        float* outp = g_attnT + ((size_t)cb*NR + r)*NWD;
        for (int n = 0; n < NWD; n++) outp[n] = vals[n]*is;
    }
}

__global__ void k_ctx(const float* __restrict__ cap) {
    int cb = blockIdx.x;
    int c = cb / NB;
    __shared__ float sT[NR*NWD];
    const float* at = g_attnT + (size_t)cb*NR*NWD;
    for (int i = threadIdx.x; i < NR*NWD; i += 256) sT[i] = at[i];
    __syncthreads();
    float* outp = g_ctx + (size_t)cb*NR*ND;
    for (int it = 0; it < 4; it++) {
        int d = threadIdx.x + it*256;
        float acc[NR];
        #pragma unroll
        for (int r = 0; r < NR; r++) acc[r] = 0.f;
        for (int n = 0; n < NWD; n++) {
            float cv = cap[((size_t)c*NWD + n)*ND + d];
            #pragma unroll
            for (int r = 0; r < NR; r++) acc[r] += sT[r*NWD + n] * cv;
        }
        for (int r = 0; r < NR; r++) outp[(size_t)r*ND + d] = acc[r];
    }
}

__global__ void k_rownorm(float* __restrict__ X, int L) {
    size_t row = blockIdx.x;
    float* p = X + row*(size_t)L;
    __shared__ float red[256];
    __shared__ float invn;
    float s = 0.f;
    for (int i = threadIdx.x; i < L; i += 256) { float v = p[i]; s += v*v; }
    float tot = blockReduceSum256(s, red);
    if (threadIdx.x == 0) invn = 1.f / (sqrtf(tot) + EPSL);
    __syncthreads();
    for (int i = threadIdx.x; i < L; i += 256) p[i] *= invn;
}

__global__ void k_rownorm_simloc(float* __restrict__ out) {
    int row = blockIdx.x;
    int cb = row / NR, r = row % NR;
    float* p = out + ((size_t)cb*37 + 1 + r)*NS;
    __shared__ float red[256];
    __shared__ float invn;
    float v = p[threadIdx.x];
    float tot = blockReduceSum256(v*v, red);
    if (threadIdx.x == 0) invn = 1.f / (sqrtf(tot) + EPSL);
    __syncthreads();
    p[threadIdx.x] = v * invn;
}

__global__ void k_finalize(const float* __restrict__ simw, const float* __restrict__ simb,
                           const float* __restrict__ lng, const float* __restrict__ lnb,
                           float* __restrict__ out, size_t out2off) {
    int cb = blockIdx.x;
    int tid = threadIdx.x;
    const float* sg = out + out2off + (size_t)cb*NS;
    __shared__ float red[256];
    __shared__ float wv[NR];
    __shared__ float mv[2];
    float sgv = sg[tid];
    float sgw = sgv * simw[tid];
    const float* sp = g_simpar + (size_t)cb*NR*NS;
    for (int r = 0; r < NR; r++) {
        float tot = blockReduceSum256(sp[(size_t)r*NS + tid] * sgw, red);
        if (tid == 0) wv[r] = tot + simb[0];
    }
    __syncthreads();
    if (tid == 0) {
        float m = 0.f;
        for (int r = 0; r < NR; r++) m += wv[r];
        m /= NR;
        float v = 0.f;
        for (int r = 0; r < NR; r++) { float d = wv[r] - m; v += d*d; }
        v /= NR;
        mv[0] = m; mv[1] = rsqrtf(v + LNEPS);
    }
    __syncthreads();
    if (tid < NR) {
        int r = tid;
        float z = (wv[r] - mv[0])*mv[1]*lng[r] + lnb[r];
        wv[r] = 1.f / (1.f + expf(-z));
    }
    __syncthreads();
    float* ob = out + (size_t)cb*37*NS;
    ob[tid] = sgv;
    for (int r = 0; r < NR; r++) ob[(size_t)(1+r)*NS + tid] *= wv[r];
}

// ---------------- host ----------------
extern "C" void kernel_launch(void* const* d_in, const int* in_sizes, int n_in,
                              void* d_out, int out_size) {
    (void)in_sizes; (void)n_in; (void)out_size;
    const float* img    = (const float*)d_in[0];
    const float* cap    = (const float*)d_in[1];
    const int*   adjs   = (const int*)d_in[3];
    const float* tsa_lw = (const float*)d_in[5];
    const float* tsa_lb = (const float*)d_in[6];
    const float* tsa_gw = (const float*)d_in[7];
    const float* tsa_gb = (const float*)d_in[8];
    const float* tsa_cw = (const float*)d_in[9];
    const float* tsa_cb = (const float*)d_in[10];
    const float* vl_w   = (const float*)d_in[11];
    const float* vl_b   = (const float*)d_in[12];
    const float* vbn_lg = (const float*)d_in[13];
    const float* vbn_lb = (const float*)d_in[14];
    const float* vg_w   = (const float*)d_in[15];
    const float* vg_b   = (const float*)d_in[16];
    const float* vbn_gg = (const float*)d_in[17];
    const float* vbn_gb = (const float*)d_in[18];
    const float* vc_w   = (const float*)d_in[19];
    const float* vc_b   = (const float*)d_in[20];
    const float* loc_w  = (const float*)d_in[21];
    const float* loc_b  = (const float*)d_in[22];
    const float* par_w  = (const float*)d_in[23];
    const float* par_b  = (const float*)d_in[24];
    const float* glo_w  = (const float*)d_in[25];
    const float* glo_b  = (const float*)d_in[26];
    const float* sim_w  = (const float*)d_in[27];
    const float* sim_b  = (const float*)d_in[28];
    const float* ln_g   = (const float*)d_in[29];
    const float* ln_b   = (const float*)d_in[30];
    float* out = (float*)d_out;

    static bool inited = false;
    static float *p_h, *p_imgave, *p_g, *p_ge, *p_le, *p_attnraw,
                 *p_ctx, *p_imgpar, *p_imgglo, *p_capglo, *p_simpar, *p_part;
    if (!inited) {
        cudaGetSymbolAddress((void**)&p_h, g_h);
        cudaGetSymbolAddress((void**)&p_imgave, g_imgave);
        cudaGetSymbolAddress((void**)&p_g, g_g);
        cudaGetSymbolAddress((void**)&p_ge, g_ge);
        cudaGetSymbolAddress((void**)&p_le, g_le);
        cudaGetSymbolAddress((void**)&p_attnraw, g_attnraw);
        cudaGetSymbolAddress((void**)&p_ctx, g_ctx);
        cudaGetSymbolAddress((void**)&p_imgpar, g_imgpar);
        cudaGetSymbolAddress((void**)&p_imgglo, g_imgglo);
        cudaGetSymbolAddress((void**)&p_capglo, g_capglo);
        cudaGetSymbolAddress((void**)&p_simpar, g_simpar);
        cudaGetSymbolAddress((void**)&p_part, g_part);
        inited = true;
    }

    const size_t out2off = (size_t)NCAP*NB*37*NS;
    float* out2 = out + out2off;
    float* p_capave; cudaGetSymbolAddress((void**)&p_capave, g_capave);

    // ---- caption-independent ----
    k_imgave<<<256, 256>>>(img);
    // h = img @ vl_w + vl_b  (2304 x 1024 x 1024)
    gemm128<0,0,0,0><<<dim3(8, 18), 256>>>(img, nullptr, vl_w, vl_b, p_h, NB*NR, ND, ND);
    k_bnstats<<<NR, 256>>>();
    // g = imgave @ vg_w (split-K, bias in epilogue, BN+tanh later)
    gemm_small_part<<<dim3(16, 8), 256>>>(p_imgave, vg_w, p_part, NB, ND, ND);
    k_small_epi<0><<<(NB*ND+255)/256, 256>>>(p_part, vg_b, p_g, NB, ND, 8);
    k_gbn<<<4, 256>>>(vbn_gg, vbn_gb);
    k_wraw<<<NB*NR, 256>>>(vc_w, vc_b, vbn_lg, vbn_lb);
    k_newglobal<<<NB, 256>>>(img);
    k_imgpar<<<NB*NR, 256>>>(img, adjs);

    // ---- caption side ----
    k_capave<<<128, 256>>>(cap);
    // le = tanh(cap @ tsa_lw + tsa_lb)  (1280 x 1024 x 1024)
    gemm128<0,0,1,0><<<dim3(8, 10), 256>>>(cap, nullptr, tsa_lw, tsa_lb, p_le, NCAP*NWD, ND, ND);
    // ge = tanh(capave @ tsa_gw + tsa_gb)
    gemm_small_part<<<dim3(16, 8), 256>>>(p_capave, tsa_gw, p_part, NCAP, ND, ND);
    k_small_epi<1><<<(NCAP*ND+255)/256, 256>>>(p_part, tsa_gb, p_ge, NCAP, ND, 8);
    k_capglo<<<NCAP, 256>>>(cap, tsa_cw, tsa_cb);

    // attn = cap_all[1280x1024] @ img^T[1024x2304] -> g_attnraw[(c*40+n)][b*36+r]
    gemm128<0,1,0,0><<<dim3(18, 10), 256>>>(cap, nullptr, img, nullptr, p_attnraw,
                                            NCAP*NWD, NB*NR, ND);
    k_attnfuse<<<NCAP*NB, 256>>>();
    k_ctx<<<NCAP*NB, 256>>>(cap);
    k_rownorm<<<NCAP*NB*NR, 256>>>(p_ctx, ND);

    // ---- heavy diff-square GEMMs (f32x2) ----
    // sim_loc: relu((ctx - img)^2 @ loc_w + loc_b) -> scattered into out
    gemm128<1,0,2,1><<<dim3(2, 18, NCAP), 256>>>(p_ctx, img, loc_w, loc_b, out, NB*NR, NS, ND);
    k_rownorm_simloc<<<NCAP*NB*NR, 256>>>(out);
    // sim_par: relu((imgpar - capglo)^2 @ par_w + par_b)
    gemm128<2,0,2,0><<<dim3(2, 18, NCAP), 256>>>(p_imgpar, p_capglo, par_w, par_b, p_simpar, NB*NR, NS, ND);
    k_rownorm<<<NCAP*NB*NR, 256>>>(p_simpar, NS);
    // sim_glo (tiny)
    gemm_diffsq_glo<<<dim3(4, 1, NCAP), 256>>>(p_imgglo, p_capglo, glo_w, glo_b, out2, NB, NS, ND);
    k_rownorm<<<NCAP*NB, 256>>>(out2, NS);

    // ---- wts + layernorm + sigmoid + scale + assemble ----
    k_finalize<<<NCAP*NB, 256>>>(sim_w, sim_b, ln_g, ln_b, out, out2off);
}

// round 5
// speedup vs baseline: 2.7025x; 1.4625x over previous
#include <cuda_runtime.h>
#include <cuda_bf16.h>
#include <cstdint>
#include <stdint.h>
#include <math.h>

#define NB 64
#define NR 36
#define ND 1024
#define NCAP 32
#define NWD 40
#define NS 256
#define NPART 5
#define EPSL 1e-8f
#define BNEPS 1e-5f
#define LNEPS 1e-5f
#define SMOOTHF 9.0f

typedef unsigned long long ull;

// ---------------- scratch ----------------
__device__ float g_h[NB*NR*ND];
__device__ float g_imgave[NB*ND];
__device__ float g_bnmu[NR];
__device__ float g_bnvar[NR];
__device__ float g_g[NB*ND];
__device__ float g_wraw[NB*NR];
__device__ float g_imgglo[NB*ND];
__device__ float g_normglo[NB];
__device__ float g_imgpar[NB*NR*ND];
__device__ float g_capave[NCAP*ND];
__device__ float g_le[NCAP*NWD*ND];
__device__ float g_ge[NCAP*ND];
__device__ float g_capglo[NCAP*ND];
__device__ float g_attnraw[(size_t)NCAP*NWD*NB*NR];
__device__ float g_attnT[(size_t)NCAP*NB*NR*NWD];
__device__ float g_ctx[(size_t)NCAP*NB*NR*ND];
__device__ float g_simpar[(size_t)NCAP*NB*NR*NS];
__device__ float g_part[8*64*1024];
__device__ __nv_bfloat16 g_wth[2][NS*ND];   // [0]=loc_w^T, [1]=par_w^T  (hi)
__device__ __nv_bfloat16 g_wtl[2][NS*ND];   // lo

// ---------------- helpers ----------------
__device__ __forceinline__ uint32_t smem_u32(const void* p) {
    uint32_t a;
    asm("{ .reg .u64 t; cvta.to.shared.u64 t, %1; cvt.u32.u64 %0, t; }" : "=r"(a) : "l"(p));
    return a;
}

__device__ __forceinline__ float blockReduceSum256(float v, float* red) {
    int tid = threadIdx.x;
    red[tid] = v; __syncthreads();
    #pragma unroll
    for (int s = 128; s > 0; s >>= 1) {
        if (tid < s) red[tid] += red[tid + s];
        __syncthreads();
    }
    float r = red[0]; __syncthreads();
    return r;
}

__device__ __forceinline__ void ffma2(ull &c, ull a, ull b) {
    asm("fma.rn.f32x2 %0, %1, %2, %0;" : "+l"(c) : "l"(a), "l"(b));
}
__device__ __forceinline__ float2 unpack2(ull u) {
    float2 f;
    f.x = __int_as_float((int)(u & 0xffffffffull));
    f.y = __int_as_float((int)(u >> 32));
    return f;
}

#define LDSM4(r0, r1, r2, r3, addr) \
    asm volatile("ldmatrix.sync.aligned.m8n8.x4.shared.b16 {%0,%1,%2,%3}, [%4];" \
        : "=r"(r0), "=r"(r1), "=r"(r2), "=r"(r3) : "r"(addr))

#define MMA_BF16(d, a, b) \
    asm volatile("mma.sync.aligned.m16n8k16.row.col.f32.bf16.bf16.f32 " \
        "{%0,%1,%2,%3}, {%4,%5,%6,%7}, {%8,%9}, {%0,%1,%2,%3};" \
        : "+f"((d)[0]), "+f"((d)[1]), "+f"((d)[2]), "+f"((d)[3]) \
        : "r"((a)[0]), "r"((a)[1]), "r"((a)[2]), "r"((a)[3]), "r"((b)[0]), "r"((b)[1]))

// ---------------- weight transpose + bf16 split ----------------
__global__ void k_wsplit(const float* __restrict__ W, __nv_bfloat16* __restrict__ H,
                         __nv_bfloat16* __restrict__ L) {
    int idx = blockIdx.x * 256 + threadIdx.x;   // N*K = 262144
    int n = idx >> 10, k = idx & 1023;
    float w = W[(size_t)k * NS + n];
    __nv_bfloat16 h = __float2bfloat16(w);
    H[idx] = h;
    L[idx] = __float2bfloat16(w - __bfloat162float(h));
}

// ============ HMMA (mma.sync bf16 split) diff-square GEMM ============
// D[z][m][n] = relu( sum_k (X-Y)^2[m,k] * Wt[n,k] + bias[n] )
// MODE 0: X batched by z (ctx), Y indexed by m (img); scatter into out(c,b,1+r,s)
// MODE 1: X shared (imgpar), Y = vector per z (capglo); out -> simpar
#define APAD 40
template<int MODE>
__global__ void __launch_bounds__(256)
hmma_diffsq(const float* __restrict__ X, const float* __restrict__ Y,
            const __nv_bfloat16* __restrict__ Bh, const __nv_bfloat16* __restrict__ Bl,
            const float* __restrict__ bias, float* __restrict__ outp)
{
    __shared__ __nv_bfloat16 sAh[128][APAD];
    __shared__ __nv_bfloat16 sAl[128][APAD];
    __shared__ __nv_bfloat16 sBh[128][APAD];
    __shared__ __nv_bfloat16 sBl[128][APAD];
    int tid = threadIdx.x;
    int lane = tid & 31, warp = tid >> 5;
    int mw = warp >> 2, nw = warp & 3;          // 2 (M) x 4 (N) warp grid
    int n0 = blockIdx.x * 128, m0 = blockIdx.y * 128, z = blockIdx.z;

    const float* Xp = (MODE == 0) ? X + ((size_t)z*2304 + m0)*ND : X + (size_t)m0*ND;
    const float* Yp = (MODE == 0) ? Y + (size_t)m0*ND : Y + (size_t)z*ND;

    float acc[4][4][4];
    #pragma unroll
    for (int i = 0; i < 4; i++)
        #pragma unroll
        for (int j = 0; j < 4; j++)
            #pragma unroll
            for (int e = 0; e < 4; e++) acc[i][j][e] = 0.f;

    uint32_t aAh = smem_u32(sAh), aAl = smem_u32(sAl);
    uint32_t aBh = smem_u32(sBh), aBl = smem_u32(sBl);

    // per-warp ldmatrix addresses (element offsets; x2 at the end for bytes)
    int a_row = mw*64 + (lane & 15);
    int a_col8 = (lane >> 4) * 8;
    int b_row = nw*32 + (lane >> 4)*8 + (lane & 7);
    int b_col8 = ((lane >> 3) & 1) * 8;

    for (int ch = 0; ch < 32; ch++) {
        int k0 = ch * 32;
        // ---- A: (X-Y)^2 fp32 -> split bf16 hi/lo ----
        #pragma unroll
        for (int i = 0; i < 4; i++) {
            int slot = tid + i*256;             // 1024 = 128 rows x 8 float4
            int row = slot >> 3, q = slot & 7;
            size_t off = (size_t)row*ND + k0 + q*4;
            float4 xv = *(const float4*)(Xp + off);
            float4 yv;
            if (MODE == 0) yv = *(const float4*)(Yp + off);
            else           yv = *(const float4*)(Yp + k0 + q*4);
            float d0 = xv.x - yv.x, d1 = xv.y - yv.y, d2 = xv.z - yv.z, d3 = xv.w - yv.w;
            float a0 = d0*d0, a1 = d1*d1, a2 = d2*d2, a3 = d3*d3;
            __nv_bfloat162 h01 = __floats2bfloat162_rn(a0, a1);
            __nv_bfloat162 h23 = __floats2bfloat162_rn(a2, a3);
            float r0 = a0 - __bfloat162float(h01.x);
            float r1 = a1 - __bfloat162float(h01.y);
            float r2 = a2 - __bfloat162float(h23.x);
            float r3 = a3 - __bfloat162float(h23.y);
            __nv_bfloat162 l01 = __floats2bfloat162_rn(r0, r1);
            __nv_bfloat162 l23 = __floats2bfloat162_rn(r2, r3);
            *(uint2*)&sAh[row][q*4] = make_uint2(*(uint32_t*)&h01, *(uint32_t*)&h23);
            *(uint2*)&sAl[row][q*4] = make_uint2(*(uint32_t*)&l01, *(uint32_t*)&l23);
        }
        // ---- B: pre-split bf16 [n][k] ----
        #pragma unroll
        for (int i = 0; i < 2; i++) {
            int slot = tid + i*256;             // 512 = 128 rows x 4 x 16B
            int row = slot >> 2, c = slot & 3;
            size_t src = (size_t)(n0 + row)*ND + k0 + c*8;
            *(uint4*)&sBh[row][c*8] = *(const uint4*)(Bh + src);
            *(uint4*)&sBl[row][c*8] = *(const uint4*)(Bl + src);
        }
        __syncthreads();

        #pragma unroll
        for (int k16 = 0; k16 < 2; k16++) {
            uint32_t bh[4][2], bl[4][2];
            #pragma unroll
            for (int half = 0; half < 2; half++) {
                uint32_t off = (uint32_t)((b_row + half*16)*APAD + k16*16 + b_col8) * 2;
                uint32_t r0, r1, r2, r3;
                LDSM4(r0, r1, r2, r3, aBh + off);
                bh[half*2+0][0] = r0; bh[half*2+0][1] = r1;
                bh[half*2+1][0] = r2; bh[half*2+1][1] = r3;
                LDSM4(r0, r1, r2, r3, aBl + off);
                bl[half*2+0][0] = r0; bl[half*2+0][1] = r1;
                bl[half*2+1][0] = r2; bl[half*2+1][1] = r3;
            }
            #pragma unroll
            for (int mt = 0; mt < 4; mt++) {
                uint32_t ah[4], al[4];
                uint32_t off = (uint32_t)((a_row + mt*16)*APAD + k16*16 + a_col8) * 2;
                LDSM4(ah[0], ah[1], ah[2], ah[3], aAh + off);
                LDSM4(al[0], al[1], al[2], al[3], aAl + off);
                #pragma unroll
                for (int nt = 0; nt < 4; nt++) {
                    MMA_BF16(acc[mt][nt], ah, bh[nt]);
                    MMA_BF16(acc[mt][nt], ah, bl[nt]);
                    MMA_BF16(acc[mt][nt], al, bh[nt]);
                }
            }
        }
        __syncthreads();
    }

    // ---- epilogue: bias + relu (+ scatter for MODE 0) ----
    #pragma unroll
    for (int mt = 0; mt < 4; mt++) {
        int mA = m0 + mw*64 + mt*16 + (lane >> 2);   // row for c0,c1
        int mB = mA + 8;                              // row for c2,c3
        float* dA;
        float* dB;
        if (MODE == 0) {
            int bA = mA / NR, rA = mA % NR;
            int bB = mB / NR, rB = mB % NR;
            dA = outp + (((size_t)z*NB + bA)*37 + 1 + rA)*NS;
            dB = outp + (((size_t)z*NB + bB)*37 + 1 + rB)*NS;
        } else {
            dA = outp + ((size_t)z*2304 + mA)*NS;
            dB = outp + ((size_t)z*2304 + mB)*NS;
        }
        #pragma unroll
        for (int nt = 0; nt < 4; nt++) {
            int n = n0 + nw*32 + nt*8 + (lane & 3)*2;
            float b0 = bias[n], b1 = bias[n+1];
            float2 vA = make_float2(fmaxf(acc[mt][nt][0] + b0, 0.f),
                                    fmaxf(acc[mt][nt][1] + b1, 0.f));
            float2 vB = make_float2(fmaxf(acc[mt][nt][2] + b0, 0.f),
                                    fmaxf(acc[mt][nt][3] + b1, 0.f));
            *(float2*)&dA[n] = vA;
            *(float2*)&dB[n] = vB;
        }
    }
}

// ============ f32x2 GEMM ============
template<int TRANSA, int BTRANS, int ACT, int SCATTER>
__global__ void __launch_bounds__(256, 2)
gemm128(const float* __restrict__ A, const float* __restrict__ Y,
        const float* __restrict__ Bmat, const float* __restrict__ bias,
        float* __restrict__ C, int M, int N, int K)
{
    __shared__ float2 As[16][128];
    __shared__ float  Bs[16][128];
    int tid = threadIdx.x;
    int tr = tid >> 4, tc = tid & 15;
    int m0 = blockIdx.y * 128, n0 = blockIdx.x * 128;
    int z = blockIdx.z;
    const float* Ap = A;
    const float* Yp = Y;
    if (TRANSA == 1) Ap = A + (size_t)z*M*K;
    if (TRANSA == 2) Yp = Y + (size_t)z*K;

    ull acc[8][4];
    #pragma unroll
    for (int i = 0; i < 8; i++)
        #pragma unroll
        for (int j = 0; j < 4; j++) acc[i][j] = 0ull;

    for (int k0 = 0; k0 < K; k0 += 16) {
        #pragma unroll
        for (int i = 0; i < 2; i++) {
            int idx = tid + i*256;
            int m  = idx >> 2;
            int kq = (idx & 3) << 2;
            size_t off = (size_t)(m0+m)*K + k0 + kq;
            float4 v = *(const float4*)(Ap + off);
            if (TRANSA == 1) {
                float4 y = *(const float4*)(Y + off);
                v.x -= y.x; v.y -= y.y; v.z -= y.z; v.w -= y.w;
            } else if (TRANSA == 2) {
                const float* yv = Yp + k0 + kq;
                v.x -= yv[0]; v.y -= yv[1]; v.z -= yv[2]; v.w -= yv[3];
            }
            if (TRANSA) { v.x *= v.x; v.y *= v.y; v.z *= v.z; v.w *= v.w; }
            As[kq+0][m] = make_float2(v.x, v.x);
            As[kq+1][m] = make_float2(v.y, v.y);
            As[kq+2][m] = make_float2(v.z, v.z);
            As[kq+3][m] = make_float2(v.w, v.w);
        }
        #pragma unroll
        for (int i = 0; i < 2; i++) {
            int idx = tid + i*256;
            if (BTRANS == 0) {
                int k = idx >> 5, n = (idx & 31) << 2;
                *(float4*)&Bs[k][n] = *(const float4*)(Bmat + (size_t)(k0+k)*N + n0 + n);
            } else {
                int n  = idx >> 2;
                int kq = (idx & 3) << 2;
                float4 v = *(const float4*)(Bmat + (size_t)(n0+n)*K + k0 + kq);
                Bs[kq+0][n] = v.x; Bs[kq+1][n] = v.y; Bs[kq+2][n] = v.z; Bs[kq+3][n] = v.w;
            }
        }
        __syncthreads();
        #pragma unroll
        for (int k = 0; k < 16; k++) {
            ull a[8], b[4];
            {
                ulonglong2 t0 = *(const ulonglong2*)&As[k][tr*8 + 0];
                ulonglong2 t1 = *(const ulonglong2*)&As[k][tr*8 + 2];
                ulonglong2 t2 = *(const ulonglong2*)&As[k][tr*8 + 4];
                ulonglong2 t3 = *(const ulonglong2*)&As[k][tr*8 + 6];
                a[0]=t0.x; a[1]=t0.y; a[2]=t1.x; a[3]=t1.y;
                a[4]=t2.x; a[5]=t2.y; a[6]=t3.x; a[7]=t3.y;
            }
            {
                ulonglong2 u0 = *(const ulonglong2*)&Bs[k][tc*8 + 0];
                ulonglong2 u1 = *(const ulonglong2*)&Bs[k][tc*8 + 4];
                b[0]=u0.x; b[1]=u0.y; b[2]=u1.x; b[3]=u1.y;
            }
            #pragma unroll
            for (int i = 0; i < 8; i++)
                #pragma unroll
                for (int j = 0; j < 4; j++) ffma2(acc[i][j], a[i], b[j]);
        }
        __syncthreads();
    }
    #pragma unroll
    for (int i = 0; i < 8; i++) {
        int m = m0 + tr*8 + i;
        #pragma unroll
        for (int j = 0; j < 4; j++) {
            int n = n0 + tc*8 + j*2;
            float2 v = unpack2(acc[i][j]);
            if (bias) { v.x += bias[n]; v.y += bias[n+1]; }
            if (ACT == 1) { v.x = tanhf(v.x); v.y = tanhf(v.y); }
            if (ACT == 2) { v.x = fmaxf(v.x, 0.f); v.y = fmaxf(v.y, 0.f); }
            if (SCATTER) {
                int bb = m / NR, r = m % NR;
                *(float2*)&C[(((size_t)z*NB + bb)*37 + 1 + r)*NS + n] = v;
            } else if (TRANSA == 2) {
                *(float2*)&C[(size_t)z*M*N + (size_t)m*N + n] = v;
            } else {
                *(float2*)&C[(size_t)m*N + n] = v;
            }
        }
    }
}

// ============ small-M GEMM via split-K ============
__global__ void gemm_small_part(const float* __restrict__ A, const float* __restrict__ W,
                                float* __restrict__ part, int M, int N, int K)
{
    const int BK = 16;
    __shared__ float As[BK][64];
    __shared__ float Bs[BK][64];
    int tid = threadIdx.x, tr = tid >> 4, tc = tid & 15;
    int n0 = blockIdx.x * 64;
    int KS = gridDim.y;
    int Kc = K / KS;
    int kz = blockIdx.y;
    float acc[4][4] = {};
    for (int k0 = kz*Kc; k0 < (kz+1)*Kc; k0 += BK) {
        for (int i = tid; i < 64*BK; i += 256) {
            int m = i >> 4, k = i & 15;
            As[k][m] = (m < M) ? A[(size_t)m*K + k0 + k] : 0.f;
        }
        for (int i = tid; i < BK*64; i += 256) {
            int k = i >> 6, n = i & 63;
            Bs[k][n] = W[(size_t)(k0+k)*N + n0 + n];
        }
        __syncthreads();
        #pragma unroll
        for (int k = 0; k < BK; k++) {
            float a[4], b[4];
            #pragma unroll
            for (int i = 0; i < 4; i++) a[i] = As[k][tr*4+i];
            #pragma unroll
            for (int j = 0; j < 4; j++) b[j] = Bs[k][tc*4+j];
            #pragma unroll
            for (int i = 0; i < 4; i++)
                #pragma unroll
                for (int j = 0; j < 4; j++) acc[i][j] += a[i]*b[j];
        }
        __syncthreads();
    }
    #pragma unroll
    for (int i = 0; i < 4; i++) {
        int m = tr*4 + i;
        if (m >= M) continue;
        #pragma unroll
        for (int j = 0; j < 4; j++)
            part[((size_t)kz*M + m)*N + n0 + tc*4 + j] = acc[i][j];
    }
}

template<int ACT>
__global__ void k_small_epi(const float* __restrict__ part, const float* __restrict__ bias,
                            float* __restrict__ C, int M, int N, int KS)
{
    int idx = blockIdx.x*256 + threadIdx.x;
    if (idx >= M*N) return;
    int n = idx % N;
    float s = 0.f;
    for (int kz = 0; kz < KS; kz++) s += part[(size_t)kz*M*N + idx];
    s += bias[n];
    if (ACT == 1) s = tanhf(s);
    C[idx] = s;
}

// ---------------- tiny glo diff-square GEMM ----------------
__global__ void gemm_diffsq_glo(const float* __restrict__ X, const float* __restrict__ Y,
                                const float* __restrict__ W, const float* __restrict__ bias,
                                float* __restrict__ Cbase, int M, int N, int K)
{
    const int BM = 64, BN = 64, BK = 16;
    int c = blockIdx.z;
    const float* Yp = Y + (size_t)c*K;
    __shared__ float As[BK][BM];
    __shared__ float Bs[BK][BN];
    int tid = threadIdx.x;
    int tr = tid >> 4, tc = tid & 15;
    int m0 = blockIdx.y * BM, n0 = blockIdx.x * BN;
    float acc[4][4] = {};
    for (int k0 = 0; k0 < K; k0 += BK) {
        #pragma unroll
        for (int i = tid; i < BM*BK; i += 256) {
            int m = i >> 4, k = i & 15;
            float v = 0.f;
            if (m0 + m < M) {
                float d = X[(size_t)(m0+m)*K + k0 + k] - Yp[k0 + k];
                v = d * d;
            }
            As[k][m] = v;
        }
        #pragma unroll
        for (int i = tid; i < BK*BN; i += 256) {
            int k = i >> 6, n = i & 63;
            Bs[k][n] = W[(size_t)(k0+k)*N + n0 + n];
        }
        __syncthreads();
        #pragma unroll
        for (int k = 0; k < BK; k++) {
            float a[4], b[4];
            #pragma unroll
            for (int i = 0; i < 4; i++) a[i] = As[k][tr*4+i];
            #pragma unroll
            for (int j = 0; j < 4; j++) b[j] = Bs[k][tc*4+j];
            #pragma unroll
            for (int i = 0; i < 4; i++)
                #pragma unroll
                for (int j = 0; j < 4; j++) acc[i][j] += a[i]*b[j];
        }
        __syncthreads();
    }
    #pragma unroll
    for (int i = 0; i < 4; i++) {
        int m = m0 + tr*4 + i;
        if (m >= M) continue;
        #pragma unroll
        for (int j = 0; j < 4; j++) {
            int n = n0 + tc*4 + j;
            float v = fmaxf(acc[i][j] + bias[n], 0.f);
            Cbase[(size_t)c*M*N + (size_t)m*N + n] = v;
        }
    }
}

// ---------------- small kernels ----------------
__global__ void k_imgave(const float* __restrict__ img) {
    int i = blockIdx.x*blockDim.x + threadIdx.x;
    int b = i >> 10, d = i & 1023;
    float s = 0.f;
    for (int r = 0; r < NR; r++) s += img[((size_t)b*NR + r)*ND + d];
    g_imgave[i] = s * (1.f / NR);
}

__global__ void k_bnstats() {
    int r = blockIdx.x;
    __shared__ float red[256], red2[256];
    float s = 0.f, ss = 0.f;
    for (int i = threadIdx.x; i < NB*ND; i += 256) {
        int b = i >> 10, d = i & 1023;
        float v = g_h[((size_t)b*NR + r)*ND + d];
        s += v; ss += v*v;
    }
    red[threadIdx.x] = s; red2[threadIdx.x] = ss; __syncthreads();
    for (int st = 128; st > 0; st >>= 1) {
        if (threadIdx.x < st) { red[threadIdx.x] += red[threadIdx.x+st]; red2[threadIdx.x] += red2[threadIdx.x+st]; }
        __syncthreads();
    }
    if (threadIdx.x == 0) {
        float mu = red[0] / (float)(NB*ND);
        g_bnmu[r] = mu;
        g_bnvar[r] = red2[0] / (float)(NB*ND) - mu*mu;
    }
}

__global__ void k_gbn(const float* __restrict__ gamma, const float* __restrict__ beta) {
    int d = blockIdx.x*blockDim.x + threadIdx.x;
    float s = 0.f, ss = 0.f;
    for (int b = 0; b < NB; b++) { float v = g_g[(size_t)b*ND + d]; s += v; ss += v*v; }
    float mu = s / NB;
    float var = ss / NB - mu*mu;
    float inv = rsqrtf(var + BNEPS);
    float ga = gamma[d], be = beta[d];
    for (int b = 0; b < NB; b++) {
        float v = g_g[(size_t)b*ND + d];
        g_g[(size_t)b*ND + d] = tanhf((v - mu)*inv*ga + be);
    }
}

__global__ void k_wraw(const float* __restrict__ vcw, const float* __restrict__ vcb,
                       const float* __restrict__ lg, const float* __restrict__ lb) {
    int br = blockIdx.x;
    int b = br / NR, r = br % NR;
    __shared__ float red[256];
    float mu = g_bnmu[r], inv = rsqrtf(g_bnvar[r] + BNEPS);
    float ga = lg[r], be = lb[r];
    float s = 0.f;
    for (int d = threadIdx.x; d < ND; d += 256) {
        float le = tanhf((g_h[(size_t)br*ND + d] - mu)*inv*ga + be);
        s += le * g_g[(size_t)b*ND + d] * vcw[d];
    }
    float tot = blockReduceSum256(s, red);
    if (threadIdx.x == 0) g_wraw[br] = tot + vcb[0];
}

__global__ void k_newglobal(const float* __restrict__ img) {
    int b = blockIdx.x;
    __shared__ float w[NR];
    __shared__ float red[256];
    __shared__ float invn;
    if (threadIdx.x == 0) {
        float mx = -1e30f;
        for (int r = 0; r < NR; r++) mx = fmaxf(mx, g_wraw[b*NR + r]);
        float sum = 0.f;
        for (int r = 0; r < NR; r++) { w[r] = expf(g_wraw[b*NR + r] - mx); sum += w[r]; }
        float is = 1.f / sum;
        for (int r = 0; r < NR; r++) w[r] *= is;
    }
    __syncthreads();
    float ssq = 0.f;
    for (int d = threadIdx.x; d < ND; d += 256) {
        float s = 0.f;
        for (int r = 0; r < NR; r++) s += w[r] * img[((size_t)b*NR + r)*ND + d];
        g_imgglo[(size_t)b*ND + d] = s;
        ssq += s*s;
    }
    float tot = blockReduceSum256(ssq, red);
    if (threadIdx.x == 0) {
        float nrm = sqrtf(tot) + EPSL;
        g_normglo[b] = nrm;
        invn = 1.f / nrm;
    }
    __syncthreads();
    for (int d = threadIdx.x; d < ND; d += 256) g_imgglo[(size_t)b*ND + d] *= invn;
}

__global__ void k_imgpar(const float* __restrict__ img, const int* __restrict__ adjs) {
    int br = blockIdx.x;
    int b = br / NR, r = br % NR;
    __shared__ int eff[NPART];
    __shared__ float wg[NPART];
    if (threadIdx.x == 0) {
        int cnt = 0;
        const int* row = adjs + (size_t)b*NR*NR + (size_t)r*NR;
        for (int j = 0; j < NR && cnt < NPART; j++)
            if (row[j] == 1) eff[cnt++] = j;
        for (; cnt < NPART; cnt++) eff[cnt] = r;
        float v[NPART], mx = -1e30f;
        for (int k = 0; k < NPART; k++) { v[k] = g_wraw[b*NR + eff[k]]; mx = fmaxf(mx, v[k]); }
        float sum = 0.f;
        for (int k = 0; k < NPART; k++) { v[k] = expf(v[k] - mx); sum += v[k]; }
        float is = 1.f / sum;
        for (int k = 0; k < NPART; k++) wg[k] = v[k]*is;
    }
    __syncthreads();
    float invn = 1.f / g_normglo[b];
    for (int d = threadIdx.x; d < ND; d += 256) {
        float s = 0.f;
        #pragma unroll
        for (int k = 0; k < NPART; k++) s += wg[k] * img[((size_t)b*NR + eff[k])*ND + d];
        g_imgpar[(size_t)br*ND + d] = s * invn;
    }
}

__global__ void k_capave(const float* __restrict__ cap) {
    int i = blockIdx.x*blockDim.x + threadIdx.x;
    int c = i >> 10, d = i & 1023;
    float s = 0.f;
    for (int n = 0; n < NWD; n++) s += cap[((size_t)c*NWD + n)*ND + d];
    g_capave[i] = s * (1.f / NWD);
}

__global__ void k_capglo(const float* __restrict__ cap, const float* __restrict__ tsacw,
                         const float* __restrict__ tsacb) {
    int c = blockIdx.x;
    __shared__ float red[256];
    __shared__ float cw[NWD];
    __shared__ float invn;
    float gw[4];
    #pragma unroll
    for (int i = 0; i < 4; i++) {
        int d = threadIdx.x + i*256;
        gw[i] = g_ge[(size_t)c*ND + d] * tsacw[d];
    }
    for (int n = 0; n < NWD; n++) {
        float s = 0.f;
        #pragma unroll
        for (int i = 0; i < 4; i++) {
            int d = threadIdx.x + i*256;
            s += g_le[((size_t)c*NWD + n)*ND + d] * gw[i];
        }
        float tot = blockReduceSum256(s, red);
        if (threadIdx.x == 0) cw[n] = tot + tsacb[0];
    }
    __syncthreads();
    if (threadIdx.x == 0) {
        float mx = -1e30f;
        for (int n = 0; n < NWD; n++) mx = fmaxf(mx, cw[n]);
        float sum = 0.f;
        for (int n = 0; n < NWD; n++) { cw[n] = expf(cw[n] - mx); sum += cw[n]; }
        float is = 1.f / sum;
        for (int n = 0; n < NWD; n++) cw[n] *= is;
    }
    __syncthreads();
    float ssq = 0.f;
    #pragma unroll
    for (int i = 0; i < 4; i++) {
        int d = threadIdx.x + i*256;
        float s = 0.f;
        for (int n = 0; n < NWD; n++) s += cw[n] * cap[((size_t)c*NWD + n)*ND + d];
        g_capglo[(size_t)c*ND + d] = s;
        ssq += s*s;
    }
    float tot = blockReduceSum256(ssq, red);
    if (threadIdx.x == 0) invn = 1.f / (sqrtf(tot) + EPSL);
    __syncthreads();
    #pragma unroll
    for (int i = 0; i < 4; i++) {
        int d = threadIdx.x + i*256;
        g_capglo[(size_t)c*ND + d] *= invn;
    }
}

__global__ void k_attnfuse() {
    int cb = blockIdx.x;
    int c = cb / NB, b = cb % NB;
    __shared__ float sA[NWD*NR];
    __shared__ float nrm[NWD];
    const float* raw = g_attnraw + (size_t)c*NWD*NB*NR;
    for (int i = threadIdx.x; i < NWD*NR; i += 256) {
        int n = i / NR, r = i % NR;
        float v = raw[(size_t)n*NB*NR + (size_t)b*NR + r];
        v = (v > 0.f) ? v : 0.1f*v;
        sA[i] = v;
    }
    __syncthreads();
    if (threadIdx.x < NWD) {
        int n = threadIdx.x;
        float s = 0.f;
        for (int r = 0; r < NR; r++) { float v = sA[n*NR + r]; s += v*v; }
        nrm[n] = 1.f / (sqrtf(s) + EPSL);
    }
    __syncthreads();
    if (threadIdx.x < NR) {
        int r = threadIdx.x;
        float vals[NWD];
        float mx = -1e30f;
        for (int n = 0; n < NWD; n++) {
            float v = SMOOTHF * sA[n*NR + r] * nrm[n];
            vals[n] = v;
            mx = fmaxf(mx, v);
        }
        float sum = 0.f;
        for (int n = 0; n < NWD; n++) { vals[n] = expf(vals[n] - mx); sum += vals[n]; }
        float is = 1.f / sum;
        float* outp = g_attnT + ((size_t)cb*NR + r)*NWD;
        for (int n = 0; n < NWD; n++) outp[n] = vals[n]*is;
    }
}

__global__ void k_ctx(const float* __restrict__ cap) {
    int cb = blockIdx.x;
    int c = cb / NB;
    __shared__ float sT[NR*NWD];
    const float* at = g_attnT + (size_t)cb*NR*NWD;
    for (int i = threadIdx.x; i < NR*NWD; i += 256) sT[i] = at[i];
    __syncthreads();
    float* outp = g_ctx + (size_t)cb*NR*ND;
    for (int it = 0; it < 4; it++) {
        int d = threadIdx.x + it*256;
        float acc[NR];
        #pragma unroll
        for (int r = 0; r < NR; r++) acc[r] = 0.f;
        for (int n = 0; n < NWD; n++) {
            float cv = cap[((size_t)c*NWD + n)*ND + d];
            #pragma unroll
            for (int r = 0; r < NR; r++) acc[r] += sT[r*NWD + n] * cv;
        }
        for (int r = 0; r < NR; r++) outp[(size_t)r*ND + d] = acc[r];
    }
}

__global__ void k_rownorm(float* __restrict__ X, int L) {
    size_t row = blockIdx.x;
    float* p = X + row*(size_t)L;
    __shared__ float red[256];
    __shared__ float invn;
    float s = 0.f;
    for (int i = threadIdx.x; i < L; i += 256) { float v = p[i]; s += v*v; }
    float tot = blockReduceSum256(s, red);
    if (threadIdx.x == 0) invn = 1.f / (sqrtf(tot) + EPSL);
    __syncthreads();
    for (int i = threadIdx.x; i < L; i += 256) p[i] *= invn;
}

__global__ void k_rownorm_simloc(float* __restrict__ out) {
    int row = blockIdx.x;
    int cb = row / NR, r = row % NR;
    float* p = out + ((size_t)cb*37 + 1 + r)*NS;
    __shared__ float red[256];
    __shared__ float invn;
    float v = p[threadIdx.x];
    float tot = blockReduceSum256(v*v, red);
    if (threadIdx.x == 0) invn = 1.f / (sqrtf(tot) + EPSL);
    __syncthreads();
    p[threadIdx.x] = v * invn;
}

__global__ void k_finalize(const float* __restrict__ simw, const float* __restrict__ simb,
                           const float* __restrict__ lng, const float* __restrict__ lnb,
                           float* __restrict__ out, size_t out2off) {
    int cb = blockIdx.x;
    int tid = threadIdx.x;
    const float* sg = out + out2off + (size_t)cb*NS;
    __shared__ float red[256];
    __shared__ float wv[NR];
    __shared__ float mv[2];
    float sgv = sg[tid];
    float sgw = sgv * simw[tid];
    const float* sp = g_simpar + (size_t)cb*NR*NS;
    for (int r = 0; r < NR; r++) {
        float tot = blockReduceSum256(sp[(size_t)r*NS + tid] * sgw, red);
        if (tid == 0) wv[r] = tot + simb[0];
    }
    __syncthreads();
    if (tid == 0) {
        float m = 0.f;
        for (int r = 0; r < NR; r++) m += wv[r];
        m /= NR;
        float v = 0.f;
        for (int r = 0; r < NR; r++) { float d = wv[r] - m; v += d*d; }
        v /= NR;
        mv[0] = m; mv[1] = rsqrtf(v + LNEPS);
    }
    __syncthreads();
    if (tid < NR) {
        int r = tid;
        float z = (wv[r] - mv[0])*mv[1]*lng[r] + lnb[r];
        wv[r] = 1.f / (1.f + expf(-z));
    }
    __syncthreads();
    float* ob = out + (size_t)cb*37*NS;
    ob[tid] = sgv;
    for (int r = 0; r < NR; r++) ob[(size_t)(1+r)*NS + tid] *= wv[r];
}

// ---------------- host ----------------
extern "C" void kernel_launch(void* const* d_in, const int* in_sizes, int n_in,
                              void* d_out, int out_size) {
    (void)in_sizes; (void)n_in; (void)out_size;
    const float* img    = (const float*)d_in[0];
    const float* cap    = (const float*)d_in[1];
    const int*   adjs   = (const int*)d_in[3];
    const float* tsa_lw = (const float*)d_in[5];
    const float* tsa_lb = (const float*)d_in[6];
    const float* tsa_gw = (const float*)d_in[7];
    const float* tsa_gb = (const float*)d_in[8];
    const float* tsa_cw = (const float*)d_in[9];
    const float* tsa_cb = (const float*)d_in[10];
    const float* vl_w   = (const float*)d_in[11];
    const float* vl_b   = (const float*)d_in[12];
    const float* vbn_lg = (const float*)d_in[13];
    const float* vbn_lb = (const float*)d_in[14];
    const float* vg_w   = (const float*)d_in[15];
    const float* vg_b   = (const float*)d_in[16];
    const float* vbn_gg = (const float*)d_in[17];
    const float* vbn_gb = (const float*)d_in[18];
    const float* vc_w   = (const float*)d_in[19];
    const float* vc_b   = (const float*)d_in[20];
    const float* loc_w  = (const float*)d_in[21];
    const float* loc_b  = (const float*)d_in[22];
    const float* par_w  = (const float*)d_in[23];
    const float* par_b  = (const float*)d_in[24];
    const float* glo_w  = (const float*)d_in[25];
    const float* glo_b  = (const float*)d_in[26];
    const float* sim_w  = (const float*)d_in[27];
    const float* sim_b  = (const float*)d_in[28];
    const float* ln_g   = (const float*)d_in[29];
    const float* ln_b   = (const float*)d_in[30];
    float* out = (float*)d_out;

    static bool inited = false;
    static float *p_h, *p_imgave, *p_g, *p_ge, *p_le, *p_attnraw,
                 *p_ctx, *p_imgpar, *p_imgglo, *p_capglo, *p_simpar, *p_part, *p_capave;
    static __nv_bfloat16 *p_wth, *p_wtl;
    if (!inited) {
        cudaGetSymbolAddress((void**)&p_h, g_h);
        cudaGetSymbolAddress((void**)&p_imgave, g_imgave);
        cudaGetSymbolAddress((void**)&p_g, g_g);
        cudaGetSymbolAddress((void**)&p_ge, g_ge);
        cudaGetSymbolAddress((void**)&p_le, g_le);
        cudaGetSymbolAddress((void**)&p_attnraw, g_attnraw);
        cudaGetSymbolAddress((void**)&p_ctx, g_ctx);
        cudaGetSymbolAddress((void**)&p_imgpar, g_imgpar);
        cudaGetSymbolAddress((void**)&p_imgglo, g_imgglo);
        cudaGetSymbolAddress((void**)&p_capglo, g_capglo);
        cudaGetSymbolAddress((void**)&p_simpar, g_simpar);
        cudaGetSymbolAddress((void**)&p_part, g_part);
        cudaGetSymbolAddress((void**)&p_capave, g_capave);
        cudaGetSymbolAddress((void**)&p_wth, g_wth);
        cudaGetSymbolAddress((void**)&p_wtl, g_wtl);
        inited = true;
    }

    const size_t out2off = (size_t)NCAP*NB*37*NS;
    float* out2 = out + out2off;

    // ---- weight transpose + split (cheap, every launch) ----
    k_wsplit<<<1024, 256>>>(loc_w, p_wth,            p_wtl);
    k_wsplit<<<1024, 256>>>(par_w, p_wth + NS*ND,    p_wtl + NS*ND);

    // ---- caption-independent ----
    k_imgave<<<256, 256>>>(img);
    gemm128<0,0,0,0><<<dim3(8, 18), 256>>>(img, nullptr, vl_w, vl_b, p_h, NB*NR, ND, ND);
    k_bnstats<<<NR, 256>>>();
    gemm_small_part<<<dim3(16, 8), 256>>>(p_imgave, vg_w, p_part, NB, ND, ND);
    k_small_epi<0><<<(NB*ND+255)/256, 256>>>(p_part, vg_b, p_g, NB, ND, 8);
    k_gbn<<<4, 256>>>(vbn_gg, vbn_gb);
    k_wraw<<<NB*NR, 256>>>(vc_w, vc_b, vbn_lg, vbn_lb);
    k_newglobal<<<NB, 256>>>(img);
    k_imgpar<<<NB*NR, 256>>>(img, adjs);

    // ---- caption side ----
    k_capave<<<128, 256>>>(cap);
    gemm128<0,0,1,0><<<dim3(8, 10), 256>>>(cap, nullptr, tsa_lw, tsa_lb, p_le, NCAP*NWD, ND, ND);
    gemm_small_part<<<dim3(16, 8), 256>>>(p_capave, tsa_gw, p_part, NCAP, ND, ND);
    k_small_epi<1><<<(NCAP*ND+255)/256, 256>>>(p_part, tsa_gb, p_ge, NCAP, ND, 8);
    k_capglo<<<NCAP, 256>>>(cap, tsa_cw, tsa_cb);

    gemm128<0,1,0,0><<<dim3(18, 10), 256>>>(cap, nullptr, img, nullptr, p_attnraw,
                                            NCAP*NWD, NB*NR, ND);
    k_attnfuse<<<NCAP*NB, 256>>>();
    k_ctx<<<NCAP*NB, 256>>>(cap);
    k_rownorm<<<NCAP*NB*NR, 256>>>(p_ctx, ND);

    // ---- heavy diff-square GEMMs on tensor cores (mma.sync, split-bf16) ----
    hmma_diffsq<0><<<dim3(2, 18, NCAP), 256>>>(p_ctx, img, p_wth, p_wtl, loc_b, out);
    k_rownorm_simloc<<<NCAP*NB*NR, 256>>>(out);
    hmma_diffsq<1><<<dim3(2, 18, NCAP), 256>>>(p_imgpar, p_capglo,
                                               p_wth + NS*ND, p_wtl + NS*ND, par_b, p_simpar);
    k_rownorm<<<NCAP*NB*NR, 256>>>(p_simpar, NS);

    // sim_glo (tiny, fp32)
    gemm_diffsq_glo<<<dim3(4, 1, NCAP), 256>>>(p_imgglo, p_capglo, glo_w, glo_b, out2, NB, NS, ND);
    k_rownorm<<<NCAP*NB, 256>>>(out2, NS);

    // ---- finalize ----
    k_finalize<<<NCAP*NB, 256>>>(sim_w, sim_b, ln_g, ln_b, out, out2off);
}

// round 6
// speedup vs baseline: 2.8874x; 1.0684x over previous
#include <cuda_runtime.h>
#include <cuda_bf16.h>
#include <cstdint>
#include <stdint.h>
#include <math.h>

#define NB 64
#define NR 36
#define ND 1024
#define NCAP 32
#define NWD 40
#define NS 256
#define NPART 5
#define EPSL 1e-8f
#define BNEPS 1e-5f
#define LNEPS 1e-5f
#define SMOOTHF 9.0f

typedef unsigned long long ull;

// ---------------- scratch ----------------
__device__ float g_h[NB*NR*ND];
__device__ float g_imgave[NB*ND];
__device__ float g_bnmu[NR];
__device__ float g_bnvar[NR];
__device__ float g_g[NB*ND];
__device__ float g_wraw[NB*NR];
__device__ float g_imgglo[NB*ND];
__device__ float g_normglo[NB];
__device__ float g_imgpar[NB*NR*ND];
__device__ float g_capave[NCAP*ND];
__device__ float g_le[NCAP*NWD*ND];
__device__ float g_ge[NCAP*ND];
__device__ float g_capglo[NCAP*ND];
__device__ float g_attnraw[(size_t)NCAP*NWD*NB*NR];
__device__ float g_attnT[(size_t)NCAP*NB*NR*NWD];
__device__ float g_ctx[(size_t)NCAP*NB*NR*ND];      // UNNORMALIZED now
__device__ float g_ctxinv[NCAP*NB*NR];              // 1/(||row||+eps)
__device__ float g_simpar[(size_t)NCAP*NB*NR*NS];   // raw (un-normalized)
__device__ float g_part[8*64*1024];
__device__ __nv_bfloat16 g_wth[2][NS*ND];           // loc_w^T, par_w^T hi
__device__ __nv_bfloat16 g_wtl[2][NS*ND];           // lo
__device__ __nv_bfloat16 g_imgh[NB*NR*ND], g_imgl[NB*NR*ND];
__device__ __nv_bfloat16 g_caph[NCAP*NWD*ND], g_capl[NCAP*NWD*ND];
__device__ __nv_bfloat16 g_wbh[2][ND*ND], g_wbl[2][ND*ND];  // vl_w^T, tsa_lw^T

// ---------------- helpers ----------------
__device__ __forceinline__ uint32_t smem_u32(const void* p) {
    uint32_t a;
    asm("{ .reg .u64 t; cvta.to.shared.u64 t, %1; cvt.u32.u64 %0, t; }" : "=r"(a) : "l"(p));
    return a;
}

__device__ __forceinline__ float blockReduceSum256(float v, float* red) {
    int tid = threadIdx.x;
    red[tid] = v; __syncthreads();
    #pragma unroll
    for (int s = 128; s > 0; s >>= 1) {
        if (tid < s) red[tid] += red[tid + s];
        __syncthreads();
    }
    float r = red[0]; __syncthreads();
    return r;
}

#define LDSM4(r0, r1, r2, r3, addr) \
    asm volatile("ldmatrix.sync.aligned.m8n8.x4.shared.b16 {%0,%1,%2,%3}, [%4];" \
        : "=r"(r0), "=r"(r1), "=r"(r2), "=r"(r3) : "r"(addr))

#define MMA_BF16(d, a, b) \
    asm volatile("mma.sync.aligned.m16n8k16.row.col.f32.bf16.bf16.f32 " \
        "{%0,%1,%2,%3}, {%4,%5,%6,%7}, {%8,%9}, {%0,%1,%2,%3};" \
        : "+f"((d)[0]), "+f"((d)[1]), "+f"((d)[2]), "+f"((d)[3]) \
        : "r"((a)[0]), "r"((a)[1]), "r"((a)[2]), "r"((a)[3]), "r"((b)[0]), "r"((b)[1]))

// ---------------- split kernels ----------------
__global__ void k_split(const float* __restrict__ X, __nv_bfloat16* __restrict__ H,
                        __nv_bfloat16* __restrict__ L, int total) {
    int idx = blockIdx.x * 256 + threadIdx.x;
    if (idx >= total) return;
    float v = X[idx];
    __nv_bfloat16 h = __float2bfloat16(v);
    H[idx] = h;
    L[idx] = __float2bfloat16(v - __bfloat162float(h));
}

// W [K][Ncols] row-major -> out [n][k], split
__global__ void k_wsplitT(const float* __restrict__ W, __nv_bfloat16* __restrict__ H,
                          __nv_bfloat16* __restrict__ L, int Ncols, int K) {
    int idx = blockIdx.x * 256 + threadIdx.x;
    if (idx >= Ncols * K) return;
    int n = idx / K, k = idx - n * K;
    float w = W[(size_t)k * Ncols + n];
    __nv_bfloat16 h = __float2bfloat16(w);
    H[idx] = h;
    L[idx] = __float2bfloat16(w - __bfloat162float(h));
}

#define APAD 40

// ============ generic HMMA GEMM on pre-split operands ============
// C[m][n] = act( sum_k A[m][k]*B[n][k] + bias[n] ),  ACT: 0 none, 1 tanh
template<int ACT>
__global__ void __launch_bounds__(256)
hmma_gemm(const __nv_bfloat16* __restrict__ Ah, const __nv_bfloat16* __restrict__ Al,
          const __nv_bfloat16* __restrict__ Bh, const __nv_bfloat16* __restrict__ Bl,
          const float* __restrict__ bias, float* __restrict__ C, int N, int K)
{
    __shared__ __nv_bfloat16 sAh[128][APAD];
    __shared__ __nv_bfloat16 sAl[128][APAD];
    __shared__ __nv_bfloat16 sBh[128][APAD];
    __shared__ __nv_bfloat16 sBl[128][APAD];
    int tid = threadIdx.x, lane = tid & 31, warp = tid >> 5;
    int mw = warp >> 2, nw = warp & 3;
    int n0 = blockIdx.x * 128, m0 = blockIdx.y * 128;
    const __nv_bfloat16* Ah0 = Ah + (size_t)m0 * K;
    const __nv_bfloat16* Al0 = Al + (size_t)m0 * K;
    const __nv_bfloat16* Bh0 = Bh + (size_t)n0 * K;
    const __nv_bfloat16* Bl0 = Bl + (size_t)n0 * K;

    float acc[4][4][4];
    #pragma unroll
    for (int i = 0; i < 4; i++)
        #pragma unroll
        for (int j = 0; j < 4; j++)
            #pragma unroll
            for (int e = 0; e < 4; e++) acc[i][j][e] = 0.f;

    uint32_t aAh = smem_u32(sAh), aAl = smem_u32(sAl);
    uint32_t aBh = smem_u32(sBh), aBl = smem_u32(sBl);
    int a_row = mw*64 + (lane & 15);
    int a_col8 = (lane >> 4) * 8;
    int b_row = nw*32 + (lane >> 4)*8 + (lane & 7);
    int b_col8 = ((lane >> 3) & 1) * 8;

    for (int ch = 0; ch < K/32; ch++) {
        int k0 = ch * 32;
        #pragma unroll
        for (int i = 0; i < 2; i++) {
            int slot = tid + i*256;             // 512 = 128 rows x 4 x 16B
            int row = slot >> 2, c = slot & 3;
            size_t src = (size_t)row*K + k0 + c*8;
            *(uint4*)&sAh[row][c*8] = *(const uint4*)(Ah0 + src);
            *(uint4*)&sAl[row][c*8] = *(const uint4*)(Al0 + src);
            *(uint4*)&sBh[row][c*8] = *(const uint4*)(Bh0 + src);
            *(uint4*)&sBl[row][c*8] = *(const uint4*)(Bl0 + src);
        }
        __syncthreads();
        #pragma unroll
        for (int k16 = 0; k16 < 2; k16++) {
            uint32_t bh[4][2], bl[4][2];
            #pragma unroll
            for (int half = 0; half < 2; half++) {
                uint32_t off = (uint32_t)((b_row + half*16)*APAD + k16*16 + b_col8) * 2;
                uint32_t r0, r1, r2, r3;
                LDSM4(r0, r1, r2, r3, aBh + off);
                bh[half*2+0][0] = r0; bh[half*2+0][1] = r1;
                bh[half*2+1][0] = r2; bh[half*2+1][1] = r3;
                LDSM4(r0, r1, r2, r3, aBl + off);
                bl[half*2+0][0] = r0; bl[half*2+0][1] = r1;
                bl[half*2+1][0] = r2; bl[half*2+1][1] = r3;
            }
            #pragma unroll
            for (int mt = 0; mt < 4; mt++) {
                uint32_t ah[4], al[4];
                uint32_t off = (uint32_t)((a_row + mt*16)*APAD + k16*16 + a_col8) * 2;
                LDSM4(ah[0], ah[1], ah[2], ah[3], aAh + off);
                LDSM4(al[0], al[1], al[2], al[3], aAl + off);
                #pragma unroll
                for (int nt = 0; nt < 4; nt++) {
                    MMA_BF16(acc[mt][nt], ah, bh[nt]);
                    MMA_BF16(acc[mt][nt], ah, bl[nt]);
                    MMA_BF16(acc[mt][nt], al, bh[nt]);
                }
            }
        }
        __syncthreads();
    }

    #pragma unroll
    for (int mt = 0; mt < 4; mt++) {
        int mA = m0 + mw*64 + mt*16 + (lane >> 2);
        int mB = mA + 8;
        float* dA = C + (size_t)mA * N;
        float* dB = C + (size_t)mB * N;
        #pragma unroll
        for (int nt = 0; nt < 4; nt++) {
            int n = n0 + nw*32 + nt*8 + (lane & 3)*2;
            float b0 = 0.f, b1 = 0.f;
            if (bias) { b0 = bias[n]; b1 = bias[n+1]; }
            float v0 = acc[mt][nt][0] + b0, v1 = acc[mt][nt][1] + b1;
            float v2 = acc[mt][nt][2] + b0, v3 = acc[mt][nt][3] + b1;
            if (ACT == 1) { v0 = tanhf(v0); v1 = tanhf(v1); v2 = tanhf(v2); v3 = tanhf(v3); }
            *(float2*)&dA[n] = make_float2(v0, v1);
            *(float2*)&dB[n] = make_float2(v2, v3);
        }
    }
}

// ============ HMMA diff-square GEMM ============
// MODE 0: A = (X*inv - Y)^2, X batched by z (ctx raw), inv per-row, Y=img; scatter out
// MODE 1: A = (X - Yv[z])^2, X shared (imgpar); out -> simpar raw
template<int MODE>
__global__ void __launch_bounds__(256)
hmma_diffsq(const float* __restrict__ X, const float* __restrict__ Y,
            const float* __restrict__ rowinv,
            const __nv_bfloat16* __restrict__ Bh, const __nv_bfloat16* __restrict__ Bl,
            const float* __restrict__ bias, float* __restrict__ outp)
{
    __shared__ __nv_bfloat16 sAh[128][APAD];
    __shared__ __nv_bfloat16 sAl[128][APAD];
    __shared__ __nv_bfloat16 sBh[128][APAD];
    __shared__ __nv_bfloat16 sBl[128][APAD];
    int tid = threadIdx.x;
    int lane = tid & 31, warp = tid >> 5;
    int mw = warp >> 2, nw = warp & 3;
    int n0 = blockIdx.x * 128, m0 = blockIdx.y * 128, z = blockIdx.z;

    const float* Xp = (MODE == 0) ? X + ((size_t)z*2304 + m0)*ND : X + (size_t)m0*ND;
    const float* Yp = (MODE == 0) ? Y + (size_t)m0*ND : Y + (size_t)z*ND;
    const float* invp = (MODE == 0) ? rowinv + (size_t)z*2304 + m0 : nullptr;

    float acc[4][4][4];
    #pragma unroll
    for (int i = 0; i < 4; i++)
        #pragma unroll
        for (int j = 0; j < 4; j++)
            #pragma unroll
            for (int e = 0; e < 4; e++) acc[i][j][e] = 0.f;

    uint32_t aAh = smem_u32(sAh), aAl = smem_u32(sAl);
    uint32_t aBh = smem_u32(sBh), aBl = smem_u32(sBl);
    int a_row = mw*64 + (lane & 15);
    int a_col8 = (lane >> 4) * 8;
    int b_row = nw*32 + (lane >> 4)*8 + (lane & 7);
    int b_col8 = ((lane >> 3) & 1) * 8;

    for (int ch = 0; ch < 32; ch++) {
        int k0 = ch * 32;
        #pragma unroll
        for (int i = 0; i < 4; i++) {
            int slot = tid + i*256;             // 1024 = 128 rows x 8 float4
            int row = slot >> 3, q = slot & 7;
            size_t off = (size_t)row*ND + k0 + q*4;
            float4 xv = *(const float4*)(Xp + off);
            float4 yv;
            if (MODE == 0) yv = *(const float4*)(Yp + off);
            else           yv = *(const float4*)(Yp + k0 + q*4);
            float iv = (MODE == 0) ? invp[row] : 1.f;
            float d0, d1, d2, d3;
            if (MODE == 0) {
                d0 = xv.x*iv - yv.x; d1 = xv.y*iv - yv.y;
                d2 = xv.z*iv - yv.z; d3 = xv.w*iv - yv.w;
            } else {
                d0 = xv.x - yv.x; d1 = xv.y - yv.y;
                d2 = xv.z - yv.z; d3 = xv.w - yv.w;
            }
            float a0 = d0*d0, a1 = d1*d1, a2 = d2*d2, a3 = d3*d3;
            __nv_bfloat162 h01 = __floats2bfloat162_rn(a0, a1);
            __nv_bfloat162 h23 = __floats2bfloat162_rn(a2, a3);
            float r0 = a0 - __bfloat162float(h01.x);
            float r1 = a1 - __bfloat162float(h01.y);
            float r2 = a2 - __bfloat162float(h23.x);
            float r3 = a3 - __bfloat162float(h23.y);
            __nv_bfloat162 l01 = __floats2bfloat162_rn(r0, r1);
            __nv_bfloat162 l23 = __floats2bfloat162_rn(r2, r3);
            *(uint2*)&sAh[row][q*4] = make_uint2(*(uint32_t*)&h01, *(uint32_t*)&h23);
            *(uint2*)&sAl[row][q*4] = make_uint2(*(uint32_t*)&l01, *(uint32_t*)&l23);
        }
        #pragma unroll
        for (int i = 0; i < 2; i++) {
            int slot = tid + i*256;
            int row = slot >> 2, c = slot & 3;
            size_t src = (size_t)(n0 + row)*ND + k0 + c*8;
            *(uint4*)&sBh[row][c*8] = *(const uint4*)(Bh + src);
            *(uint4*)&sBl[row][c*8] = *(const uint4*)(Bl + src);
        }
        __syncthreads();

        #pragma unroll
        for (int k16 = 0; k16 < 2; k16++) {
            uint32_t bh[4][2], bl[4][2];
            #pragma unroll
            for (int half = 0; half < 2; half++) {
                uint32_t off = (uint32_t)((b_row + half*16)*APAD + k16*16 + b_col8) * 2;
                uint32_t r0, r1, r2, r3;
                LDSM4(r0, r1, r2, r3, aBh + off);
                bh[half*2+0][0] = r0; bh[half*2+0][1] = r1;
                bh[half*2+1][0] = r2; bh[half*2+1][1] = r3;
                LDSM4(r0, r1, r2, r3, aBl + off);
                bl[half*2+0][0] = r0; bl[half*2+0][1] = r1;
                bl[half*2+1][0] = r2; bl[half*2+1][1] = r3;
            }
            #pragma unroll
            for (int mt = 0; mt < 4; mt++) {
                uint32_t ah[4], al[4];
                uint32_t off = (uint32_t)((a_row + mt*16)*APAD + k16*16 + a_col8) * 2;
                LDSM4(ah[0], ah[1], ah[2], ah[3], aAh + off);
                LDSM4(al[0], al[1], al[2], al[3], aAl + off);
                #pragma unroll
                for (int nt = 0; nt < 4; nt++) {
                    MMA_BF16(acc[mt][nt], ah, bh[nt]);
                    MMA_BF16(acc[mt][nt], ah, bl[nt]);
                    MMA_BF16(acc[mt][nt], al, bh[nt]);
                }
            }
        }
        __syncthreads();
    }

    #pragma unroll
    for (int mt = 0; mt < 4; mt++) {
        int mA = m0 + mw*64 + mt*16 + (lane >> 2);
        int mB = mA + 8;
        float* dA;
        float* dB;
        if (MODE == 0) {
            int bA = mA / NR, rA = mA % NR;
            int bB = mB / NR, rB = mB % NR;
            dA = outp + (((size_t)z*NB + bA)*37 + 1 + rA)*NS;
            dB = outp + (((size_t)z*NB + bB)*37 + 1 + rB)*NS;
        } else {
            dA = outp + ((size_t)z*2304 + mA)*NS;
            dB = outp + ((size_t)z*2304 + mB)*NS;
        }
        #pragma unroll
        for (int nt = 0; nt < 4; nt++) {
            int n = n0 + nw*32 + nt*8 + (lane & 3)*2;
            float b0 = bias[n], b1 = bias[n+1];
            *(float2*)&dA[n] = make_float2(fmaxf(acc[mt][nt][0] + b0, 0.f),
                                           fmaxf(acc[mt][nt][1] + b1, 0.f));
            *(float2*)&dB[n] = make_float2(fmaxf(acc[mt][nt][2] + b0, 0.f),
                                           fmaxf(acc[mt][nt][3] + b1, 0.f));
        }
    }
}

// ============ small-M GEMM via split-K ============
__global__ void gemm_small_part(const float* __restrict__ A, const float* __restrict__ W,
                                float* __restrict__ part, int M, int N, int K)
{
    const int BK = 16;
    __shared__ float As[BK][64];
    __shared__ float Bs[BK][64];
    int tid = threadIdx.x, tr = tid >> 4, tc = tid & 15;
    int n0 = blockIdx.x * 64;
    int KS = gridDim.y;
    int Kc = K / KS;
    int kz = blockIdx.y;
    float acc[4][4] = {};
    for (int k0 = kz*Kc; k0 < (kz+1)*Kc; k0 += BK) {
        for (int i = tid; i < 64*BK; i += 256) {
            int m = i >> 4, k = i & 15;
            As[k][m] = (m < M) ? A[(size_t)m*K + k0 + k] : 0.f;
        }
        for (int i = tid; i < BK*64; i += 256) {
            int k = i >> 6, n = i & 63;
            Bs[k][n] = W[(size_t)(k0+k)*N + n0 + n];
        }
        __syncthreads();
        #pragma unroll
        for (int k = 0; k < BK; k++) {
            float a[4], b[4];
            #pragma unroll
            for (int i = 0; i < 4; i++) a[i] = As[k][tr*4+i];
            #pragma unroll
            for (int j = 0; j < 4; j++) b[j] = Bs[k][tc*4+j];
            #pragma unroll
            for (int i = 0; i < 4; i++)
                #pragma unroll
                for (int j = 0; j < 4; j++) acc[i][j] += a[i]*b[j];
        }
        __syncthreads();
    }
    #pragma unroll
    for (int i = 0; i < 4; i++) {
        int m = tr*4 + i;
        if (m >= M) continue;
        #pragma unroll
        for (int j = 0; j < 4; j++)
            part[((size_t)kz*M + m)*N + n0 + tc*4 + j] = acc[i][j];
    }
}

template<int ACT>
__global__ void k_small_epi(const float* __restrict__ part, const float* __restrict__ bias,
                            float* __restrict__ C, int M, int N, int KS)
{
    int idx = blockIdx.x*256 + threadIdx.x;
    if (idx >= M*N) return;
    int n = idx % N;
    float s = 0.f;
    for (int kz = 0; kz < KS; kz++) s += part[(size_t)kz*M*N + idx];
    s += bias[n];
    if (ACT == 1) s = tanhf(s);
    C[idx] = s;
}

// ---------------- tiny glo diff-square GEMM ----------------
__global__ void gemm_diffsq_glo(const float* __restrict__ X, const float* __restrict__ Y,
                                const float* __restrict__ W, const float* __restrict__ bias,
                                float* __restrict__ Cbase, int M, int N, int K)
{
    const int BM = 64, BN = 64, BK = 16;
    int c = blockIdx.z;
    const float* Yp = Y + (size_t)c*K;
    __shared__ float As[BK][BM];
    __shared__ float Bs[BK][BN];
    int tid = threadIdx.x;
    int tr = tid >> 4, tc = tid & 15;
    int m0 = blockIdx.y * BM, n0 = blockIdx.x * BN;
    float acc[4][4] = {};
    for (int k0 = 0; k0 < K; k0 += BK) {
        #pragma unroll
        for (int i = tid; i < BM*BK; i += 256) {
            int m = i >> 4, k = i & 15;
            float v = 0.f;
            if (m0 + m < M) {
                float d = X[(size_t)(m0+m)*K + k0 + k] - Yp[k0 + k];
                v = d * d;
            }
            As[k][m] = v;
        }
        #pragma unroll
        for (int i = tid; i < BK*BN; i += 256) {
            int k = i >> 6, n = i & 63;
            Bs[k][n] = W[(size_t)(k0+k)*N + n0 + n];
        }
        __syncthreads();
        #pragma unroll
        for (int k = 0; k < BK; k++) {
            float a[4], b[4];
            #pragma unroll
            for (int i = 0; i < 4; i++) a[i] = As[k][tr*4+i];
            #pragma unroll
            for (int j = 0; j < 4; j++) b[j] = Bs[k][tc*4+j];
            #pragma unroll
            for (int i = 0; i < 4; i++)
                #pragma unroll
                for (int j = 0; j < 4; j++) acc[i][j] += a[i]*b[j];
        }
        __syncthreads();
    }
    #pragma unroll
    for (int i = 0; i < 4; i++) {
        int m = m0 + tr*4 + i;
        if (m >= M) continue;
        #pragma unroll
        for (int j = 0; j < 4; j++) {
            int n = n0 + tc*4 + j;
            float v = fmaxf(acc[i][j] + bias[n], 0.f);
            Cbase[(size_t)c*M*N + (size_t)m*N + n] = v;
        }
    }
}

// ---------------- small kernels ----------------
__global__ void k_imgave(const float* __restrict__ img) {
    int i = blockIdx.x*blockDim.x + threadIdx.x;
    int b = i >> 10, d = i & 1023;
    float s = 0.f;
    for (int r = 0; r < NR; r++) s += img[((size_t)b*NR + r)*ND + d];
    g_imgave[i] = s * (1.f / NR);
}

__global__ void k_bnstats() {
    int r = blockIdx.x;
    __shared__ float red[256], red2[256];
    float s = 0.f, ss = 0.f;
    for (int i = threadIdx.x; i < NB*ND; i += 256) {
        int b = i >> 10, d = i & 1023;
        float v = g_h[((size_t)b*NR + r)*ND + d];
        s += v; ss += v*v;
    }
    red[threadIdx.x] = s; red2[threadIdx.x] = ss; __syncthreads();
    for (int st = 128; st > 0; st >>= 1) {
        if (threadIdx.x < st) { red[threadIdx.x] += red[threadIdx.x+st]; red2[threadIdx.x] += red2[threadIdx.x+st]; }
        __syncthreads();
    }
    if (threadIdx.x == 0) {
        float mu = red[0] / (float)(NB*ND);
        g_bnmu[r] = mu;
        g_bnvar[r] = red2[0] / (float)(NB*ND) - mu*mu;
    }
}

__global__ void k_gbn(const float* __restrict__ gamma, const float* __restrict__ beta) {
    int d = blockIdx.x*blockDim.x + threadIdx.x;
    float s = 0.f, ss = 0.f;
    for (int b = 0; b < NB; b++) { float v = g_g[(size_t)b*ND + d]; s += v; ss += v*v; }
    float mu = s / NB;
    float var = ss / NB - mu*mu;
    float inv = rsqrtf(var + BNEPS);
    float ga = gamma[d], be = beta[d];
    for (int b = 0; b < NB; b++) {
        float v = g_g[(size_t)b*ND + d];
        g_g[(size_t)b*ND + d] = tanhf((v - mu)*inv*ga + be);
    }
}

__global__ void k_wraw(const float* __restrict__ vcw, const float* __restrict__ vcb,
                       const float* __restrict__ lg, const float* __restrict__ lb) {
    int br = blockIdx.x;
    int b = br / NR, r = br % NR;
    __shared__ float red[256];
    float mu = g_bnmu[r], inv = rsqrtf(g_bnvar[r] + BNEPS);
    float ga = lg[r], be = lb[r];
    float s = 0.f;
    for (int d = threadIdx.x; d < ND; d += 256) {
        float le = tanhf((g_h[(size_t)br*ND + d] - mu)*inv*ga + be);
        s += le * g_g[(size_t)b*ND + d] * vcw[d];
    }
    float tot = blockReduceSum256(s, red);
    if (threadIdx.x == 0) g_wraw[br] = tot + vcb[0];
}

__global__ void k_newglobal(const float* __restrict__ img) {
    int b = blockIdx.x;
    __shared__ float w[NR];
    __shared__ float red[256];
    __shared__ float invn;
    if (threadIdx.x == 0) {
        float mx = -1e30f;
        for (int r = 0; r < NR; r++) mx = fmaxf(mx, g_wraw[b*NR + r]);
        float sum = 0.f;
        for (int r = 0; r < NR; r++) { w[r] = expf(g_wraw[b*NR + r] - mx); sum += w[r]; }
        float is = 1.f / sum;
        for (int r = 0; r < NR; r++) w[r] *= is;
    }
    __syncthreads();
    float ssq = 0.f;
    for (int d = threadIdx.x; d < ND; d += 256) {
        float s = 0.f;
        for (int r = 0; r < NR; r++) s += w[r] * img[((size_t)b*NR + r)*ND + d];
        g_imgglo[(size_t)b*ND + d] = s;
        ssq += s*s;
    }
    float tot = blockReduceSum256(ssq, red);
    if (threadIdx.x == 0) {
        float nrm = sqrtf(tot) + EPSL;
        g_normglo[b] = nrm;
        invn = 1.f / nrm;
    }
    __syncthreads();
    for (int d = threadIdx.x; d < ND; d += 256) g_imgglo[(size_t)b*ND + d] *= invn;
}

__global__ void k_imgpar(const float* __restrict__ img, const int* __restrict__ adjs) {
    int br = blockIdx.x;
    int b = br / NR, r = br % NR;
    __shared__ int eff[NPART];
    __shared__ float wg[NPART];
    if (threadIdx.x == 0) {
        int cnt = 0;
        const int* row = adjs + (size_t)b*NR*NR + (size_t)r*NR;
        for (int j = 0; j < NR && cnt < NPART; j++)
            if (row[j] == 1) eff[cnt++] = j;
        for (; cnt < NPART; cnt++) eff[cnt] = r;
        float v[NPART], mx = -1e30f;
        for (int k = 0; k < NPART; k++) { v[k] = g_wraw[b*NR + eff[k]]; mx = fmaxf(mx, v[k]); }
        float sum = 0.f;
        for (int k = 0; k < NPART; k++) { v[k] = expf(v[k] - mx); sum += v[k]; }
        float is = 1.f / sum;
        for (int k = 0; k < NPART; k++) wg[k] = v[k]*is;
    }
    __syncthreads();
    float invn = 1.f / g_normglo[b];
    for (int d = threadIdx.x; d < ND; d += 256) {
        float s = 0.f;
        #pragma unroll
        for (int k = 0; k < NPART; k++) s += wg[k] * img[((size_t)b*NR + eff[k])*ND + d];
        g_imgpar[(size_t)br*ND + d] = s * invn;
    }
}

__global__ void k_capave(const float* __restrict__ cap) {
    int i = blockIdx.x*blockDim.x + threadIdx.x;
    int c = i >> 10, d = i & 1023;
    float s = 0.f;
    for (int n = 0; n < NWD; n++) s += cap[((size_t)c*NWD + n)*ND + d];
    g_capave[i] = s * (1.f / NWD);
}

__global__ void k_capglo(const float* __restrict__ cap, const float* __restrict__ tsacw,
                         const float* __restrict__ tsacb) {
    int c = blockIdx.x;
    __shared__ float red[256];
    __shared__ float cw[NWD];
    __shared__ float invn;
    float gw[4];
    #pragma unroll
    for (int i = 0; i < 4; i++) {
        int d = threadIdx.x + i*256;
        gw[i] = g_ge[(size_t)c*ND + d] * tsacw[d];
    }
    for (int n = 0; n < NWD; n++) {
        float s = 0.f;
        #pragma unroll
        for (int i = 0; i < 4; i++) {
            int d = threadIdx.x + i*256;
            s += g_le[((size_t)c*NWD + n)*ND + d] * gw[i];
        }
        float tot = blockReduceSum256(s, red);
        if (threadIdx.x == 0) cw[n] = tot + tsacb[0];
    }
    __syncthreads();
    if (threadIdx.x == 0) {
        float mx = -1e30f;
        for (int n = 0; n < NWD; n++) mx = fmaxf(mx, cw[n]);
        float sum = 0.f;
        for (int n = 0; n < NWD; n++) { cw[n] = expf(cw[n] - mx); sum += cw[n]; }
        float is = 1.f / sum;
        for (int n = 0; n < NWD; n++) cw[n] *= is;
    }
    __syncthreads();
    float ssq = 0.f;
    #pragma unroll
    for (int i = 0; i < 4; i++) {
        int d = threadIdx.x + i*256;
        float s = 0.f;
        for (int n = 0; n < NWD; n++) s += cw[n] * cap[((size_t)c*NWD + n)*ND + d];
        g_capglo[(size_t)c*ND + d] = s;
        ssq += s*s;
    }
    float tot = blockReduceSum256(ssq, red);
    if (threadIdx.x == 0) invn = 1.f / (sqrtf(tot) + EPSL);
    __syncthreads();
    #pragma unroll
    for (int i = 0; i < 4; i++) {
        int d = threadIdx.x + i*256;
        g_capglo[(size_t)c*ND + d] *= invn;
    }
}

__global__ void k_attnfuse() {
    int cb = blockIdx.x;
    int c = cb / NB, b = cb % NB;
    __shared__ float sA[NWD*NR];
    __shared__ float nrm[NWD];
    const float* raw = g_attnraw + (size_t)c*NWD*NB*NR;
    for (int i = threadIdx.x; i < NWD*NR; i += 256) {
        int n = i / NR, r = i % NR;
        float v = raw[(size_t)n*NB*NR + (size_t)b*NR + r];
        v = (v > 0.f) ? v : 0.1f*v;
        sA[i] = v;
    }
    __syncthreads();
    if (threadIdx.x < NWD) {
        int n = threadIdx.x;
        float s = 0.f;
        for (int r = 0; r < NR; r++) { float v = sA[n*NR + r]; s += v*v; }
        nrm[n] = 1.f / (sqrtf(s) + EPSL);
    }
    __syncthreads();
    if (threadIdx.x < NR) {
        int r = threadIdx.x;
        float vals[NWD];
        float mx = -1e30f;
        for (int n = 0; n < NWD; n++) {
            float v = SMOOTHF * sA[n*NR + r] * nrm[n];
            vals[n] = v;
            mx = fmaxf(mx, v);
        }
        float sum = 0.f;
        for (int n = 0; n < NWD; n++) { vals[n] = expf(vals[n] - mx); sum += vals[n]; }
        float is = 1.f / sum;
        float* outp = g_attnT + ((size_t)cb*NR + r)*NWD;
        for (int n = 0; n < NWD; n++) outp[n] = vals[n]*is;
    }
}

// ctx (unnormalized) + per-row inv-norm
__global__ void k_ctx(const float* __restrict__ cap) {
    int cb = blockIdx.x;
    int c = cb / NB;
    __shared__ float sT[NR*NWD];
    __shared__ float sW[8][NR];
    int tid = threadIdx.x;
    int lane = tid & 31, warp = tid >> 5;
    const float* at = g_attnT + (size_t)cb*NR*NWD;
    for (int i = tid; i < NR*NWD; i += 256) sT[i] = at[i];
    __syncthreads();
    float* outp = g_ctx + (size_t)cb*NR*ND;
    float ssq_l[NR];
    #pragma unroll
    for (int r = 0; r < NR; r++) ssq_l[r] = 0.f;
    for (int it = 0; it < 4; it++) {
        int d = tid + it*256;
        float acc[NR];
        #pragma unroll
        for (int r = 0; r < NR; r++) acc[r] = 0.f;
        for (int n = 0; n < NWD; n++) {
            float cv = cap[((size_t)c*NWD + n)*ND + d];
            #pragma unroll
            for (int r = 0; r < NR; r++) acc[r] += sT[r*NWD + n] * cv;
        }
        #pragma unroll
        for (int r = 0; r < NR; r++) {
            outp[(size_t)r*ND + d] = acc[r];
            ssq_l[r] += acc[r]*acc[r];
        }
    }
    #pragma unroll
    for (int r = 0; r < NR; r++) {
        float v = ssq_l[r];
        v += __shfl_xor_sync(0xffffffffu, v, 16);
        v += __shfl_xor_sync(0xffffffffu, v, 8);
        v += __shfl_xor_sync(0xffffffffu, v, 4);
        v += __shfl_xor_sync(0xffffffffu, v, 2);
        v += __shfl_xor_sync(0xffffffffu, v, 1);
        if (lane == 0) sW[warp][r] = v;
    }
    __syncthreads();
    if (tid < NR) {
        float s = 0.f;
        #pragma unroll
        for (int w = 0; w < 8; w++) s += sW[w][tid];
        g_ctxinv[cb*NR + tid] = 1.f / (sqrtf(s) + EPSL);
    }
}

__global__ void k_rownorm(float* __restrict__ X, int L) {
    size_t row = blockIdx.x;
    float* p = X + row*(size_t)L;
    __shared__ float red[256];
    __shared__ float invn;
    float s = 0.f;
    for (int i = threadIdx.x; i < L; i += 256) { float v = p[i]; s += v*v; }
    float tot = blockReduceSum256(s, red);
    if (threadIdx.x == 0) invn = 1.f / (sqrtf(tot) + EPSL);
    __syncthreads();
    for (int i = threadIdx.x; i < L; i += 256) p[i] *= invn;
}

__global__ void k_rownorm_simloc(float* __restrict__ out) {
    int row = blockIdx.x;
    int cb = row / NR, r = row % NR;
    float* p = out + ((size_t)cb*37 + 1 + r)*NS;
    __shared__ float red[256];
    __shared__ float invn;
    float v = p[threadIdx.x];
    float tot = blockReduceSum256(v*v, red);
    if (threadIdx.x == 0) invn = 1.f / (sqrtf(tot) + EPSL);
    __syncthreads();
    p[threadIdx.x] = v * invn;
}

// finalize with simpar row-norm fused (simpar is raw)
__global__ void k_finalize(const float* __restrict__ simw, const float* __restrict__ simb,
                           const float* __restrict__ lng, const float* __restrict__ lnb,
                           float* __restrict__ out, size_t out2off) {
    int cb = blockIdx.x;
    int tid = threadIdx.x;
    const float* sg = out + out2off + (size_t)cb*NS;
    __shared__ float red[256], red2[256];
    __shared__ float wv[NR];
    __shared__ float mv[2];
    float sgv = sg[tid];
    float sgw = sgv * simw[tid];
    const float* sp = g_simpar + (size_t)cb*NR*NS;
    for (int r = 0; r < NR; r++) {
        float v = sp[(size_t)r*NS + tid];
        red[tid] = v * sgw;
        red2[tid] = v * v;
        __syncthreads();
        #pragma unroll
        for (int s = 128; s > 0; s >>= 1) {
            if (tid < s) { red[tid] += red[tid+s]; red2[tid] += red2[tid+s]; }
            __syncthreads();
        }
        if (tid == 0) wv[r] = red[0] / (sqrtf(red2[0]) + EPSL) + simb[0];
        __syncthreads();
    }
    if (tid == 0) {
        float m = 0.f;
        for (int r = 0; r < NR; r++) m += wv[r];
        m /= NR;
        float v = 0.f;
        for (int r = 0; r < NR; r++) { float d = wv[r] - m; v += d*d; }
        v /= NR;
        mv[0] = m; mv[1] = rsqrtf(v + LNEPS);
    }
    __syncthreads();
    if (tid < NR) {
        int r = tid;
        float z = (wv[r] - mv[0])*mv[1]*lng[r] + lnb[r];
        wv[r] = 1.f / (1.f + expf(-z));
    }
    __syncthreads();
    float* ob = out + (size_t)cb*37*NS;
    ob[tid] = sgv;
    for (int r = 0; r < NR; r++) ob[(size_t)(1+r)*NS + tid] *= wv[r];
}

// ---------------- host ----------------
extern "C" void kernel_launch(void* const* d_in, const int* in_sizes, int n_in,
                              void* d_out, int out_size) {
    (void)in_sizes; (void)n_in; (void)out_size;
    const float* img    = (const float*)d_in[0];
    const float* cap    = (const float*)d_in[1];
    const int*   adjs   = (const int*)d_in[3];
    const float* tsa_lw = (const float*)d_in[5];
    const float* tsa_lb = (const float*)d_in[6];
    const float* tsa_gw = (const float*)d_in[7];
    const float* tsa_gb = (const float*)d_in[8];
    const float* tsa_cw = (const float*)d_in[9];
    const float* tsa_cb = (const float*)d_in[10];
    const float* vl_w   = (const float*)d_in[11];
    const float* vl_b   = (const float*)d_in[12];
    const float* vbn_lg = (const float*)d_in[13];
    const float* vbn_lb = (const float*)d_in[14];
    const float* vg_w   = (const float*)d_in[15];
    const float* vg_b   = (const float*)d_in[16];
    const float* vbn_gg = (const float*)d_in[17];
    const float* vbn_gb = (const float*)d_in[18];
    const float* vc_w   = (const float*)d_in[19];
    const float* vc_b   = (const float*)d_in[20];
    const float* loc_w  = (const float*)d_in[21];
    const float* loc_b  = (const float*)d_in[22];
    const float* par_w  = (const float*)d_in[23];
    const float* par_b  = (const float*)d_in[24];
    const float* glo_w  = (const float*)d_in[25];
    const float* glo_b  = (const float*)d_in[26];
    const float* sim_w  = (const float*)d_in[27];
    const float* sim_b  = (const float*)d_in[28];
    const float* ln_g   = (const float*)d_in[29];
    const float* ln_b   = (const float*)d_in[30];
    float* out = (float*)d_out;

    static bool inited = false;
    static float *p_h, *p_imgave, *p_g, *p_ge, *p_le, *p_attnraw,
                 *p_ctx, *p_ctxinv, *p_imgpar, *p_imgglo, *p_capglo, *p_simpar, *p_part, *p_capave;
    static __nv_bfloat16 *p_wth, *p_wtl, *p_imgh, *p_imgl, *p_caph, *p_capl, *p_wbh, *p_wbl;
    if (!inited) {
        cudaGetSymbolAddress((void**)&p_h, g_h);
        cudaGetSymbolAddress((void**)&p_imgave, g_imgave);
        cudaGetSymbolAddress((void**)&p_g, g_g);
        cudaGetSymbolAddress((void**)&p_ge, g_ge);
        cudaGetSymbolAddress((void**)&p_le, g_le);
        cudaGetSymbolAddress((void**)&p_attnraw, g_attnraw);
        cudaGetSymbolAddress((void**)&p_ctx, g_ctx);
        cudaGetSymbolAddress((void**)&p_ctxinv, g_ctxinv);
        cudaGetSymbolAddress((void**)&p_imgpar, g_imgpar);
        cudaGetSymbolAddress((void**)&p_imgglo, g_imgglo);
        cudaGetSymbolAddress((void**)&p_capglo, g_capglo);
        cudaGetSymbolAddress((void**)&p_simpar, g_simpar);
        cudaGetSymbolAddress((void**)&p_part, g_part);
        cudaGetSymbolAddress((void**)&p_capave, g_capave);
        cudaGetSymbolAddress((void**)&p_wth, g_wth);
        cudaGetSymbolAddress((void**)&p_wtl, g_wtl);
        cudaGetSymbolAddress((void**)&p_imgh, g_imgh);
        cudaGetSymbolAddress((void**)&p_imgl, g_imgl);
        cudaGetSymbolAddress((void**)&p_caph, g_caph);
        cudaGetSymbolAddress((void**)&p_capl, g_capl);
        cudaGetSymbolAddress((void**)&p_wbh, g_wbh);
        cudaGetSymbolAddress((void**)&p_wbl, g_wbl);
        inited = true;
    }

    const size_t out2off = (size_t)NCAP*NB*37*NS;
    float* out2 = out + out2off;

    // ---- operand splits ----
    k_split<<<(NB*NR*ND+255)/256, 256>>>(img, p_imgh, p_imgl, NB*NR*ND);
    k_split<<<(NCAP*NWD*ND+255)/256, 256>>>(cap, p_caph, p_capl, NCAP*NWD*ND);
    k_wsplitT<<<(ND*ND+255)/256, 256>>>(vl_w,   p_wbh,         p_wbl,         ND, ND);
    k_wsplitT<<<(ND*ND+255)/256, 256>>>(tsa_lw, p_wbh + ND*ND, p_wbl + ND*ND, ND, ND);
    k_wsplitT<<<(NS*ND+255)/256, 256>>>(loc_w,  p_wth,         p_wtl,         NS, ND);
    k_wsplitT<<<(NS*ND+255)/256, 256>>>(par_w,  p_wth + NS*ND, p_wtl + NS*ND, NS, ND);

    // ---- caption-independent ----
    k_imgave<<<256, 256>>>(img);
    // h = img @ vl_w + vl_b   (HMMA)
    hmma_gemm<0><<<dim3(8, 18), 256>>>(p_imgh, p_imgl, p_wbh, p_wbl, vl_b, p_h, ND, ND);
    k_bnstats<<<NR, 256>>>();
    gemm_small_part<<<dim3(16, 8), 256>>>(p_imgave, vg_w, p_part, NB, ND, ND);
    k_small_epi<0><<<(NB*ND+255)/256, 256>>>(p_part, vg_b, p_g, NB, ND, 8);
    k_gbn<<<4, 256>>>(vbn_gg, vbn_gb);
    k_wraw<<<NB*NR, 256>>>(vc_w, vc_b, vbn_lg, vbn_lb);
    k_newglobal<<<NB, 256>>>(img);
    k_imgpar<<<NB*NR, 256>>>(img, adjs);

    // ---- caption side ----
    k_capave<<<128, 256>>>(cap);
    // le = tanh(cap @ tsa_lw + tsa_lb)  (HMMA)
    hmma_gemm<1><<<dim3(8, 10), 256>>>(p_caph, p_capl, p_wbh + ND*ND, p_wbl + ND*ND,
                                       tsa_lb, p_le, ND, ND);
    gemm_small_part<<<dim3(16, 8), 256>>>(p_capave, tsa_gw, p_part, NCAP, ND, ND);
    k_small_epi<1><<<(NCAP*ND+255)/256, 256>>>(p_part, tsa_gb, p_ge, NCAP, ND, 8);
    k_capglo<<<NCAP, 256>>>(cap, tsa_cw, tsa_cb);

    // attn = cap @ img^T  (HMMA, no bias)
    hmma_gemm<0><<<dim3(18, 10), 256>>>(p_caph, p_capl, p_imgh, p_imgl,
                                        nullptr, p_attnraw, NB*NR, ND);
    k_attnfuse<<<NCAP*NB, 256>>>();
    k_ctx<<<NCAP*NB, 256>>>(cap);   // writes raw ctx + g_ctxinv

    // ---- heavy diff-square GEMMs (HMMA split-bf16) ----
    hmma_diffsq<0><<<dim3(2, 18, NCAP), 256>>>(p_ctx, img, p_ctxinv, p_wth, p_wtl, loc_b, out);
    k_rownorm_simloc<<<NCAP*NB*NR, 256>>>(out);
    hmma_diffsq<1><<<dim3(2, 18, NCAP), 256>>>(p_imgpar, p_capglo, nullptr,
                                               p_wth + NS*ND, p_wtl + NS*ND, par_b, p_simpar);

    // sim_glo (tiny, fp32)
    gemm_diffsq_glo<<<dim3(4, 1, NCAP), 256>>>(p_imgglo, p_capglo, glo_w, glo_b, out2, NB, NS, ND);
    k_rownorm<<<NCAP*NB, 256>>>(out2, NS);

    // ---- finalize (simpar norm fused) ----
    k_finalize<<<NCAP*NB, 256>>>(sim_w, sim_b, ln_g, ln_b, out, out2off);
}

// round 7
// speedup vs baseline: 3.2346x; 1.1202x over previous
#include <cuda_runtime.h>
#include <cuda_bf16.h>
#include <cstdint>
#include <stdint.h>
#include <math.h>

#define NB 64
#define NR 36
#define ND 1024
#define NCAP 32
#define NWD 40
#define NS 256
#define NPART 5
#define EPSL 1e-8f
#define BNEPS 1e-5f
#define LNEPS 1e-5f
#define SMOOTHF 9.0f

typedef unsigned long long ull;

// ---------------- scratch ----------------
__device__ float g_h[NB*NR*ND];
__device__ float g_imgave[NB*ND];
__device__ float g_bnmu[NR];
__device__ float g_bnvar[NR];
__device__ float g_g[NB*ND];
__device__ float g_wraw[NB*NR];
__device__ float g_imgglo[NB*ND];
__device__ float g_normglo[NB];
__device__ float g_imgpar[NB*NR*ND];
__device__ float g_capave[NCAP*ND];
__device__ float g_le[NCAP*NWD*ND];
__device__ float g_ge[NCAP*ND];
__device__ float g_capglo[NCAP*ND];
__device__ float g_attnraw[(size_t)NCAP*NWD*NB*NR];
__device__ float g_attnT[(size_t)NCAP*NB*NR*NWD];
__device__ float g_ctx[(size_t)NCAP*NB*NR*ND];      // unnormalized
__device__ float g_ctxinv[NCAP*NB*NR];              // 1/(||row||+eps)
__device__ float g_simpar[(size_t)NCAP*NB*NR*NS];   // raw (un-normalized)
__device__ float g_part[8*64*1024];
__device__ __nv_bfloat16 g_wth[2][NS*ND];           // loc_w^T, par_w^T hi
__device__ __nv_bfloat16 g_wtl[2][NS*ND];           // lo
__device__ __nv_bfloat16 g_imgh[NB*NR*ND], g_imgl[NB*NR*ND];
__device__ __nv_bfloat16 g_caph[NCAP*NWD*ND], g_capl[NCAP*NWD*ND];
__device__ __nv_bfloat16 g_wbh[2][ND*ND], g_wbl[2][ND*ND];  // vl_w^T, tsa_lw^T

// ---------------- helpers ----------------
__device__ __forceinline__ uint32_t smem_u32(const void* p) {
    uint32_t a;
    asm("{ .reg .u64 t; cvta.to.shared.u64 t, %1; cvt.u32.u64 %0, t; }" : "=r"(a) : "l"(p));
    return a;
}

__device__ __forceinline__ float blockReduceSum256(float v, float* red) {
    int tid = threadIdx.x;
    red[tid] = v; __syncthreads();
    #pragma unroll
    for (int s = 128; s > 0; s >>= 1) {
        if (tid < s) red[tid] += red[tid + s];
        __syncthreads();
    }
    float r = red[0]; __syncthreads();
    return r;
}

__device__ __forceinline__ float warpReduceSum(float v) {
    v += __shfl_xor_sync(0xffffffffu, v, 16);
    v += __shfl_xor_sync(0xffffffffu, v, 8);
    v += __shfl_xor_sync(0xffffffffu, v, 4);
    v += __shfl_xor_sync(0xffffffffu, v, 2);
    v += __shfl_xor_sync(0xffffffffu, v, 1);
    return v;
}

#define LDSM4(r0, r1, r2, r3, addr) \
    asm volatile("ldmatrix.sync.aligned.m8n8.x4.shared.b16 {%0,%1,%2,%3}, [%4];" \
        : "=r"(r0), "=r"(r1), "=r"(r2), "=r"(r3) : "r"(addr))

#define MMA_BF16(d, a, b) \
    asm volatile("mma.sync.aligned.m16n8k16.row.col.f32.bf16.bf16.f32 " \
        "{%0,%1,%2,%3}, {%4,%5,%6,%7}, {%8,%9}, {%0,%1,%2,%3};" \
        : "+f"((d)[0]), "+f"((d)[1]), "+f"((d)[2]), "+f"((d)[3]) \
        : "r"((a)[0]), "r"((a)[1]), "r"((a)[2]), "r"((a)[3]), "r"((b)[0]), "r"((b)[1]))

// ---------------- split kernels ----------------
__global__ void k_split(const float* __restrict__ X, __nv_bfloat16* __restrict__ H,
                        __nv_bfloat16* __restrict__ L, int total) {
    int idx = blockIdx.x * 256 + threadIdx.x;
    if (idx >= total) return;
    float v = X[idx];
    __nv_bfloat16 h = __float2bfloat16(v);
    H[idx] = h;
    L[idx] = __float2bfloat16(v - __bfloat162float(h));
}

// W [K][Ncols] row-major -> out [n][k], split
__global__ void k_wsplitT(const float* __restrict__ W, __nv_bfloat16* __restrict__ H,
                          __nv_bfloat16* __restrict__ L, int Ncols, int K) {
    int idx = blockIdx.x * 256 + threadIdx.x;
    if (idx >= Ncols * K) return;
    int n = idx / K, k = idx - n * K;
    float w = W[(size_t)k * Ncols + n];
    __nv_bfloat16 h = __float2bfloat16(w);
    H[idx] = h;
    L[idx] = __float2bfloat16(w - __bfloat162float(h));
}

#define APAD 40

// ============ generic HMMA GEMM on pre-split operands ============
template<int ACT>
__global__ void __launch_bounds__(256)
hmma_gemm(const __nv_bfloat16* __restrict__ Ah, const __nv_bfloat16* __restrict__ Al,
          const __nv_bfloat16* __restrict__ Bh, const __nv_bfloat16* __restrict__ Bl,
          const float* __restrict__ bias, float* __restrict__ C, int N, int K)
{
    __shared__ __nv_bfloat16 sAh[128][APAD];
    __shared__ __nv_bfloat16 sAl[128][APAD];
    __shared__ __nv_bfloat16 sBh[128][APAD];
    __shared__ __nv_bfloat16 sBl[128][APAD];
    int tid = threadIdx.x, lane = tid & 31, warp = tid >> 5;
    int mw = warp >> 2, nw = warp & 3;
    int n0 = blockIdx.x * 128, m0 = blockIdx.y * 128;
    const __nv_bfloat16* Ah0 = Ah + (size_t)m0 * K;
    const __nv_bfloat16* Al0 = Al + (size_t)m0 * K;
    const __nv_bfloat16* Bh0 = Bh + (size_t)n0 * K;
    const __nv_bfloat16* Bl0 = Bl + (size_t)n0 * K;

    float acc[4][4][4];
    #pragma unroll
    for (int i = 0; i < 4; i++)
        #pragma unroll
        for (int j = 0; j < 4; j++)
            #pragma unroll
            for (int e = 0; e < 4; e++) acc[i][j][e] = 0.f;

    uint32_t aAh = smem_u32(sAh), aAl = smem_u32(sAl);
    uint32_t aBh = smem_u32(sBh), aBl = smem_u32(sBl);
    int a_row = mw*64 + (lane & 15);
    int a_col8 = (lane >> 4) * 8;
    int b_row = nw*32 + (lane >> 4)*8 + (lane & 7);
    int b_col8 = ((lane >> 3) & 1) * 8;

    for (int ch = 0; ch < K/32; ch++) {
        int k0 = ch * 32;
        #pragma unroll
        for (int i = 0; i < 2; i++) {
            int slot = tid + i*256;
            int row = slot >> 2, c = slot & 3;
            size_t src = (size_t)row*K + k0 + c*8;
            *(uint4*)&sAh[row][c*8] = *(const uint4*)(Ah0 + src);
            *(uint4*)&sAl[row][c*8] = *(const uint4*)(Al0 + src);
            *(uint4*)&sBh[row][c*8] = *(const uint4*)(Bh0 + src);
            *(uint4*)&sBl[row][c*8] = *(const uint4*)(Bl0 + src);
        }
        __syncthreads();
        #pragma unroll
        for (int k16 = 0; k16 < 2; k16++) {
            uint32_t bh[4][2], bl[4][2];
            #pragma unroll
            for (int half = 0; half < 2; half++) {
                uint32_t off = (uint32_t)((b_row + half*16)*APAD + k16*16 + b_col8) * 2;
                uint32_t r0, r1, r2, r3;
                LDSM4(r0, r1, r2, r3, aBh + off);
                bh[half*2+0][0] = r0; bh[half*2+0][1] = r1;
                bh[half*2+1][0] = r2; bh[half*2+1][1] = r3;
                LDSM4(r0, r1, r2, r3, aBl + off);
                bl[half*2+0][0] = r0; bl[half*2+0][1] = r1;
                bl[half*2+1][0] = r2; bl[half*2+1][1] = r3;
            }
            #pragma unroll
            for (int mt = 0; mt < 4; mt++) {
                uint32_t ah[4], al[4];
                uint32_t off = (uint32_t)((a_row + mt*16)*APAD + k16*16 + a_col8) * 2;
                LDSM4(ah[0], ah[1], ah[2], ah[3], aAh + off);
                LDSM4(al[0], al[1], al[2], al[3], aAl + off);
                #pragma unroll
                for (int nt = 0; nt < 4; nt++) {
                    MMA_BF16(acc[mt][nt], ah, bh[nt]);
                    MMA_BF16(acc[mt][nt], ah, bl[nt]);
                    MMA_BF16(acc[mt][nt], al, bh[nt]);
                }
            }
        }
        __syncthreads();
    }

    #pragma unroll
    for (int mt = 0; mt < 4; mt++) {
        int mA = m0 + mw*64 + mt*16 + (lane >> 2);
        int mB = mA + 8;
        float* dA = C + (size_t)mA * N;
        float* dB = C + (size_t)mB * N;
        #pragma unroll
        for (int nt = 0; nt < 4; nt++) {
            int n = n0 + nw*32 + nt*8 + (lane & 3)*2;
            float b0 = 0.f, b1 = 0.f;
            if (bias) { b0 = bias[n]; b1 = bias[n+1]; }
            float v0 = acc[mt][nt][0] + b0, v1 = acc[mt][nt][1] + b1;
            float v2 = acc[mt][nt][2] + b0, v3 = acc[mt][nt][3] + b1;
            if (ACT == 1) { v0 = tanhf(v0); v1 = tanhf(v1); v2 = tanhf(v2); v3 = tanhf(v3); }
            *(float2*)&dA[n] = make_float2(v0, v1);
            *(float2*)&dB[n] = make_float2(v2, v3);
        }
    }
}

// ============ HMMA diff-square GEMM ============
template<int MODE>
__global__ void __launch_bounds__(256)
hmma_diffsq(const float* __restrict__ X, const float* __restrict__ Y,
            const float* __restrict__ rowinv,
            const __nv_bfloat16* __restrict__ Bh, const __nv_bfloat16* __restrict__ Bl,
            const float* __restrict__ bias, float* __restrict__ outp)
{
    __shared__ __nv_bfloat16 sAh[128][APAD];
    __shared__ __nv_bfloat16 sAl[128][APAD];
    __shared__ __nv_bfloat16 sBh[128][APAD];
    __shared__ __nv_bfloat16 sBl[128][APAD];
    int tid = threadIdx.x;
    int lane = tid & 31, warp = tid >> 5;
    int mw = warp >> 2, nw = warp & 3;
    int n0 = blockIdx.x * 128, m0 = blockIdx.y * 128, z = blockIdx.z;

    const float* Xp = (MODE == 0) ? X + ((size_t)z*2304 + m0)*ND : X + (size_t)m0*ND;
    const float* Yp = (MODE == 0) ? Y + (size_t)m0*ND : Y + (size_t)z*ND;
    const float* invp = (MODE == 0) ? rowinv + (size_t)z*2304 + m0 : nullptr;

    float acc[4][4][4];
    #pragma unroll
    for (int i = 0; i < 4; i++)
        #pragma unroll
        for (int j = 0; j < 4; j++)
            #pragma unroll
            for (int e = 0; e < 4; e++) acc[i][j][e] = 0.f;

    uint32_t aAh = smem_u32(sAh), aAl = smem_u32(sAl);
    uint32_t aBh = smem_u32(sBh), aBl = smem_u32(sBl);
    int a_row = mw*64 + (lane & 15);
    int a_col8 = (lane >> 4) * 8;
    int b_row = nw*32 + (lane >> 4)*8 + (lane & 7);
    int b_col8 = ((lane >> 3) & 1) * 8;

    for (int ch = 0; ch < 32; ch++) {
        int k0 = ch * 32;
        #pragma unroll
        for (int i = 0; i < 4; i++) {
            int slot = tid + i*256;
            int row = slot >> 3, q = slot & 7;
            size_t off = (size_t)row*ND + k0 + q*4;
            float4 xv = *(const float4*)(Xp + off);
            float4 yv;
            if (MODE == 0) yv = *(const float4*)(Yp + off);
            else           yv = *(const float4*)(Yp + k0 + q*4);
            float iv = (MODE == 0) ? invp[row] : 1.f;
            float d0, d1, d2, d3;
            if (MODE == 0) {
                d0 = xv.x*iv - yv.x; d1 = xv.y*iv - yv.y;
                d2 = xv.z*iv - yv.z; d3 = xv.w*iv - yv.w;
            } else {
                d0 = xv.x - yv.x; d1 = xv.y - yv.y;
                d2 = xv.z - yv.z; d3 = xv.w - yv.w;
            }
            float a0 = d0*d0, a1 = d1*d1, a2 = d2*d2, a3 = d3*d3;
            __nv_bfloat162 h01 = __floats2bfloat162_rn(a0, a1);
            __nv_bfloat162 h23 = __floats2bfloat162_rn(a2, a3);
            float r0 = a0 - __bfloat162float(h01.x);
            float r1 = a1 - __bfloat162float(h01.y);
            float r2 = a2 - __bfloat162float(h23.x);
            float r3 = a3 - __bfloat162float(h23.y);
            __nv_bfloat162 l01 = __floats2bfloat162_rn(r0, r1);
            __nv_bfloat162 l23 = __floats2bfloat162_rn(r2, r3);
            *(uint2*)&sAh[row][q*4] = make_uint2(*(uint32_t*)&h01, *(uint32_t*)&h23);
            *(uint2*)&sAl[row][q*4] = make_uint2(*(uint32_t*)&l01, *(uint32_t*)&l23);
        }
        #pragma unroll
        for (int i = 0; i < 2; i++) {
            int slot = tid + i*256;
            int row = slot >> 2, c = slot & 3;
            size_t src = (size_t)(n0 + row)*ND + k0 + c*8;
            *(uint4*)&sBh[row][c*8] = *(const uint4*)(Bh + src);
            *(uint4*)&sBl[row][c*8] = *(const uint4*)(Bl + src);
        }
        __syncthreads();

        #pragma unroll
        for (int k16 = 0; k16 < 2; k16++) {
            uint32_t bh[4][2], bl[4][2];
            #pragma unroll
            for (int half = 0; half < 2; half++) {
                uint32_t off = (uint32_t)((b_row + half*16)*APAD + k16*16 + b_col8) * 2;
                uint32_t r0, r1, r2, r3;
                LDSM4(r0, r1, r2, r3, aBh + off);
                bh[half*2+0][0] = r0; bh[half*2+0][1] = r1;
                bh[half*2+1][0] = r2; bh[half*2+1][1] = r3;
                LDSM4(r0, r1, r2, r3, aBl + off);
                bl[half*2+0][0] = r0; bl[half*2+0][1] = r1;
                bl[half*2+1][0] = r2; bl[half*2+1][1] = r3;
            }
            #pragma unroll
            for (int mt = 0; mt < 4; mt++) {
                uint32_t ah[4], al[4];
                uint32_t off = (uint32_t)((a_row + mt*16)*APAD + k16*16 + a_col8) * 2;
                LDSM4(ah[0], ah[1], ah[2], ah[3], aAh + off);
                LDSM4(al[0], al[1], al[2], al[3], aAl + off);
                #pragma unroll
                for (int nt = 0; nt < 4; nt++) {
                    MMA_BF16(acc[mt][nt], ah, bh[nt]);
                    MMA_BF16(acc[mt][nt], ah, bl[nt]);
                    MMA_BF16(acc[mt][nt], al, bh[nt]);
                }
            }
        }
        __syncthreads();
    }

    #pragma unroll
    for (int mt = 0; mt < 4; mt++) {
        int mA = m0 + mw*64 + mt*16 + (lane >> 2);
        int mB = mA + 8;
        float* dA;
        float* dB;
        if (MODE == 0) {
            int bA = mA / NR, rA = mA % NR;
            int bB = mB / NR, rB = mB % NR;
            dA = outp + (((size_t)z*NB + bA)*37 + 1 + rA)*NS;
            dB = outp + (((size_t)z*NB + bB)*37 + 1 + rB)*NS;
        } else {
            dA = outp + ((size_t)z*2304 + mA)*NS;
            dB = outp + ((size_t)z*2304 + mB)*NS;
        }
        #pragma unroll
        for (int nt = 0; nt < 4; nt++) {
            int n = n0 + nw*32 + nt*8 + (lane & 3)*2;
            float b0 = bias[n], b1 = bias[n+1];
            *(float2*)&dA[n] = make_float2(fmaxf(acc[mt][nt][0] + b0, 0.f),
                                           fmaxf(acc[mt][nt][1] + b1, 0.f));
            *(float2*)&dB[n] = make_float2(fmaxf(acc[mt][nt][2] + b0, 0.f),
                                           fmaxf(acc[mt][nt][3] + b1, 0.f));
        }
    }
}

// ============ small-M GEMM via split-K ============
__global__ void gemm_small_part(const float* __restrict__ A, const float* __restrict__ W,
                                float* __restrict__ part, int M, int N, int K)
{
    const int BK = 16;
    __shared__ float As[BK][64];
    __shared__ float Bs[BK][64];
    int tid = threadIdx.x, tr = tid >> 4, tc = tid & 15;
    int n0 = blockIdx.x * 64;
    int KS = gridDim.y;
    int Kc = K / KS;
    int kz = blockIdx.y;
    float acc[4][4] = {};
    for (int k0 = kz*Kc; k0 < (kz+1)*Kc; k0 += BK) {
        for (int i = tid; i < 64*BK; i += 256) {
            int m = i >> 4, k = i & 15;
            As[k][m] = (m < M) ? A[(size_t)m*K + k0 + k] : 0.f;
        }
        for (int i = tid; i < BK*64; i += 256) {
            int k = i >> 6, n = i & 63;
            Bs[k][n] = W[(size_t)(k0+k)*N + n0 + n];
        }
        __syncthreads();
        #pragma unroll
        for (int k = 0; k < BK; k++) {
            float a[4], b[4];
            #pragma unroll
            for (int i = 0; i < 4; i++) a[i] = As[k][tr*4+i];
            #pragma unroll
            for (int j = 0; j < 4; j++) b[j] = Bs[k][tc*4+j];
            #pragma unroll
            for (int i = 0; i < 4; i++)
                #pragma unroll
                for (int j = 0; j < 4; j++) acc[i][j] += a[i]*b[j];
        }
        __syncthreads();
    }
    #pragma unroll
    for (int i = 0; i < 4; i++) {
        int m = tr*4 + i;
        if (m >= M) continue;
        #pragma unroll
        for (int j = 0; j < 4; j++)
            part[((size_t)kz*M + m)*N + n0 + tc*4 + j] = acc[i][j];
    }
}

template<int ACT>
__global__ void k_small_epi(const float* __restrict__ part, const float* __restrict__ bias,
                            float* __restrict__ C, int M, int N, int KS)
{
    int idx = blockIdx.x*256 + threadIdx.x;
    if (idx >= M*N) return;
    int n = idx % N;
    float s = 0.f;
    for (int kz = 0; kz < KS; kz++) s += part[(size_t)kz*M*N + idx];
    s += bias[n];
    if (ACT == 1) s = tanhf(s);
    C[idx] = s;
}

// ---------------- tiny glo diff-square GEMM ----------------
__global__ void gemm_diffsq_glo(const float* __restrict__ X, const float* __restrict__ Y,
                                const float* __restrict__ W, const float* __restrict__ bias,
                                float* __restrict__ Cbase, int M, int N, int K)
{
    const int BM = 64, BN = 64, BK = 16;
    int c = blockIdx.z;
    const float* Yp = Y + (size_t)c*K;
    __shared__ float As[BK][BM];
    __shared__ float Bs[BK][BN];
    int tid = threadIdx.x;
    int tr = tid >> 4, tc = tid & 15;
    int m0 = blockIdx.y * BM, n0 = blockIdx.x * BN;
    float acc[4][4] = {};
    for (int k0 = 0; k0 < K; k0 += BK) {
        #pragma unroll
        for (int i = tid; i < BM*BK; i += 256) {
            int m = i >> 4, k = i & 15;
            float v = 0.f;
            if (m0 + m < M) {
                float d = X[(size_t)(m0+m)*K + k0 + k] - Yp[k0 + k];
                v = d * d;
            }
            As[k][m] = v;
        }
        #pragma unroll
        for (int i = tid; i < BK*BN; i += 256) {
            int k = i >> 6, n = i & 63;
            Bs[k][n] = W[(size_t)(k0+k)*N + n0 + n];
        }
        __syncthreads();
        #pragma unroll
        for (int k = 0; k < BK; k++) {
            float a[4], b[4];
            #pragma unroll
            for (int i = 0; i < 4; i++) a[i] = As[k][tr*4+i];
            #pragma unroll
            for (int j = 0; j < 4; j++) b[j] = Bs[k][tc*4+j];
            #pragma unroll
            for (int i = 0; i < 4; i++)
                #pragma unroll
                for (int j = 0; j < 4; j++) acc[i][j] += a[i]*b[j];
        }
        __syncthreads();
    }
    #pragma unroll
    for (int i = 0; i < 4; i++) {
        int m = m0 + tr*4 + i;
        if (m >= M) continue;
        #pragma unroll
        for (int j = 0; j < 4; j++) {
            int n = n0 + tc*4 + j;
            float v = fmaxf(acc[i][j] + bias[n], 0.f);
            Cbase[(size_t)c*M*N + (size_t)m*N + n] = v;
        }
    }
}

// ---------------- small kernels ----------------
__global__ void k_imgave(const float* __restrict__ img) {
    int i = blockIdx.x*blockDim.x + threadIdx.x;
    int b = i >> 10, d = i & 1023;
    float s = 0.f;
    for (int r = 0; r < NR; r++) s += img[((size_t)b*NR + r)*ND + d];
    g_imgave[i] = s * (1.f / NR);
}

__global__ void k_bnstats() {
    int r = blockIdx.x;
    __shared__ float red[256], red2[256];
    float s = 0.f, ss = 0.f;
    for (int i = threadIdx.x; i < NB*ND; i += 256) {
        int b = i >> 10, d = i & 1023;
        float v = g_h[((size_t)b*NR + r)*ND + d];
        s += v; ss += v*v;
    }
    red[threadIdx.x] = s; red2[threadIdx.x] = ss; __syncthreads();
    for (int st = 128; st > 0; st >>= 1) {
        if (threadIdx.x < st) { red[threadIdx.x] += red[threadIdx.x+st]; red2[threadIdx.x] += red2[threadIdx.x+st]; }
        __syncthreads();
    }
    if (threadIdx.x == 0) {
        float mu = red[0] / (float)(NB*ND);
        g_bnmu[r] = mu;
        g_bnvar[r] = red2[0] / (float)(NB*ND) - mu*mu;
    }
}

__global__ void k_gbn(const float* __restrict__ gamma, const float* __restrict__ beta) {
    int d = blockIdx.x*blockDim.x + threadIdx.x;
    float s = 0.f, ss = 0.f;
    for (int b = 0; b < NB; b++) { float v = g_g[(size_t)b*ND + d]; s += v; ss += v*v; }
    float mu = s / NB;
    float var = ss / NB - mu*mu;
    float inv = rsqrtf(var + BNEPS);
    float ga = gamma[d], be = beta[d];
    for (int b = 0; b < NB; b++) {
        float v = g_g[(size_t)b*ND + d];
        g_g[(size_t)b*ND + d] = tanhf((v - mu)*inv*ga + be);
    }
}

__global__ void k_wraw(const float* __restrict__ vcw, const float* __restrict__ vcb,
                       const float* __restrict__ lg, const float* __restrict__ lb) {
    int br = blockIdx.x;
    int b = br / NR, r = br % NR;
    __shared__ float red[256];
    float mu = g_bnmu[r], inv = rsqrtf(g_bnvar[r] + BNEPS);
    float ga = lg[r], be = lb[r];
    float s = 0.f;
    for (int d = threadIdx.x; d < ND; d += 256) {
        float le = tanhf((g_h[(size_t)br*ND + d] - mu)*inv*ga + be);
        s += le * g_g[(size_t)b*ND + d] * vcw[d];
    }
    float tot = blockReduceSum256(s, red);
    if (threadIdx.x == 0) g_wraw[br] = tot + vcb[0];
}

__global__ void k_newglobal(const float* __restrict__ img) {
    int b = blockIdx.x;
    __shared__ float w[NR];
    __shared__ float red[256];
    __shared__ float invn;
    if (threadIdx.x == 0) {
        float mx = -1e30f;
        for (int r = 0; r < NR; r++) mx = fmaxf(mx, g_wraw[b*NR + r]);
        float sum = 0.f;
        for (int r = 0; r < NR; r++) { w[r] = expf(g_wraw[b*NR + r] - mx); sum += w[r]; }
        float is = 1.f / sum;
        for (int r = 0; r < NR; r++) w[r] *= is;
    }
    __syncthreads();
    float ssq = 0.f;
    for (int d = threadIdx.x; d < ND; d += 256) {
        float s = 0.f;
        for (int r = 0; r < NR; r++) s += w[r] * img[((size_t)b*NR + r)*ND + d];
        g_imgglo[(size_t)b*ND + d] = s;
        ssq += s*s;
    }
    float tot = blockReduceSum256(ssq, red);
    if (threadIdx.x == 0) {
        float nrm = sqrtf(tot) + EPSL;
        g_normglo[b] = nrm;
        invn = 1.f / nrm;
    }
    __syncthreads();
    for (int d = threadIdx.x; d < ND; d += 256) g_imgglo[(size_t)b*ND + d] *= invn;
}

__global__ void k_imgpar(const float* __restrict__ img, const int* __restrict__ adjs) {
    int br = blockIdx.x;
    int b = br / NR, r = br % NR;
    __shared__ int eff[NPART];
    __shared__ float wg[NPART];
    if (threadIdx.x == 0) {
        int cnt = 0;
        const int* row = adjs + (size_t)b*NR*NR + (size_t)r*NR;
        for (int j = 0; j < NR && cnt < NPART; j++)
            if (row[j] == 1) eff[cnt++] = j;
        for (; cnt < NPART; cnt++) eff[cnt] = r;
        float v[NPART], mx = -1e30f;
        for (int k = 0; k < NPART; k++) { v[k] = g_wraw[b*NR + eff[k]]; mx = fmaxf(mx, v[k]); }
        float sum = 0.f;
        for (int k = 0; k < NPART; k++) { v[k] = expf(v[k] - mx); sum += v[k]; }
        float is = 1.f / sum;
        for (int k = 0; k < NPART; k++) wg[k] = v[k]*is;
    }
    __syncthreads();
    float invn = 1.f / g_normglo[b];
    for (int d = threadIdx.x; d < ND; d += 256) {
        float s = 0.f;
        #pragma unroll
        for (int k = 0; k < NPART; k++) s += wg[k] * img[((size_t)b*NR + eff[k])*ND + d];
        g_imgpar[(size_t)br*ND + d] = s * invn;
    }
}

__global__ void k_capave(const float* __restrict__ cap) {
    int i = blockIdx.x*blockDim.x + threadIdx.x;
    int c = i >> 10, d = i & 1023;
    float s = 0.f;
    for (int n = 0; n < NWD; n++) s += cap[((size_t)c*NWD + n)*ND + d];
    g_capave[i] = s * (1.f / NWD);
}

__global__ void k_capglo(const float* __restrict__ cap, const float* __restrict__ tsacw,
                         const float* __restrict__ tsacb) {
    int c = blockIdx.x;
    __shared__ float red[256];
    __shared__ float cw[NWD];
    __shared__ float invn;
    float gw[4];
    #pragma unroll
    for (int i = 0; i < 4; i++) {
        int d = threadIdx.x + i*256;
        gw[i] = g_ge[(size_t)c*ND + d] * tsacw[d];
    }
    for (int n = 0; n < NWD; n++) {
        float s = 0.f;
        #pragma unroll
        for (int i = 0; i < 4; i++) {
            int d = threadIdx.x + i*256;
            s += g_le[((size_t)c*NWD + n)*ND + d] * gw[i];
        }
        float tot = blockReduceSum256(s, red);
        if (threadIdx.x == 0) cw[n] = tot + tsacb[0];
    }
    __syncthreads();
    if (threadIdx.x == 0) {
        float mx = -1e30f;
        for (int n = 0; n < NWD; n++) mx = fmaxf(mx, cw[n]);
        float sum = 0.f;
        for (int n = 0; n < NWD; n++) { cw[n] = expf(cw[n] - mx); sum += cw[n]; }
        float is = 1.f / sum;
        for (int n = 0; n < NWD; n++) cw[n] *= is;
    }
    __syncthreads();
    float ssq = 0.f;
    #pragma unroll
    for (int i = 0; i < 4; i++) {
        int d = threadIdx.x + i*256;
        float s = 0.f;
        for (int n = 0; n < NWD; n++) s += cw[n] * cap[((size_t)c*NWD + n)*ND + d];
        g_capglo[(size_t)c*ND + d] = s;
        ssq += s*s;
    }
    float tot = blockReduceSum256(ssq, red);
    if (threadIdx.x == 0) invn = 1.f / (sqrtf(tot) + EPSL);
    __syncthreads();
    #pragma unroll
    for (int i = 0; i < 4; i++) {
        int d = threadIdx.x + i*256;
        g_capglo[(size_t)c*ND + d] *= invn;
    }
}

__global__ void k_attnfuse() {
    int cb = blockIdx.x;
    int c = cb / NB, b = cb % NB;
    __shared__ float sA[NWD*NR];
    __shared__ float nrm[NWD];
    const float* raw = g_attnraw + (size_t)c*NWD*NB*NR;
    for (int i = threadIdx.x; i < NWD*NR; i += 256) {
        int n = i / NR, r = i % NR;
        float v = raw[(size_t)n*NB*NR + (size_t)b*NR + r];
        v = (v > 0.f) ? v : 0.1f*v;
        sA[i] = v;
    }
    __syncthreads();
    if (threadIdx.x < NWD) {
        int n = threadIdx.x;
        float s = 0.f;
        for (int r = 0; r < NR; r++) { float v = sA[n*NR + r]; s += v*v; }
        nrm[n] = 1.f / (sqrtf(s) + EPSL);
    }
    __syncthreads();
    if (threadIdx.x < NR) {
        int r = threadIdx.x;
        float vals[NWD];
        float mx = -1e30f;
        for (int n = 0; n < NWD; n++) {
            float v = SMOOTHF * sA[n*NR + r] * nrm[n];
            vals[n] = v;
            mx = fmaxf(mx, v);
        }
        float sum = 0.f;
        for (int n = 0; n < NWD; n++) { vals[n] = expf(vals[n] - mx); sum += vals[n]; }
        float is = 1.f / sum;
        float* outp = g_attnT + ((size_t)cb*NR + r)*NWD;
        for (int n = 0; n < NWD; n++) outp[n] = vals[n]*is;
    }
}

// ctx raw (R5 shape: no fused ssq -> no spill)
__global__ void k_ctx(const float* __restrict__ cap) {
    int cb = blockIdx.x;
    int c = cb / NB;
    __shared__ float sT[NR*NWD];
    const float* at = g_attnT + (size_t)cb*NR*NWD;
    for (int i = threadIdx.x; i < NR*NWD; i += 256) sT[i] = at[i];
    __syncthreads();
    float* outp = g_ctx + (size_t)cb*NR*ND;
    for (int it = 0; it < 4; it++) {
        int d = threadIdx.x + it*256;
        float acc[NR];
        #pragma unroll
        for (int r = 0; r < NR; r++) acc[r] = 0.f;
        for (int n = 0; n < NWD; n++) {
            float cv = cap[((size_t)c*NWD + n)*ND + d];
            #pragma unroll
            for (int r = 0; r < NR; r++) acc[r] += sT[r*NWD + n] * cv;
        }
        for (int r = 0; r < NR; r++) outp[(size_t)r*ND + d] = acc[r];
    }
}

// read-only pass: g_ctxinv[row] = 1/(||ctx_row||+eps), one warp per row
__global__ void k_ctxssq() {
    int row = blockIdx.x * 8 + (threadIdx.x >> 5);   // 8 warps/block
    int lane = threadIdx.x & 31;
    const float* p = g_ctx + (size_t)row * ND;
    float s = 0.f;
    #pragma unroll
    for (int i = 0; i < 8; i++) {
        float4 v = *(const float4*)(p + lane*4 + i*128);
        s += v.x*v.x + v.y*v.y + v.z*v.z + v.w*v.w;
    }
    s = warpReduceSum(s);
    if (lane == 0) g_ctxinv[row] = 1.f / (sqrtf(s) + EPSL);
}

__global__ void k_rownorm(float* __restrict__ X, int L) {
    size_t row = blockIdx.x;
    float* p = X + row*(size_t)L;
    __shared__ float red[256];
    __shared__ float invn;
    float s = 0.f;
    for (int i = threadIdx.x; i < L; i += 256) { float v = p[i]; s += v*v; }
    float tot = blockReduceSum256(s, red);
    if (threadIdx.x == 0) invn = 1.f / (sqrtf(tot) + EPSL);
    __syncthreads();
    for (int i = threadIdx.x; i < L; i += 256) p[i] *= invn;
}

__global__ void k_rownorm_simloc(float* __restrict__ out) {
    int row = blockIdx.x;
    int cb = row / NR, r = row % NR;
    float* p = out + ((size_t)cb*37 + 1 + r)*NS;
    __shared__ float red[256];
    __shared__ float invn;
    float v = p[threadIdx.x];
    float tot = blockReduceSum256(v*v, red);
    if (threadIdx.x == 0) invn = 1.f / (sqrtf(tot) + EPSL);
    __syncthreads();
    p[threadIdx.x] = v * invn;
}

// finalize: warp-parallel over r, simpar row-norm fused
__global__ void k_finalize(const float* __restrict__ simw, const float* __restrict__ simb,
                           const float* __restrict__ lng, const float* __restrict__ lnb,
                           float* __restrict__ out, size_t out2off) {
    int cb = blockIdx.x;
    int tid = threadIdx.x;
    int lane = tid & 31, warp = tid >> 5;
    const float* sg = out + out2off + (size_t)cb*NS;
    __shared__ float sSgw[NS];
    __shared__ float wv[NR];
    __shared__ float mv[2];
    float sgv = sg[tid];
    sSgw[tid] = sgv * simw[tid];
    __syncthreads();
    const float* sp = g_simpar + (size_t)cb*NR*NS;
    for (int r = warp; r < NR; r += 8) {
        const float* row = sp + (size_t)r*NS;
        float dot = 0.f, ss = 0.f;
        #pragma unroll
        for (int i = 0; i < 8; i++) {
            int c = lane + i*32;
            float v = row[c];
            dot += v * sSgw[c];
            ss += v * v;
        }
        dot = warpReduceSum(dot);
        ss = warpReduceSum(ss);
        if (lane == 0) wv[r] = dot / (sqrtf(ss) + EPSL) + simb[0];
    }
    __syncthreads();
    if (tid == 0) {
        float m = 0.f;
        for (int r = 0; r < NR; r++) m += wv[r];
        m /= NR;
        float v = 0.f;
        for (int r = 0; r < NR; r++) { float d = wv[r] - m; v += d*d; }
        v /= NR;
        mv[0] = m; mv[1] = rsqrtf(v + LNEPS);
    }
    __syncthreads();
    if (tid < NR) {
        int r = tid;
        float z = (wv[r] - mv[0])*mv[1]*lng[r] + lnb[r];
        wv[r] = 1.f / (1.f + expf(-z));
    }
    __syncthreads();
    float* ob = out + (size_t)cb*37*NS;
    ob[tid] = sgv;
    for (int r = 0; r < NR; r++) ob[(size_t)(1+r)*NS + tid] *= wv[r];
}

// ---------------- host ----------------
extern "C" void kernel_launch(void* const* d_in, const int* in_sizes, int n_in,
                              void* d_out, int out_size) {
    (void)in_sizes; (void)n_in; (void)out_size;
    const float* img    = (const float*)d_in[0];
    const float* cap    = (const float*)d_in[1];
    const int*   adjs   = (const int*)d_in[3];
    const float* tsa_lw = (const float*)d_in[5];
    const float* tsa_lb = (const float*)d_in[6];
    const float* tsa_gw = (const float*)d_in[7];
    const float* tsa_gb = (const float*)d_in[8];
    const float* tsa_cw = (const float*)d_in[9];
    const float* tsa_cb = (const float*)d_in[10];
    const float* vl_w   = (const float*)d_in[11];
    const float* vl_b   = (const float*)d_in[12];
    const float* vbn_lg = (const float*)d_in[13];
    const float* vbn_lb = (const float*)d_in[14];
    const float* vg_w   = (const float*)d_in[15];
    const float* vg_b   = (const float*)d_in[16];
    const float* vbn_gg = (const float*)d_in[17];
    const float* vbn_gb = (const float*)d_in[18];
    const float* vc_w   = (const float*)d_in[19];
    const float* vc_b   = (const float*)d_in[20];
    const float* loc_w  = (const float*)d_in[21];
    const float* loc_b  = (const float*)d_in[22];
    const float* par_w  = (const float*)d_in[23];
    const float* par_b  = (const float*)d_in[24];
    const float* glo_w  = (const float*)d_in[25];
    const float* glo_b  = (const float*)d_in[26];
    const float* sim_w  = (const float*)d_in[27];
    const float* sim_b  = (const float*)d_in[28];
    const float* ln_g   = (const float*)d_in[29];
    const float* ln_b   = (const float*)d_in[30];
    float* out = (float*)d_out;

    static bool inited = false;
    static float *p_h, *p_imgave, *p_g, *p_ge, *p_le, *p_attnraw,
                 *p_ctx, *p_ctxinv, *p_imgpar, *p_imgglo, *p_capglo, *p_simpar, *p_part, *p_capave;
    static __nv_bfloat16 *p_wth, *p_wtl, *p_imgh, *p_imgl, *p_caph, *p_capl, *p_wbh, *p_wbl;
    if (!inited) {
        cudaGetSymbolAddress((void**)&p_h, g_h);
        cudaGetSymbolAddress((void**)&p_imgave, g_imgave);
        cudaGetSymbolAddress((void**)&p_g, g_g);
        cudaGetSymbolAddress((void**)&p_ge, g_ge);
        cudaGetSymbolAddress((void**)&p_le, g_le);
        cudaGetSymbolAddress((void**)&p_attnraw, g_attnraw);
        cudaGetSymbolAddress((void**)&p_ctx, g_ctx);
        cudaGetSymbolAddress((void**)&p_ctxinv, g_ctxinv);
        cudaGetSymbolAddress((void**)&p_imgpar, g_imgpar);
        cudaGetSymbolAddress((void**)&p_imgglo, g_imgglo);
        cudaGetSymbolAddress((void**)&p_capglo, g_capglo);
        cudaGetSymbolAddress((void**)&p_simpar, g_simpar);
        cudaGetSymbolAddress((void**)&p_part, g_part);
        cudaGetSymbolAddress((void**)&p_capave, g_capave);
        cudaGetSymbolAddress((void**)&p_wth, g_wth);
        cudaGetSymbolAddress((void**)&p_wtl, g_wtl);
        cudaGetSymbolAddress((void**)&p_imgh, g_imgh);
        cudaGetSymbolAddress((void**)&p_imgl, g_imgl);
        cudaGetSymbolAddress((void**)&p_caph, g_caph);
        cudaGetSymbolAddress((void**)&p_capl, g_capl);
        cudaGetSymbolAddress((void**)&p_wbh, g_wbh);
        cudaGetSymbolAddress((void**)&p_wbl, g_wbl);
        inited = true;
    }

    const size_t out2off = (size_t)NCAP*NB*37*NS;
    float* out2 = out + out2off;

    // ---- operand splits ----
    k_split<<<(NB*NR*ND+255)/256, 256>>>(img, p_imgh, p_imgl, NB*NR*ND);
    k_split<<<(NCAP*NWD*ND+255)/256, 256>>>(cap, p_caph, p_capl, NCAP*NWD*ND);
    k_wsplitT<<<(ND*ND+255)/256, 256>>>(vl_w,   p_wbh,         p_wbl,         ND, ND);
    k_wsplitT<<<(ND*ND+255)/256, 256>>>(tsa_lw, p_wbh + ND*ND, p_wbl + ND*ND, ND, ND);
    k_wsplitT<<<(NS*ND+255)/256, 256>>>(loc_w,  p_wth,         p_wtl,         NS, ND);
    k_wsplitT<<<(NS*ND+255)/256, 256>>>(par_w,  p_wth + NS*ND, p_wtl + NS*ND, NS, ND);

    // ---- caption-independent ----
    k_imgave<<<256, 256>>>(img);
    hmma_gemm<0><<<dim3(8, 18), 256>>>(p_imgh, p_imgl, p_wbh, p_wbl, vl_b, p_h, ND, ND);
    k_bnstats<<<NR, 256>>>();
    gemm_small_part<<<dim3(16, 8), 256>>>(p_imgave, vg_w, p_part, NB, ND, ND);
    k_small_epi<0><<<(NB*ND+255)/256, 256>>>(p_part, vg_b, p_g, NB, ND, 8);
    k_gbn<<<4, 256>>>(vbn_gg, vbn_gb);
    k_wraw<<<NB*NR, 256>>>(vc_w, vc_b, vbn_lg, vbn_lb);
    k_newglobal<<<NB, 256>>>(img);
    k_imgpar<<<NB*NR, 256>>>(img, adjs);

    // ---- caption side ----
    k_capave<<<128, 256>>>(cap);
    hmma_gemm<1><<<dim3(8, 10), 256>>>(p_caph, p_capl, p_wbh + ND*ND, p_wbl + ND*ND,
                                       tsa_lb, p_le, ND, ND);
    gemm_small_part<<<dim3(16, 8), 256>>>(p_capave, tsa_gw, p_part, NCAP, ND, ND);
    k_small_epi<1><<<(NCAP*ND+255)/256, 256>>>(p_part, tsa_gb, p_ge, NCAP, ND, 8);
    k_capglo<<<NCAP, 256>>>(cap, tsa_cw, tsa_cb);

    hmma_gemm<0><<<dim3(18, 10), 256>>>(p_caph, p_capl, p_imgh, p_imgl,
                                        nullptr, p_attnraw, NB*NR, ND);
    k_attnfuse<<<NCAP*NB, 256>>>();
    k_ctx<<<NCAP*NB, 256>>>(cap);            // raw ctx, no spill
    k_ctxssq<<<NCAP*NB*NR/8, 256>>>();       // warp-per-row inv norms

    // ---- heavy diff-square GEMMs (HMMA split-bf16) ----
    hmma_diffsq<0><<<dim3(2, 18, NCAP), 256>>>(p_ctx, img, p_ctxinv, p_wth, p_wtl, loc_b, out);
    k_rownorm_simloc<<<NCAP*NB*NR, 256>>>(out);
    hmma_diffsq<1><<<dim3(2, 18, NCAP), 256>>>(p_imgpar, p_capglo, nullptr,
                                               p_wth + NS*ND, p_wtl + NS*ND, par_b, p_simpar);

    // sim_glo (tiny, fp32)
    gemm_diffsq_glo<<<dim3(4, 1, NCAP), 256>>>(p_imgglo, p_capglo, glo_w, glo_b, out2, NB, NS, ND);
    k_rownorm<<<NCAP*NB, 256>>>(out2, NS);

    // ---- finalize ----
    k_finalize<<<NCAP*NB, 256>>>(sim_w, sim_b, ln_g, ln_b, out, out2off);
}

// round 8
// speedup vs baseline: 3.8466x; 1.1892x over previous
#include <cuda_runtime.h>
#include <cuda_bf16.h>
#include <cstdint>
#include <stdint.h>
#include <math.h>

#define NB 64
#define NR 36
#define ND 1024
#define NCAP 32
#define NWD 40
#define NS 256
#define NPART 5
#define EPSL 1e-8f
#define BNEPS 1e-5f
#define LNEPS 1e-5f
#define SMOOTHF 9.0f

typedef unsigned long long ull;

// ---------------- scratch ----------------
__device__ float g_h[NB*NR*ND];
__device__ float g_imgave[NB*ND];
__device__ float g_bnmu[NR];
__device__ float g_bnvar[NR];
__device__ float g_g[NB*ND];
__device__ float g_wraw[NB*NR];
__device__ float g_imgglo[NB*ND];
__device__ float g_normglo[NB];
__device__ float g_imgpar[NB*NR*ND];
__device__ float g_capave[NCAP*ND];
__device__ float g_le[NCAP*NWD*ND];
__device__ float g_ge[NCAP*ND];
__device__ float g_capglo[NCAP*ND];
__device__ float g_attnraw[(size_t)NCAP*NWD*NB*NR];
__device__ float g_attnT[(size_t)NCAP*NB*NR*NWD];
__device__ float g_ctx[(size_t)NCAP*NB*NR*ND];
__device__ float g_ctxinv[NCAP*NB*NR];
__device__ float g_simpar[(size_t)NCAP*NB*NR*NS];
__device__ float g_part[8*64*1024];
__device__ __nv_bfloat16 g_wth[2][NS*ND];
__device__ __nv_bfloat16 g_wtl[2][NS*ND];
__device__ __nv_bfloat16 g_imgh[NB*NR*ND], g_imgl[NB*NR*ND];
__device__ __nv_bfloat16 g_caph[NCAP*NWD*ND], g_capl[NCAP*NWD*ND];
__device__ __nv_bfloat16 g_wbh[2][ND*ND], g_wbl[2][ND*ND];

// ---------------- helpers ----------------
__device__ __forceinline__ uint32_t smem_u32(const void* p) {
    uint32_t a;
    asm("{ .reg .u64 t; cvta.to.shared.u64 t, %1; cvt.u32.u64 %0, t; }" : "=r"(a) : "l"(p));
    return a;
}

__device__ __forceinline__ float blockReduceSum256(float v, float* red) {
    int tid = threadIdx.x;
    red[tid] = v; __syncthreads();
    #pragma unroll
    for (int s = 128; s > 0; s >>= 1) {
        if (tid < s) red[tid] += red[tid + s];
        __syncthreads();
    }
    float r = red[0]; __syncthreads();
    return r;
}

__device__ __forceinline__ float warpReduceSum(float v) {
    v += __shfl_xor_sync(0xffffffffu, v, 16);
    v += __shfl_xor_sync(0xffffffffu, v, 8);
    v += __shfl_xor_sync(0xffffffffu, v, 4);
    v += __shfl_xor_sync(0xffffffffu, v, 2);
    v += __shfl_xor_sync(0xffffffffu, v, 1);
    return v;
}

#define LDSM4(r0, r1, r2, r3, addr) \
    asm volatile("ldmatrix.sync.aligned.m8n8.x4.shared.b16 {%0,%1,%2,%3}, [%4];" \
        : "=r"(r0), "=r"(r1), "=r"(r2), "=r"(r3) : "r"(addr))

#define MMA_BF16(d, a, b) \
    asm volatile("mma.sync.aligned.m16n8k16.row.col.f32.bf16.bf16.f32 " \
        "{%0,%1,%2,%3}, {%4,%5,%6,%7}, {%8,%9}, {%0,%1,%2,%3};" \
        : "+f"((d)[0]), "+f"((d)[1]), "+f"((d)[2]), "+f"((d)[3]) \
        : "r"((a)[0]), "r"((a)[1]), "r"((a)[2]), "r"((a)[3]), "r"((b)[0]), "r"((b)[1]))

// ---------------- split kernels ----------------
__global__ void k_split(const float* __restrict__ X, __nv_bfloat16* __restrict__ H,
                        __nv_bfloat16* __restrict__ L, int total) {
    int idx = blockIdx.x * 256 + threadIdx.x;
    if (idx >= total) return;
    float v = X[idx];
    __nv_bfloat16 h = __float2bfloat16(v);
    H[idx] = h;
    L[idx] = __float2bfloat16(v - __bfloat162float(h));
}

__global__ void k_wsplitT(const float* __restrict__ W, __nv_bfloat16* __restrict__ H,
                          __nv_bfloat16* __restrict__ L, int Ncols, int K) {
    int idx = blockIdx.x * 256 + threadIdx.x;
    if (idx >= Ncols * K) return;
    int n = idx / K, k = idx - n * K;
    float w = W[(size_t)k * Ncols + n];
    __nv_bfloat16 h = __float2bfloat16(w);
    H[idx] = h;
    L[idx] = __float2bfloat16(w - __bfloat162float(h));
}

#define APAD 40

// ============ generic HMMA GEMM on pre-split operands (128x128 tile) ============
template<int ACT>
__global__ void __launch_bounds__(256)
hmma_gemm(const __nv_bfloat16* __restrict__ Ah, const __nv_bfloat16* __restrict__ Al,
          const __nv_bfloat16* __restrict__ Bh, const __nv_bfloat16* __restrict__ Bl,
          const float* __restrict__ bias, float* __restrict__ C, int N, int K)
{
    __shared__ __nv_bfloat16 sAh[128][APAD];
    __shared__ __nv_bfloat16 sAl[128][APAD];
    __shared__ __nv_bfloat16 sBh[128][APAD];
    __shared__ __nv_bfloat16 sBl[128][APAD];
    int tid = threadIdx.x, lane = tid & 31, warp = tid >> 5;
    int mw = warp >> 2, nw = warp & 3;
    int n0 = blockIdx.x * 128, m0 = blockIdx.y * 128;
    const __nv_bfloat16* Ah0 = Ah + (size_t)m0 * K;
    const __nv_bfloat16* Al0 = Al + (size_t)m0 * K;
    const __nv_bfloat16* Bh0 = Bh + (size_t)n0 * K;
    const __nv_bfloat16* Bl0 = Bl + (size_t)n0 * K;

    float acc[4][4][4];
    #pragma unroll
    for (int i = 0; i < 4; i++)
        #pragma unroll
        for (int j = 0; j < 4; j++)
            #pragma unroll
            for (int e = 0; e < 4; e++) acc[i][j][e] = 0.f;

    uint32_t aAh = smem_u32(sAh), aAl = smem_u32(sAl);
    uint32_t aBh = smem_u32(sBh), aBl = smem_u32(sBl);
    int a_row = mw*64 + (lane & 15);
    int a_col8 = (lane >> 4) * 8;
    int b_row = nw*32 + (lane >> 4)*8 + (lane & 7);
    int b_col8 = ((lane >> 3) & 1) * 8;

    for (int ch = 0; ch < K/32; ch++) {
        int k0 = ch * 32;
        #pragma unroll
        for (int i = 0; i < 2; i++) {
            int slot = tid + i*256;
            int row = slot >> 2, c = slot & 3;
            size_t src = (size_t)row*K + k0 + c*8;
            *(uint4*)&sAh[row][c*8] = *(const uint4*)(Ah0 + src);
            *(uint4*)&sAl[row][c*8] = *(const uint4*)(Al0 + src);
            *(uint4*)&sBh[row][c*8] = *(const uint4*)(Bh0 + src);
            *(uint4*)&sBl[row][c*8] = *(const uint4*)(Bl0 + src);
        }
        __syncthreads();
        #pragma unroll
        for (int k16 = 0; k16 < 2; k16++) {
            uint32_t bh[4][2], bl[4][2];
            #pragma unroll
            for (int half = 0; half < 2; half++) {
                uint32_t off = (uint32_t)((b_row + half*16)*APAD + k16*16 + b_col8) * 2;
                uint32_t r0, r1, r2, r3;
                LDSM4(r0, r1, r2, r3, aBh + off);
                bh[half*2+0][0] = r0; bh[half*2+0][1] = r1;
                bh[half*2+1][0] = r2; bh[half*2+1][1] = r3;
                LDSM4(r0, r1, r2, r3, aBl + off);
                bl[half*2+0][0] = r0; bl[half*2+0][1] = r1;
                bl[half*2+1][0] = r2; bl[half*2+1][1] = r3;
            }
            #pragma unroll
            for (int mt = 0; mt < 4; mt++) {
                uint32_t ah[4], al[4];
                uint32_t off = (uint32_t)((a_row + mt*16)*APAD + k16*16 + a_col8) * 2;
                LDSM4(ah[0], ah[1], ah[2], ah[3], aAh + off);
                LDSM4(al[0], al[1], al[2], al[3], aAl + off);
                #pragma unroll
                for (int nt = 0; nt < 4; nt++) {
                    MMA_BF16(acc[mt][nt], ah, bh[nt]);
                    MMA_BF16(acc[mt][nt], ah, bl[nt]);
                    MMA_BF16(acc[mt][nt], al, bh[nt]);
                }
            }
        }
        __syncthreads();
    }

    #pragma unroll
    for (int mt = 0; mt < 4; mt++) {
        int mA = m0 + mw*64 + mt*16 + (lane >> 2);
        int mB = mA + 8;
        float* dA = C + (size_t)mA * N;
        float* dB = C + (size_t)mB * N;
        #pragma unroll
        for (int nt = 0; nt < 4; nt++) {
            int n = n0 + nw*32 + nt*8 + (lane & 3)*2;
            float b0 = 0.f, b1 = 0.f;
            if (bias) { b0 = bias[n]; b1 = bias[n+1]; }
            float v0 = acc[mt][nt][0] + b0, v1 = acc[mt][nt][1] + b1;
            float v2 = acc[mt][nt][2] + b0, v3 = acc[mt][nt][3] + b1;
            if (ACT == 1) { v0 = tanhf(v0); v1 = tanhf(v1); v2 = tanhf(v2); v3 = tanhf(v3); }
            *(float2*)&dA[n] = make_float2(v0, v1);
            *(float2*)&dB[n] = make_float2(v2, v3);
        }
    }
}

// ============ HMMA diff-square GEMM, full-N 128x256 tile ============
// MODE 0: A = (X*inv - Y)^2, scatter + FUSED row-l2norm into out(c,b,1+r,s)
// MODE 1: A = (X - Yv[z])^2, raw store -> simpar
template<int MODE>
__global__ void __launch_bounds__(256)
hmma_diffsq(const float* __restrict__ X, const float* __restrict__ Y,
            const float* __restrict__ rowinv,
            const __nv_bfloat16* __restrict__ Bh, const __nv_bfloat16* __restrict__ Bl,
            const float* __restrict__ bias, float* __restrict__ outp)
{
    __shared__ __nv_bfloat16 sAh[128][APAD];
    __shared__ __nv_bfloat16 sAl[128][APAD];
    __shared__ __nv_bfloat16 sBh[256][APAD];
    __shared__ __nv_bfloat16 sBl[256][APAD];
    __shared__ float sred[4][64];   // [nw][row_local]
    __shared__ float sinv[64];
    int tid = threadIdx.x;
    int lane = tid & 31, warp = tid >> 5;
    int mw = warp >> 2, nw = warp & 3;
    int m0 = blockIdx.x * 128, z = blockIdx.y;

    const float* Xp = (MODE == 0) ? X + ((size_t)z*2304 + m0)*ND : X + (size_t)m0*ND;
    const float* Yp = (MODE == 0) ? Y + (size_t)m0*ND : Y + (size_t)z*ND;
    const float* invp = (MODE == 0) ? rowinv + (size_t)z*2304 + m0 : nullptr;

    float acc[4][8][4];
    #pragma unroll
    for (int i = 0; i < 4; i++)
        #pragma unroll
        for (int j = 0; j < 8; j++)
            #pragma unroll
            for (int e = 0; e < 4; e++) acc[i][j][e] = 0.f;

    uint32_t aAh = smem_u32(sAh), aAl = smem_u32(sAl);
    uint32_t aBh = smem_u32(sBh), aBl = smem_u32(sBl);
    int a_row = mw*64 + (lane & 15);
    int a_col8 = (lane >> 4) * 8;
    int b_row = nw*64 + (lane >> 4)*8 + (lane & 7);
    int b_col8 = ((lane >> 3) & 1) * 8;

    for (int ch = 0; ch < 32; ch++) {
        int k0 = ch * 32;
        // ---- A: (X-Y)^2 fp32 -> split bf16 hi/lo ----
        #pragma unroll
        for (int i = 0; i < 4; i++) {
            int slot = tid + i*256;             // 1024 = 128 rows x 8 float4
            int row = slot >> 3, q = slot & 7;
            size_t off = (size_t)row*ND + k0 + q*4;
            float4 xv = *(const float4*)(Xp + off);
            float4 yv;
            if (MODE == 0) yv = *(const float4*)(Yp + off);
            else           yv = *(const float4*)(Yp + k0 + q*4);
            float iv = (MODE == 0) ? invp[row] : 1.f;
            float d0, d1, d2, d3;
            if (MODE == 0) {
                d0 = xv.x*iv - yv.x; d1 = xv.y*iv - yv.y;
                d2 = xv.z*iv - yv.z; d3 = xv.w*iv - yv.w;
            } else {
                d0 = xv.x - yv.x; d1 = xv.y - yv.y;
                d2 = xv.z - yv.z; d3 = xv.w - yv.w;
            }
            float a0 = d0*d0, a1 = d1*d1, a2 = d2*d2, a3 = d3*d3;
            __nv_bfloat162 h01 = __floats2bfloat162_rn(a0, a1);
            __nv_bfloat162 h23 = __floats2bfloat162_rn(a2, a3);
            float r0 = a0 - __bfloat162float(h01.x);
            float r1 = a1 - __bfloat162float(h01.y);
            float r2 = a2 - __bfloat162float(h23.x);
            float r3 = a3 - __bfloat162float(h23.y);
            __nv_bfloat162 l01 = __floats2bfloat162_rn(r0, r1);
            __nv_bfloat162 l23 = __floats2bfloat162_rn(r2, r3);
            *(uint2*)&sAh[row][q*4] = make_uint2(*(uint32_t*)&h01, *(uint32_t*)&h23);
            *(uint2*)&sAl[row][q*4] = make_uint2(*(uint32_t*)&l01, *(uint32_t*)&l23);
        }
        // ---- B: 256 rows pre-split bf16 [n][k] ----
        #pragma unroll
        for (int i = 0; i < 4; i++) {
            int slot = tid + i*256;             // 1024 = 256 rows x 4 x 16B
            int row = slot >> 2, c = slot & 3;
            size_t src = (size_t)row*ND + k0 + c*8;
            *(uint4*)&sBh[row][c*8] = *(const uint4*)(Bh + src);
            *(uint4*)&sBl[row][c*8] = *(const uint4*)(Bl + src);
        }
        __syncthreads();

        #pragma unroll
        for (int k16 = 0; k16 < 2; k16++) {
            uint32_t bh[8][2], bl[8][2];
            #pragma unroll
            for (int p = 0; p < 4; p++) {
                uint32_t off = (uint32_t)((b_row + p*16)*APAD + k16*16 + b_col8) * 2;
                uint32_t r0, r1, r2, r3;
                LDSM4(r0, r1, r2, r3, aBh + off);
                bh[p*2+0][0] = r0; bh[p*2+0][1] = r1;
                bh[p*2+1][0] = r2; bh[p*2+1][1] = r3;
                LDSM4(r0, r1, r2, r3, aBl + off);
                bl[p*2+0][0] = r0; bl[p*2+0][1] = r1;
                bl[p*2+1][0] = r2; bl[p*2+1][1] = r3;
            }
            #pragma unroll
            for (int mt = 0; mt < 4; mt++) {
                uint32_t ah[4], al[4];
                uint32_t off = (uint32_t)((a_row + mt*16)*APAD + k16*16 + a_col8) * 2;
                LDSM4(ah[0], ah[1], ah[2], ah[3], aAh + off);
                LDSM4(al[0], al[1], al[2], al[3], aAl + off);
                #pragma unroll
                for (int nt = 0; nt < 8; nt++) {
                    MMA_BF16(acc[mt][nt], ah, bh[nt]);
                    MMA_BF16(acc[mt][nt], ah, bl[nt]);
                    MMA_BF16(acc[mt][nt], al, bh[nt]);
                }
            }
        }
        __syncthreads();
    }

    // ---- epilogue ----
    #pragma unroll
    for (int mt = 0; mt < 4; mt++) {
        int lmA = mw*64 + mt*16 + (lane >> 2);   // local row for c0,c1
        int lmB = lmA + 8;
        int mA = m0 + lmA, mB = m0 + lmB;
        // bias + relu in registers
        float vA[8][2], vB[8][2];
        float ssqA = 0.f, ssqB = 0.f;
        #pragma unroll
        for (int nt = 0; nt < 8; nt++) {
            int n = nw*64 + nt*8 + (lane & 3)*2;
            float b0 = bias[n], b1 = bias[n+1];
            vA[nt][0] = fmaxf(acc[mt][nt][0] + b0, 0.f);
            vA[nt][1] = fmaxf(acc[mt][nt][1] + b1, 0.f);
            vB[nt][0] = fmaxf(acc[mt][nt][2] + b0, 0.f);
            vB[nt][1] = fmaxf(acc[mt][nt][3] + b1, 0.f);
            if (MODE == 0) {
                ssqA += vA[nt][0]*vA[nt][0] + vA[nt][1]*vA[nt][1];
                ssqB += vB[nt][0]*vB[nt][0] + vB[nt][1]*vB[nt][1];
            }
        }
        float invA = 1.f, invB = 1.f;
        if (MODE == 0) {
            // reduce over 4 lanes sharing a row (lane&3)
            ssqA += __shfl_xor_sync(0xffffffffu, ssqA, 1);
            ssqA += __shfl_xor_sync(0xffffffffu, ssqA, 2);
            ssqB += __shfl_xor_sync(0xffffffffu, ssqB, 1);
            ssqB += __shfl_xor_sync(0xffffffffu, ssqB, 2);
            int rA = mw*32 + mt*8 + (lane >> 2) - mt*8 + mt*8;  // = mw*32 ... compute directly below
            // row_local within 64-slot buffer: A rows: mw*32 + mt*8 + (lane>>2)? rows per mt: 16 A + 16 B
            // Use: idxA = mw*32 + (lane>>2);  idxB = mw*32 + 16 + (lane>>2)   (per-mt buffer)
            (void)rA;
            if ((lane & 3) == 0) {
                sred[nw][mw*32 + (lane >> 2)] = ssqA;
                sred[nw][mw*32 + 16 + (lane >> 2)] = ssqB;
            }
            __syncthreads();
            if (tid < 64) {
                float s = sred[0][tid] + sred[1][tid] + sred[2][tid] + sred[3][tid];
                sinv[tid] = 1.f / (sqrtf(s) + EPSL);
            }
            __syncthreads();
            invA = sinv[mw*32 + (lane >> 2)];
            invB = sinv[mw*32 + 16 + (lane >> 2)];
        }
        float* dA;
        float* dB;
        if (MODE == 0) {
            int bA = mA / NR, rA2 = mA % NR;
            int bB = mB / NR, rB2 = mB % NR;
            dA = outp + (((size_t)z*NB + bA)*37 + 1 + rA2)*NS;
            dB = outp + (((size_t)z*NB + bB)*37 + 1 + rB2)*NS;
        } else {
            dA = outp + ((size_t)z*2304 + mA)*NS;
            dB = outp + ((size_t)z*2304 + mB)*NS;
        }
        #pragma unroll
        for (int nt = 0; nt < 8; nt++) {
            int n = nw*64 + nt*8 + (lane & 3)*2;
            *(float2*)&dA[n] = make_float2(vA[nt][0]*invA, vA[nt][1]*invA);
            *(float2*)&dB[n] = make_float2(vB[nt][0]*invB, vB[nt][1]*invB);
        }
        if (MODE == 0) __syncthreads();   // protect sred/sinv reuse across mt
    }
}

// ============ small-M GEMM via split-K ============
__global__ void gemm_small_part(const float* __restrict__ A, const float* __restrict__ W,
                                float* __restrict__ part, int M, int N, int K)
{
    const int BK = 16;
    __shared__ float As[BK][64];
    __shared__ float Bs[BK][64];
    int tid = threadIdx.x, tr = tid >> 4, tc = tid & 15;
    int n0 = blockIdx.x * 64;
    int KS = gridDim.y;
    int Kc = K / KS;
    int kz = blockIdx.y;
    float acc[4][4] = {};
    for (int k0 = kz*Kc; k0 < (kz+1)*Kc; k0 += BK) {
        for (int i = tid; i < 64*BK; i += 256) {
            int m = i >> 4, k = i & 15;
            As[k][m] = (m < M) ? A[(size_t)m*K + k0 + k] : 0.f;
        }
        for (int i = tid; i < BK*64; i += 256) {
            int k = i >> 6, n = i & 63;
            Bs[k][n] = W[(size_t)(k0+k)*N + n0 + n];
        }
        __syncthreads();
        #pragma unroll
        for (int k = 0; k < BK; k++) {
            float a[4], b[4];
            #pragma unroll
            for (int i = 0; i < 4; i++) a[i] = As[k][tr*4+i];
            #pragma unroll
            for (int j = 0; j < 4; j++) b[j] = Bs[k][tc*4+j];
            #pragma unroll
            for (int i = 0; i < 4; i++)
                #pragma unroll
                for (int j = 0; j < 4; j++) acc[i][j] += a[i]*b[j];
        }
        __syncthreads();
    }
    #pragma unroll
    for (int i = 0; i < 4; i++) {
        int m = tr*4 + i;
        if (m >= M) continue;
        #pragma unroll
        for (int j = 0; j < 4; j++)
            part[((size_t)kz*M + m)*N + n0 + tc*4 + j] = acc[i][j];
    }
}

template<int ACT>
__global__ void k_small_epi(const float* __restrict__ part, const float* __restrict__ bias,
                            float* __restrict__ C, int M, int N, int KS)
{
    int idx = blockIdx.x*256 + threadIdx.x;
    if (idx >= M*N) return;
    int n = idx % N;
    float s = 0.f;
    for (int kz = 0; kz < KS; kz++) s += part[(size_t)kz*M*N + idx];
    s += bias[n];
    if (ACT == 1) s = tanhf(s);
    C[idx] = s;
}

// ---------------- tiny glo diff-square GEMM ----------------
__global__ void gemm_diffsq_glo(const float* __restrict__ X, const float* __restrict__ Y,
                                const float* __restrict__ W, const float* __restrict__ bias,
                                float* __restrict__ Cbase, int M, int N, int K)
{
    const int BM = 64, BN = 64, BK = 16;
    int c = blockIdx.z;
    const float* Yp = Y + (size_t)c*K;
    __shared__ float As[BK][BM];
    __shared__ float Bs[BK][BN];
    int tid = threadIdx.x;
    int tr = tid >> 4, tc = tid & 15;
    int m0 = blockIdx.y * BM, n0 = blockIdx.x * BN;
    float acc[4][4] = {};
    for (int k0 = 0; k0 < K; k0 += BK) {
        #pragma unroll
        for (int i = tid; i < BM*BK; i += 256) {
            int m = i >> 4, k = i & 15;
            float v = 0.f;
            if (m0 + m < M) {
                float d = X[(size_t)(m0+m)*K + k0 + k] - Yp[k0 + k];
                v = d * d;
            }
            As[k][m] = v;
        }
        #pragma unroll
        for (int i = tid; i < BK*BN; i += 256) {
            int k = i >> 6, n = i & 63;
            Bs[k][n] = W[(size_t)(k0+k)*N + n0 + n];
        }
        __syncthreads();
        #pragma unroll
        for (int k = 0; k < BK; k++) {
            float a[4], b[4];
            #pragma unroll
            for (int i = 0; i < 4; i++) a[i] = As[k][tr*4+i];
            #pragma unroll
            for (int j = 0; j < 4; j++) b[j] = Bs[k][tc*4+j];
            #pragma unroll
            for (int i = 0; i < 4; i++)
                #pragma unroll
                for (int j = 0; j < 4; j++) acc[i][j] += a[i]*b[j];
        }
        __syncthreads();
    }
    #pragma unroll
    for (int i = 0; i < 4; i++) {
        int m = m0 + tr*4 + i;
        if (m >= M) continue;
        #pragma unroll
        for (int j = 0; j < 4; j++) {
            int n = n0 + tc*4 + j;
            float v = fmaxf(acc[i][j] + bias[n], 0.f);
            Cbase[(size_t)c*M*N + (size_t)m*N + n] = v;
        }
    }
}

// ---------------- small kernels ----------------
__global__ void k_imgave(const float* __restrict__ img) {
    int i = blockIdx.x*blockDim.x + threadIdx.x;
    int b = i >> 10, d = i & 1023;
    float s = 0.f;
    for (int r = 0; r < NR; r++) s += img[((size_t)b*NR + r)*ND + d];
    g_imgave[i] = s * (1.f / NR);
}

__global__ void k_bnstats() {
    int r = blockIdx.x;
    __shared__ float red[256], red2[256];
    float s = 0.f, ss = 0.f;
    for (int i = threadIdx.x; i < NB*ND; i += 256) {
        int b = i >> 10, d = i & 1023;
        float v = g_h[((size_t)b*NR + r)*ND + d];
        s += v; ss += v*v;
    }
    red[threadIdx.x] = s; red2[threadIdx.x] = ss; __syncthreads();
    for (int st = 128; st > 0; st >>= 1) {
        if (threadIdx.x < st) { red[threadIdx.x] += red[threadIdx.x+st]; red2[threadIdx.x] += red2[threadIdx.x+st]; }
        __syncthreads();
    }
    if (threadIdx.x == 0) {
        float mu = red[0] / (float)(NB*ND);
        g_bnmu[r] = mu;
        g_bnvar[r] = red2[0] / (float)(NB*ND) - mu*mu;
    }
}

__global__ void k_gbn(const float* __restrict__ gamma, const float* __restrict__ beta) {
    int d = blockIdx.x*blockDim.x + threadIdx.x;
    float s = 0.f, ss = 0.f;
    for (int b = 0; b < NB; b++) { float v = g_g[(size_t)b*ND + d]; s += v; ss += v*v; }
    float mu = s / NB;
    float var = ss / NB - mu*mu;
    float inv = rsqrtf(var + BNEPS);
    float ga = gamma[d], be = beta[d];
    for (int b = 0; b < NB; b++) {
        float v = g_g[(size_t)b*ND + d];
        g_g[(size_t)b*ND + d] = tanhf((v - mu)*inv*ga + be);
    }
}

__global__ void k_wraw(const float* __restrict__ vcw, const float* __restrict__ vcb,
                       const float* __restrict__ lg, const float* __restrict__ lb) {
    int br = blockIdx.x;
    int b = br / NR, r = br % NR;
    __shared__ float red[256];
    float mu = g_bnmu[r], inv = rsqrtf(g_bnvar[r] + BNEPS);
    float ga = lg[r], be = lb[r];
    float s = 0.f;
    for (int d = threadIdx.x; d < ND; d += 256) {
        float le = tanhf((g_h[(size_t)br*ND + d] - mu)*inv*ga + be);
        s += le * g_g[(size_t)b*ND + d] * vcw[d];
    }
    float tot = blockReduceSum256(s, red);
    if (threadIdx.x == 0) g_wraw[br] = tot + vcb[0];
}

__global__ void k_newglobal(const float* __restrict__ img) {
    int b = blockIdx.x;
    __shared__ float w[NR];
    __shared__ float red[256];
    __shared__ float invn;
    if (threadIdx.x == 0) {
        float mx = -1e30f;
        for (int r = 0; r < NR; r++) mx = fmaxf(mx, g_wraw[b*NR + r]);
        float sum = 0.f;
        for (int r = 0; r < NR; r++) { w[r] = expf(g_wraw[b*NR + r] - mx); sum += w[r]; }
        float is = 1.f / sum;
        for (int r = 0; r < NR; r++) w[r] *= is;
    }
    __syncthreads();
    float ssq = 0.f;
    for (int d = threadIdx.x; d < ND; d += 256) {
        float s = 0.f;
        for (int r = 0; r < NR; r++) s += w[r] * img[((size_t)b*NR + r)*ND + d];
        g_imgglo[(size_t)b*ND + d] = s;
        ssq += s*s;
    }
    float tot = blockReduceSum256(ssq, red);
    if (threadIdx.x == 0) {
        float nrm = sqrtf(tot) + EPSL;
        g_normglo[b] = nrm;
        invn = 1.f / nrm;
    }
    __syncthreads();
    for (int d = threadIdx.x; d < ND; d += 256) g_imgglo[(size_t)b*ND + d] *= invn;
}

__global__ void k_imgpar(const float* __restrict__ img, const int* __restrict__ adjs) {
    int br = blockIdx.x;
    int b = br / NR, r = br % NR;
    __shared__ int eff[NPART];
    __shared__ float wg[NPART];
    if (threadIdx.x == 0) {
        int cnt = 0;
        const int* row = adjs + (size_t)b*NR*NR + (size_t)r*NR;
        for (int j = 0; j < NR && cnt < NPART; j++)
            if (row[j] == 1) eff[cnt++] = j;
        for (; cnt < NPART; cnt++) eff[cnt] = r;
        float v[NPART], mx = -1e30f;
        for (int k = 0; k < NPART; k++) { v[k] = g_wraw[b*NR + eff[k]]; mx = fmaxf(mx, v[k]); }
        float sum = 0.f;
        for (int k = 0; k < NPART; k++) { v[k] = expf(v[k] - mx); sum += v[k]; }
        float is = 1.f / sum;
        for (int k = 0; k < NPART; k++) wg[k] = v[k]*is;
    }
    __syncthreads();
    float invn = 1.f / g_normglo[b];
    for (int d = threadIdx.x; d < ND; d += 256) {
        float s = 0.f;
        #pragma unroll
        for (int k = 0; k < NPART; k++) s += wg[k] * img[((size_t)b*NR + eff[k])*ND + d];
        g_imgpar[(size_t)br*ND + d] = s * invn;
    }
}

__global__ void k_capave(const float* __restrict__ cap) {
    int i = blockIdx.x*blockDim.x + threadIdx.x;
    int c = i >> 10, d = i & 1023;
    float s = 0.f;
    for (int n = 0; n < NWD; n++) s += cap[((size_t)c*NWD + n)*ND + d];
    g_capave[i] = s * (1.f / NWD);
}

__global__ void k_capglo(const float* __restrict__ cap, const float* __restrict__ tsacw,
                         const float* __restrict__ tsacb) {
    int c = blockIdx.x;
    __shared__ float red[256];
    __shared__ float cw[NWD];
    __shared__ float invn;
    float gw[4];
    #pragma unroll
    for (int i = 0; i < 4; i++) {
        int d = threadIdx.x + i*256;
        gw[i] = g_ge[(size_t)c*ND + d] * tsacw[d];
    }
    for (int n = 0; n < NWD; n++) {
        float s = 0.f;
        #pragma unroll
        for (int i = 0; i < 4; i++) {
            int d = threadIdx.x + i*256;
            s += g_le[((size_t)c*NWD + n)*ND + d] * gw[i];
        }
        float tot = blockReduceSum256(s, red);
        if (threadIdx.x == 0) cw[n] = tot + tsacb[0];
    }
    __syncthreads();
    if (threadIdx.x == 0) {
        float mx = -1e30f;
        for (int n = 0; n < NWD; n++) mx = fmaxf(mx, cw[n]);
        float sum = 0.f;
        for (int n = 0; n < NWD; n++) { cw[n] = expf(cw[n] - mx); sum += cw[n]; }
        float is = 1.f / sum;
        for (int n = 0; n < NWD; n++) cw[n] *= is;
    }
    __syncthreads();
    float ssq = 0.f;
    #pragma unroll
    for (int i = 0; i < 4; i++) {
        int d = threadIdx.x + i*256;
        float s = 0.f;
        for (int n = 0; n < NWD; n++) s += cw[n] * cap[((size_t)c*NWD + n)*ND + d];
        g_capglo[(size_t)c*ND + d] = s;
        ssq += s*s;
    }
    float tot = blockReduceSum256(ssq, red);
    if (threadIdx.x == 0) invn = 1.f / (sqrtf(tot) + EPSL);
    __syncthreads();
    #pragma unroll
    for (int i = 0; i < 4; i++) {
        int d = threadIdx.x + i*256;
        g_capglo[(size_t)c*ND + d] *= invn;
    }
}

__global__ void k_attnfuse() {
    int cb = blockIdx.x;
    int c = cb / NB, b = cb % NB;
    __shared__ float sA[NWD*NR];
    __shared__ float nrm[NWD];
    const float* raw = g_attnraw + (size_t)c*NWD*NB*NR;
    for (int i = threadIdx.x; i < NWD*NR; i += 256) {
        int n = i / NR, r = i % NR;
        float v = raw[(size_t)n*NB*NR + (size_t)b*NR + r];
        v = (v > 0.f) ? v : 0.1f*v;
        sA[i] = v;
    }
    __syncthreads();
    if (threadIdx.x < NWD) {
        int n = threadIdx.x;
        float s = 0.f;
        for (int r = 0; r < NR; r++) { float v = sA[n*NR + r]; s += v*v; }
        nrm[n] = 1.f / (sqrtf(s) + EPSL);
    }
    __syncthreads();
    if (threadIdx.x < NR) {
        int r = threadIdx.x;
        float vals[NWD];
        float mx = -1e30f;
        for (int n = 0; n < NWD; n++) {
            float v = SMOOTHF * sA[n*NR + r] * nrm[n];
            vals[n] = v;
            mx = fmaxf(mx, v);
        }
        float sum = 0.f;
        for (int n = 0; n < NWD; n++) { vals[n] = expf(vals[n] - mx); sum += vals[n]; }
        float is = 1.f / sum;
        float* outp = g_attnT + ((size_t)cb*NR + r)*NWD;
        for (int n = 0; n < NWD; n++) outp[n] = vals[n]*is;
    }
}

__global__ void k_ctx(const float* __restrict__ cap) {
    int cb = blockIdx.x;
    int c = cb / NB;
    __shared__ float sT[NR*NWD];
    const float* at = g_attnT + (size_t)cb*NR*NWD;
    for (int i = threadIdx.x; i < NR*NWD; i += 256) sT[i] = at[i];
    __syncthreads();
    float* outp = g_ctx + (size_t)cb*NR*ND;
    for (int it = 0; it < 4; it++) {
        int d = threadIdx.x + it*256;
        float acc[NR];
        #pragma unroll
        for (int r = 0; r < NR; r++) acc[r] = 0.f;
        for (int n = 0; n < NWD; n++) {
            float cv = cap[((size_t)c*NWD + n)*ND + d];
            #pragma unroll
            for (int r = 0; r < NR; r++) acc[r] += sT[r*NWD + n] * cv;
        }
        for (int r = 0; r < NR; r++) outp[(size_t)r*ND + d] = acc[r];
    }
}

__global__ void k_ctxssq() {
    int row = blockIdx.x * 8 + (threadIdx.x >> 5);
    int lane = threadIdx.x & 31;
    const float* p = g_ctx + (size_t)row * ND;
    float s = 0.f;
    #pragma unroll
    for (int i = 0; i < 8; i++) {
        float4 v = *(const float4*)(p + lane*4 + i*128);
        s += v.x*v.x + v.y*v.y + v.z*v.z + v.w*v.w;
    }
    s = warpReduceSum(s);
    if (lane == 0) g_ctxinv[row] = 1.f / (sqrtf(s) + EPSL);
}

__global__ void k_rownorm(float* __restrict__ X, int L) {
    size_t row = blockIdx.x;
    float* p = X + row*(size_t)L;
    __shared__ float red[256];
    __shared__ float invn;
    float s = 0.f;
    for (int i = threadIdx.x; i < L; i += 256) { float v = p[i]; s += v*v; }
    float tot = blockReduceSum256(s, red);
    if (threadIdx.x == 0) invn = 1.f / (sqrtf(tot) + EPSL);
    __syncthreads();
    for (int i = threadIdx.x; i < L; i += 256) p[i] *= invn;
}

// finalize: warp-parallel over r, simpar row-norm fused
__global__ void k_finalize(const float* __restrict__ simw, const float* __restrict__ simb,
                           const float* __restrict__ lng, const float* __restrict__ lnb,
                           float* __restrict__ out, size_t out2off) {
    int cb = blockIdx.x;
    int tid = threadIdx.x;
    int lane = tid & 31, warp = tid >> 5;
    const float* sg = out + out2off + (size_t)cb*NS;
    __shared__ float sSgw[NS];
    __shared__ float wv[NR];
    __shared__ float mv[2];
    float sgv = sg[tid];
    sSgw[tid] = sgv * simw[tid];
    __syncthreads();
    const float* sp = g_simpar + (size_t)cb*NR*NS;
    for (int r = warp; r < NR; r += 8) {
        const float* row = sp + (size_t)r*NS;
        float dot = 0.f, ss = 0.f;
        #pragma unroll
        for (int i = 0; i < 8; i++) {
            int c = lane + i*32;
            float v = row[c];
            dot += v * sSgw[c];
            ss += v * v;
        }
        dot = warpReduceSum(dot);
        ss = warpReduceSum(ss);
        if (lane == 0) wv[r] = dot / (sqrtf(ss) + EPSL) + simb[0];
    }
    __syncthreads();
    if (tid == 0) {
        float m = 0.f;
        for (int r = 0; r < NR; r++) m += wv[r];
        m /= NR;
        float v = 0.f;
        for (int r = 0; r < NR; r++) { float d = wv[r] - m; v += d*d; }
        v /= NR;
        mv[0] = m; mv[1] = rsqrtf(v + LNEPS);
    }
    __syncthreads();
    if (tid < NR) {
        int r = tid;
        float z = (wv[r] - mv[0])*mv[1]*lng[r] + lnb[r];
        wv[r] = 1.f / (1.f + expf(-z));
    }
    __syncthreads();
    float* ob = out + (size_t)cb*37*NS;
    ob[tid] = sgv;
    for (int r = 0; r < NR; r++) ob[(size_t)(1+r)*NS + tid] *= wv[r];
}

// ---------------- host ----------------
extern "C" void kernel_launch(void* const* d_in, const int* in_sizes, int n_in,
                              void* d_out, int out_size) {
    (void)in_sizes; (void)n_in; (void)out_size;
    const float* img    = (const float*)d_in[0];
    const float* cap    = (const float*)d_in[1];
    const int*   adjs   = (const int*)d_in[3];
    const float* tsa_lw = (const float*)d_in[5];
    const float* tsa_lb = (const float*)d_in[6];
    const float* tsa_gw = (const float*)d_in[7];
    const float* tsa_gb = (const float*)d_in[8];
    const float* tsa_cw = (const float*)d_in[9];
    const float* tsa_cb = (const float*)d_in[10];
    const float* vl_w   = (const float*)d_in[11];
    const float* vl_b   = (const float*)d_in[12];
    const float* vbn_lg = (const float*)d_in[13];
    const float* vbn_lb = (const float*)d_in[14];
    const float* vg_w   = (const float*)d_in[15];
    const float* vg_b   = (const float*)d_in[16];
    const float* vbn_gg = (const float*)d_in[17];
    const float* vbn_gb = (const float*)d_in[18];
    const float* vc_w   = (const float*)d_in[19];
    const float* vc_b   = (const float*)d_in[20];
    const float* loc_w  = (const float*)d_in[21];
    const float* loc_b  = (const float*)d_in[22];
    const float* par_w  = (const float*)d_in[23];
    const float* par_b  = (const float*)d_in[24];
    const float* glo_w  = (const float*)d_in[25];
    const float* glo_b  = (const float*)d_in[26];
    const float* sim_w  = (const float*)d_in[27];
    const float* sim_b  = (const float*)d_in[28];
    const float* ln_g   = (const float*)d_in[29];
    const float* ln_b   = (const float*)d_in[30];
    float* out = (float*)d_out;

    static bool inited = false;
    static float *p_h, *p_imgave, *p_g, *p_ge, *p_le, *p_attnraw,
                 *p_ctx, *p_ctxinv, *p_imgpar, *p_imgglo, *p_capglo, *p_simpar, *p_part, *p_capave;
    static __nv_bfloat16 *p_wth, *p_wtl, *p_imgh, *p_imgl, *p_caph, *p_capl, *p_wbh, *p_wbl;
    if (!inited) {
        cudaGetSymbolAddress((void**)&p_h, g_h);
        cudaGetSymbolAddress((void**)&p_imgave, g_imgave);
        cudaGetSymbolAddress((void**)&p_g, g_g);
        cudaGetSymbolAddress((void**)&p_ge, g_ge);
        cudaGetSymbolAddress((void**)&p_le, g_le);
        cudaGetSymbolAddress((void**)&p_attnraw, g_attnraw);
        cudaGetSymbolAddress((void**)&p_ctx, g_ctx);
        cudaGetSymbolAddress((void**)&p_ctxinv, g_ctxinv);
        cudaGetSymbolAddress((void**)&p_imgpar, g_imgpar);
        cudaGetSymbolAddress((void**)&p_imgglo, g_imgglo);
        cudaGetSymbolAddress((void**)&p_capglo, g_capglo);
        cudaGetSymbolAddress((void**)&p_simpar, g_simpar);
        cudaGetSymbolAddress((void**)&p_part, g_part);
        cudaGetSymbolAddress((void**)&p_capave, g_capave);
        cudaGetSymbolAddress((void**)&p_wth, g_wth);
        cudaGetSymbolAddress((void**)&p_wtl, g_wtl);
        cudaGetSymbolAddress((void**)&p_imgh, g_imgh);
        cudaGetSymbolAddress((void**)&p_imgl, g_imgl);
        cudaGetSymbolAddress((void**)&p_caph, g_caph);
        cudaGetSymbolAddress((void**)&p_capl, g_capl);
        cudaGetSymbolAddress((void**)&p_wbh, g_wbh);
        cudaGetSymbolAddress((void**)&p_wbl, g_wbl);
        inited = true;
    }

    const size_t out2off = (size_t)NCAP*NB*37*NS;
    float* out2 = out + out2off;

    // ---- operand splits ----
    k_split<<<(NB*NR*ND+255)/256, 256>>>(img, p_imgh, p_imgl, NB*NR*ND);
    k_split<<<(NCAP*NWD*ND+255)/256, 256>>>(cap, p_caph, p_capl, NCAP*NWD*ND);
    k_wsplitT<<<(ND*ND+255)/256, 256>>>(vl_w,   p_wbh,         p_wbl,         ND, ND);
    k_wsplitT<<<(ND*ND+255)/256, 256>>>(tsa_lw, p_wbh + ND*ND, p_wbl + ND*ND, ND, ND);
    k_wsplitT<<<(NS*ND+255)/256, 256>>>(loc_w,  p_wth,         p_wtl,         NS, ND);
    k_wsplitT<<<(NS*ND+255)/256, 256>>>(par_w,  p_wth + NS*ND, p_wtl + NS*ND, NS, ND);

    // ---- caption-independent ----
    k_imgave<<<256, 256>>>(img);
    hmma_gemm<0><<<dim3(8, 18), 256>>>(p_imgh, p_imgl, p_wbh, p_wbl, vl_b, p_h, ND, ND);
    k_bnstats<<<NR, 256>>>();
    gemm_small_part<<<dim3(16, 8), 256>>>(p_imgave, vg_w, p_part, NB, ND, ND);
    k_small_epi<0><<<(NB*ND+255)/256, 256>>>(p_part, vg_b, p_g, NB, ND, 8);
    k_gbn<<<4, 256>>>(vbn_gg, vbn_gb);
    k_wraw<<<NB*NR, 256>>>(vc_w, vc_b, vbn_lg, vbn_lb);
    k_newglobal<<<NB, 256>>>(img);
    k_imgpar<<<NB*NR, 256>>>(img, adjs);

    // ---- caption side ----
    k_capave<<<128, 256>>>(cap);
    hmma_gemm<1><<<dim3(8, 10), 256>>>(p_caph, p_capl, p_wbh + ND*ND, p_wbl + ND*ND,
                                       tsa_lb, p_le, ND, ND);
    gemm_small_part<<<dim3(16, 8), 256>>>(p_capave, tsa_gw, p_part, NCAP, ND, ND);
    k_small_epi<1><<<(NCAP*ND+255)/256, 256>>>(p_part, tsa_gb, p_ge, NCAP, ND, 8);
    k_capglo<<<NCAP, 256>>>(cap, tsa_cw, tsa_cb);

    hmma_gemm<0><<<dim3(18, 10), 256>>>(p_caph, p_capl, p_imgh, p_imgl,
                                        nullptr, p_attnraw, NB*NR, ND);
    k_attnfuse<<<NCAP*NB, 256>>>();
    k_ctx<<<NCAP*NB, 256>>>(cap);
    k_ctxssq<<<NCAP*NB*NR/8, 256>>>();

    // ---- heavy diff-square GEMMs (HMMA split-bf16, full-N tile) ----
    hmma_diffsq<0><<<dim3(18, NCAP), 256>>>(p_ctx, img, p_ctxinv, p_wth, p_wtl, loc_b, out);
    hmma_diffsq<1><<<dim3(18, NCAP), 256>>>(p_imgpar, p_capglo, nullptr,
                                            p_wth + NS*ND, p_wtl + NS*ND, par_b, p_simpar);

    // sim_glo (tiny, fp32)
    gemm_diffsq_glo<<<dim3(4, 1, NCAP), 256>>>(p_imgglo, p_capglo, glo_w, glo_b, out2, NB, NS, ND);
    k_rownorm<<<NCAP*NB, 256>>>(out2, NS);

    // ---- finalize ----
    k_finalize<<<NCAP*NB, 256>>>(sim_w, sim_b, ln_g, ln_b, out, out2off);
}

// round 10
// speedup vs baseline: 4.1211x; 1.0714x over previous
#include <cuda_runtime.h>
#include <cuda_bf16.h>
#include <cstdint>
#include <stdint.h>
#include <math.h>

#define NB 64
#define NR 36
#define ND 1024
#define NCAP 32
#define NWD 40
#define NS 256
#define NPART 5
#define EPSL 1e-8f
#define BNEPS 1e-5f
#define LNEPS 1e-5f
#define SMOOTHF 9.0f

typedef unsigned long long ull;

// ---------------- scratch ----------------
__device__ float g_h[NB*NR*ND];
__device__ float g_imgave[NB*ND];
__device__ float g_bnmu[NR];
__device__ float g_bnvar[NR];
__device__ float g_g[NB*ND];
__device__ float g_wraw[NB*NR];
__device__ float g_imgglo[NB*ND];
__device__ float g_normglo[NB];
__device__ float g_imgpar[NB*NR*ND];
__device__ float g_capave[NCAP*ND];
__device__ float g_le[NCAP*NWD*ND];
__device__ float g_ge[NCAP*ND];
__device__ float g_capglo[NCAP*ND];
__device__ float g_attnraw[(size_t)NCAP*NWD*NB*NR];
__device__ float g_attnT[(size_t)NCAP*NB*NR*NWD];
__device__ float g_ctx[(size_t)NCAP*NB*NR*ND];
__device__ float g_ctxinv[NCAP*NB*NR];
__device__ float g_simpar[(size_t)NCAP*NB*NR*NS];
__device__ float g_part[8*64*1024];
__device__ __nv_bfloat16 g_wth[2][NS*ND];
__device__ __nv_bfloat16 g_wtl[2][NS*ND];
__device__ __nv_bfloat16 g_imgh[NB*NR*ND], g_imgl[NB*NR*ND];
__device__ __nv_bfloat16 g_caph[NCAP*NWD*ND], g_capl[NCAP*NWD*ND];
__device__ __nv_bfloat16 g_wbh[2][ND*ND], g_wbl[2][ND*ND];

// ---------------- helpers ----------------
__device__ __forceinline__ uint32_t smem_u32(const void* p) {
    uint32_t a;
    asm("{ .reg .u64 t; cvta.to.shared.u64 t, %1; cvt.u32.u64 %0, t; }" : "=r"(a) : "l"(p));
    return a;
}

__device__ __forceinline__ void cp_async16(uint32_t dst, const void* src) {
    asm volatile("cp.async.cg.shared.global [%0], [%1], 16;" :: "r"(dst), "l"(src));
}
#define CP_COMMIT() asm volatile("cp.async.commit_group;")
#define CP_WAIT0()  asm volatile("cp.async.wait_group 0;")
#define CP_WAIT1()  asm volatile("cp.async.wait_group 1;")

__device__ __forceinline__ float blockReduceSum256(float v, float* red) {
    int tid = threadIdx.x;
    red[tid] = v; __syncthreads();
    #pragma unroll
    for (int s = 128; s > 0; s >>= 1) {
        if (tid < s) red[tid] += red[tid + s];
        __syncthreads();
    }
    float r = red[0]; __syncthreads();
    return r;
}

__device__ __forceinline__ float warpReduceSum(float v) {
    v += __shfl_xor_sync(0xffffffffu, v, 16);
    v += __shfl_xor_sync(0xffffffffu, v, 8);
    v += __shfl_xor_sync(0xffffffffu, v, 4);
    v += __shfl_xor_sync(0xffffffffu, v, 2);
    v += __shfl_xor_sync(0xffffffffu, v, 1);
    return v;
}

#define LDSM4(r0, r1, r2, r3, addr) \
    asm volatile("ldmatrix.sync.aligned.m8n8.x4.shared.b16 {%0,%1,%2,%3}, [%4];" \
        : "=r"(r0), "=r"(r1), "=r"(r2), "=r"(r3) : "r"(addr))

#define MMA_BF16(d, a, b) \
    asm volatile("mma.sync.aligned.m16n8k16.row.col.f32.bf16.bf16.f32 " \
        "{%0,%1,%2,%3}, {%4,%5,%6,%7}, {%8,%9}, {%0,%1,%2,%3};" \
        : "+f"((d)[0]), "+f"((d)[1]), "+f"((d)[2]), "+f"((d)[3]) \
        : "r"((a)[0]), "r"((a)[1]), "r"((a)[2]), "r"((a)[3]), "r"((b)[0]), "r"((b)[1]))

// ---------------- split kernels ----------------
__global__ void k_split(const float* __restrict__ X, __nv_bfloat16* __restrict__ H,
                        __nv_bfloat16* __restrict__ L, int total) {
    int idx = blockIdx.x * 256 + threadIdx.x;
    if (idx >= total) return;
    float v = X[idx];
    __nv_bfloat16 h = __float2bfloat16(v);
    H[idx] = h;
    L[idx] = __float2bfloat16(v - __bfloat162float(h));
}

__global__ void k_wsplitT(const float* __restrict__ W, __nv_bfloat16* __restrict__ H,
                          __nv_bfloat16* __restrict__ L, int Ncols, int K) {
    int idx = blockIdx.x * 256 + threadIdx.x;
    if (idx >= Ncols * K) return;
    int n = idx / K, k = idx - n * K;
    float w = W[(size_t)k * Ncols + n];
    __nv_bfloat16 h = __float2bfloat16(w);
    H[idx] = h;
    L[idx] = __float2bfloat16(w - __bfloat162float(h));
}

#define APAD 40
// gemm pipeline smem layout (per stage 40960B): Ah 0, Al 10240, Bh 20480, Bl 30720
#define GS_STAGE 40960
#define GS_TOTAL (2*GS_STAGE)
// diffsq layout: sAh 0, sAl 10240, sBh[2] 20480+, sBl[2] 61440+, sred 102400, sinv 103424
#define DS_AH 0
#define DS_AL 10240
#define DS_BH 20480
#define DS_BL 61440
#define DS_RED 102400
#define DS_INV 103424
#define DS_TOTAL 103680

// ============ generic HMMA GEMM, cp.async double-buffered ============
template<int ACT>
__global__ void __launch_bounds__(256)
hmma_gemm(const __nv_bfloat16* __restrict__ Ah, const __nv_bfloat16* __restrict__ Al,
          const __nv_bfloat16* __restrict__ Bh, const __nv_bfloat16* __restrict__ Bl,
          const float* __restrict__ bias, float* __restrict__ C, int N, int K)
{
    extern __shared__ char smem[];
    uint32_t sb = smem_u32(smem);
    int tid = threadIdx.x, lane = tid & 31, warp = tid >> 5;
    int mw = warp >> 2, nw = warp & 3;
    int n0 = blockIdx.x * 128, m0 = blockIdx.y * 128;
    const __nv_bfloat16* Ah0 = Ah + (size_t)m0 * K;
    const __nv_bfloat16* Al0 = Al + (size_t)m0 * K;
    const __nv_bfloat16* Bh0 = Bh + (size_t)n0 * K;
    const __nv_bfloat16* Bl0 = Bl + (size_t)n0 * K;

    float acc[4][4][4];
    #pragma unroll
    for (int i = 0; i < 4; i++)
        #pragma unroll
        for (int j = 0; j < 4; j++)
            #pragma unroll
            for (int e = 0; e < 4; e++) acc[i][j][e] = 0.f;

    int a_row = mw*64 + (lane & 15);
    int a_col8 = (lane >> 4) * 8;
    int b_row = nw*32 + (lane >> 4)*8 + (lane & 7);
    int b_col8 = ((lane >> 3) & 1) * 8;

    int ld_row = tid >> 2, ld_c = tid & 3;          // 256 threads cover rows 0..63? no:
    // 512 slots per array per chunk -> 2 per thread
    const int NCH = K / 32;

    // issue loads for a chunk into a stage
    auto issue = [&](int ch, int stage) {
        int k0 = ch * 32;
        uint32_t base = sb + stage * GS_STAGE;
        #pragma unroll
        for (int i = 0; i < 2; i++) {
            int slot = tid + i*256;
            int row = slot >> 2, c = slot & 3;
            uint32_t so = (uint32_t)(row*APAD + c*8) * 2;
            size_t src = (size_t)row*K + k0 + c*8;
            cp_async16(base + 0     + so, Ah0 + src);
            cp_async16(base + 10240 + so, Al0 + src);
            cp_async16(base + 20480 + so, Bh0 + src);
            cp_async16(base + 30720 + so, Bl0 + src);
        }
    };

    issue(0, 0); CP_COMMIT();
    for (int ch = 0; ch < NCH; ch++) {
        int stage = ch & 1;
        if (ch + 1 < NCH) { issue(ch + 1, stage ^ 1); CP_COMMIT(); CP_WAIT1(); }
        else CP_WAIT0();
        __syncthreads();
        uint32_t aA = sb + stage * GS_STAGE;
        uint32_t aAl2 = aA + 10240, aB = aA + 20480, aBl2 = aA + 30720;
        #pragma unroll
        for (int k16 = 0; k16 < 2; k16++) {
            uint32_t bh[4][2], bl[4][2];
            #pragma unroll
            for (int half = 0; half < 2; half++) {
                uint32_t off = (uint32_t)((b_row + half*16)*APAD + k16*16 + b_col8) * 2;
                uint32_t r0, r1, r2, r3;
                LDSM4(r0, r1, r2, r3, aB + off);
                bh[half*2+0][0] = r0; bh[half*2+0][1] = r1;
                bh[half*2+1][0] = r2; bh[half*2+1][1] = r3;
                LDSM4(r0, r1, r2, r3, aBl2 + off);
                bl[half*2+0][0] = r0; bl[half*2+0][1] = r1;
                bl[half*2+1][0] = r2; bl[half*2+1][1] = r3;
            }
            #pragma unroll
            for (int mt = 0; mt < 4; mt++) {
                uint32_t ah[4], al[4];
                uint32_t off = (uint32_t)((a_row + mt*16)*APAD + k16*16 + a_col8) * 2;
                LDSM4(ah[0], ah[1], ah[2], ah[3], aA + off);
                LDSM4(al[0], al[1], al[2], al[3], aAl2 + off);
                #pragma unroll
                for (int nt = 0; nt < 4; nt++) {
                    MMA_BF16(acc[mt][nt], ah, bh[nt]);
                    MMA_BF16(acc[mt][nt], ah, bl[nt]);
                    MMA_BF16(acc[mt][nt], al, bh[nt]);
                }
            }
        }
        __syncthreads();
    }
    (void)ld_row; (void)ld_c;

    #pragma unroll
    for (int mt = 0; mt < 4; mt++) {
        int mA = m0 + mw*64 + mt*16 + (lane >> 2);
        int mB = mA + 8;
        float* dA = C + (size_t)mA * N;
        float* dB = C + (size_t)mB * N;
        #pragma unroll
        for (int nt = 0; nt < 4; nt++) {
            int n = n0 + nw*32 + nt*8 + (lane & 3)*2;
            float b0 = 0.f, b1 = 0.f;
            if (bias) { b0 = bias[n]; b1 = bias[n+1]; }
            float v0 = acc[mt][nt][0] + b0, v1 = acc[mt][nt][1] + b1;
            float v2 = acc[mt][nt][2] + b0, v3 = acc[mt][nt][3] + b1;
            if (ACT == 1) { v0 = tanhf(v0); v1 = tanhf(v1); v2 = tanhf(v2); v3 = tanhf(v3); }
            *(float2*)&dA[n] = make_float2(v0, v1);
            *(float2*)&dB[n] = make_float2(v2, v3);
        }
    }
}

// ============ HMMA diff-square GEMM, full-N tile, pipelined ============
// MODE 0: A = (X*inv - Y)^2, fused row-l2norm, scatter into out
// MODE 1: A = (X - Yv[z])^2, raw -> simpar
template<int MODE>
__global__ void __launch_bounds__(256)
hmma_diffsq(const float* __restrict__ X, const float* __restrict__ Y,
            const float* __restrict__ rowinv,
            const __nv_bfloat16* __restrict__ Bh, const __nv_bfloat16* __restrict__ Bl,
            const float* __restrict__ bias, float* __restrict__ outp)
{
    extern __shared__ char smem[];
    uint32_t sb = smem_u32(smem);
    float* sred = (float*)(smem + DS_RED);   // [4][64]
    float* sinv = (float*)(smem + DS_INV);   // [64]
    int tid = threadIdx.x;
    int lane = tid & 31, warp = tid >> 5;
    int mw = warp >> 2, nw = warp & 3;
    int m0 = blockIdx.x * 128, z = blockIdx.y;

    const float* Xp = (MODE == 0) ? X + ((size_t)z*2304 + m0)*ND : X + (size_t)m0*ND;
    const float* Yp = (MODE == 0) ? Y + (size_t)m0*ND : Y + (size_t)z*ND;
    const float* invp = (MODE == 0) ? rowinv + (size_t)z*2304 + m0 : nullptr;

    float acc[4][8][4];
    #pragma unroll
    for (int i = 0; i < 4; i++)
        #pragma unroll
        for (int j = 0; j < 8; j++)
            #pragma unroll
            for (int e = 0; e < 4; e++) acc[i][j][e] = 0.f;

    int a_row = mw*64 + (lane & 15);
    int a_col8 = (lane >> 4) * 8;
    int b_row = nw*64 + (lane >> 4)*8 + (lane & 7);
    int b_col8 = ((lane >> 3) & 1) * 8;

    // per-thread A slots: 4 x (row, q); rows chunk-invariant
    int arow[4], aq[4];
    float ivr[4];
    #pragma unroll
    for (int i = 0; i < 4; i++) {
        int slot = tid + i*256;
        arow[i] = slot >> 3; aq[i] = slot & 7;
        ivr[i] = (MODE == 0) ? invp[arow[i]] : 1.f;
    }

    float4 xr[4], yr[4];
    auto load_regs = [&](int ch) {
        int k0 = ch * 32;
        #pragma unroll
        for (int i = 0; i < 4; i++) {
            size_t off = (size_t)arow[i]*ND + k0 + aq[i]*4;
            xr[i] = *(const float4*)(Xp + off);
            if (MODE == 0) yr[i] = *(const float4*)(Yp + off);
            else           yr[i] = *(const float4*)(Yp + k0 + aq[i]*4);
        }
    };
    auto issueB = [&](int ch, int stage) {
        int k0 = ch * 32;
        uint32_t bh = sb + DS_BH + stage*20480;
        uint32_t bl = sb + DS_BL + stage*20480;
        #pragma unroll
        for (int i = 0; i < 4; i++) {
            int slot = tid + i*256;
            int row = slot >> 2, c = slot & 3;
            uint32_t so = (uint32_t)(row*APAD + c*8) * 2;
            size_t src = (size_t)row*ND + k0 + c*8;
            cp_async16(bh + so, Bh + src);
            cp_async16(bl + so, Bl + src);
        }
    };

    load_regs(0);
    issueB(0, 0); CP_COMMIT();

    for (int ch = 0; ch < 32; ch++) {
        int stage = ch & 1;
        // ---- convert current regs -> sA ----
        #pragma unroll
        for (int i = 0; i < 4; i++) {
            float iv = ivr[i];
            float d0, d1, d2, d3;
            if (MODE == 0) {
                d0 = xr[i].x*iv - yr[i].x; d1 = xr[i].y*iv - yr[i].y;
                d2 = xr[i].z*iv - yr[i].z; d3 = xr[i].w*iv - yr[i].w;
            } else {
                d0 = xr[i].x - yr[i].x; d1 = xr[i].y - yr[i].y;
                d2 = xr[i].z - yr[i].z; d3 = xr[i].w - yr[i].w;
            }
            float a0 = d0*d0, a1 = d1*d1, a2 = d2*d2, a3 = d3*d3;
            __nv_bfloat162 h01 = __floats2bfloat162_rn(a0, a1);
            __nv_bfloat162 h23 = __floats2bfloat162_rn(a2, a3);
            float r0 = a0 - __bfloat162float(h01.x);
            float r1 = a1 - __bfloat162float(h01.y);
            float r2 = a2 - __bfloat162float(h23.x);
            float r3 = a3 - __bfloat162float(h23.y);
            __nv_bfloat162 l01 = __floats2bfloat162_rn(r0, r1);
            __nv_bfloat162 l23 = __floats2bfloat162_rn(r2, r3);
            uint32_t so = (uint32_t)(arow[i]*APAD + aq[i]*4) * 2;
            *(uint2*)(smem + DS_AH + so) = make_uint2(*(uint32_t*)&h01, *(uint32_t*)&h23);
            *(uint2*)(smem + DS_AL + so) = make_uint2(*(uint32_t*)&l01, *(uint32_t*)&l23);
        }
        // ---- prefetch next chunk ----
        if (ch < 31) {
            load_regs(ch + 1);                       // LDG latency hidden by MMA below
            issueB(ch + 1, stage ^ 1); CP_COMMIT();
            CP_WAIT1();
        } else {
            CP_WAIT0();
        }
        __syncthreads();
        // ---- MMA on stage ----
        uint32_t aAh = sb + DS_AH, aAl = sb + DS_AL;
        uint32_t aBh = sb + DS_BH + stage*20480;
        uint32_t aBl = sb + DS_BL + stage*20480;
        #pragma unroll
        for (int k16 = 0; k16 < 2; k16++) {
            uint32_t bh[8][2], bl[8][2];
            #pragma unroll
            for (int p = 0; p < 4; p++) {
                uint32_t off = (uint32_t)((b_row + p*16)*APAD + k16*16 + b_col8) * 2;
                uint32_t r0, r1, r2, r3;
                LDSM4(r0, r1, r2, r3, aBh + off);
                bh[p*2+0][0] = r0; bh[p*2+0][1] = r1;
                bh[p*2+1][0] = r2; bh[p*2+1][1] = r3;
                LDSM4(r0, r1, r2, r3, aBl + off);
                bl[p*2+0][0] = r0; bl[p*2+0][1] = r1;
                bl[p*2+1][0] = r2; bl[p*2+1][1] = r3;
            }
            #pragma unroll
            for (int mt = 0; mt < 4; mt++) {
                uint32_t ah[4], al[4];
                uint32_t off = (uint32_t)((a_row + mt*16)*APAD + k16*16 + a_col8) * 2;
                LDSM4(ah[0], ah[1], ah[2], ah[3], aAh + off);
                LDSM4(al[0], al[1], al[2], al[3], aAl + off);
                #pragma unroll
                for (int nt = 0; nt < 8; nt++) {
                    MMA_BF16(acc[mt][nt], ah, bh[nt]);
                    MMA_BF16(acc[mt][nt], ah, bl[nt]);
                    MMA_BF16(acc[mt][nt], al, bh[nt]);
                }
            }
        }
        __syncthreads();
    }

    // ---- epilogue ----
    #pragma unroll
    for (int mt = 0; mt < 4; mt++) {
        int lmA = mw*64 + mt*16 + (lane >> 2);
        int lmB = lmA + 8;
        int mA = m0 + lmA, mB = m0 + lmB;
        float vA[8][2], vB[8][2];
        float ssqA = 0.f, ssqB = 0.f;
        #pragma unroll
        for (int nt = 0; nt < 8; nt++) {
            int n = nw*64 + nt*8 + (lane & 3)*2;
            float b0 = bias[n], b1 = bias[n+1];
            vA[nt][0] = fmaxf(acc[mt][nt][0] + b0, 0.f);
            vA[nt][1] = fmaxf(acc[mt][nt][1] + b1, 0.f);
            vB[nt][0] = fmaxf(acc[mt][nt][2] + b0, 0.f);
            vB[nt][1] = fmaxf(acc[mt][nt][3] + b1, 0.f);
            if (MODE == 0) {
                ssqA += vA[nt][0]*vA[nt][0] + vA[nt][1]*vA[nt][1];
                ssqB += vB[nt][0]*vB[nt][0] + vB[nt][1]*vB[nt][1];
            }
        }
        float invA = 1.f, invB = 1.f;
        if (MODE == 0) {
            ssqA += __shfl_xor_sync(0xffffffffu, ssqA, 1);
            ssqA += __shfl_xor_sync(0xffffffffu, ssqA, 2);
            ssqB += __shfl_xor_sync(0xffffffffu, ssqB, 1);
            ssqB += __shfl_xor_sync(0xffffffffu, ssqB, 2);
            if ((lane & 3) == 0) {
                sred[nw*64 + mw*32 + (lane >> 2)] = ssqA;
                sred[nw*64 + mw*32 + 16 + (lane >> 2)] = ssqB;
            }
            __syncthreads();
            if (tid < 64) {
                float s = sred[0*64 + tid] + sred[1*64 + tid] + sred[2*64 + tid] + sred[3*64 + tid];
                sinv[tid] = 1.f / (sqrtf(s) + EPSL);
            }
            __syncthreads();
            invA = sinv[mw*32 + (lane >> 2)];
            invB = sinv[mw*32 + 16 + (lane >> 2)];
        }
        float* dA;
        float* dB;
        if (MODE == 0) {
            int bA = mA / NR, rA2 = mA % NR;
            int bB = mB / NR, rB2 = mB % NR;
            dA = outp + (((size_t)z*NB + bA)*37 + 1 + rA2)*NS;
            dB = outp + (((size_t)z*NB + bB)*37 + 1 + rB2)*NS;
        } else {
            dA = outp + ((size_t)z*2304 + mA)*NS;
            dB = outp + ((size_t)z*2304 + mB)*NS;
        }
        #pragma unroll
        for (int nt = 0; nt < 8; nt++) {
            int n = nw*64 + nt*8 + (lane & 3)*2;
            *(float2*)&dA[n] = make_float2(vA[nt][0]*invA, vA[nt][1]*invA);
            *(float2*)&dB[n] = make_float2(vB[nt][0]*invB, vB[nt][1]*invB);
        }
        if (MODE == 0) __syncthreads();
    }
}

// ============ small-M GEMM via split-K ============
__global__ void gemm_small_part(const float* __restrict__ A, const float* __restrict__ W,
                                float* __restrict__ part, int M, int N, int K)
{
    const int BK = 16;
    __shared__ float As[BK][64];
    __shared__ float Bs[BK][64];
    int tid = threadIdx.x, tr = tid >> 4, tc = tid & 15;
    int n0 = blockIdx.x * 64;
    int KS = gridDim.y;
    int Kc = K / KS;
    int kz = blockIdx.y;
    float acc[4][4] = {};
    for (int k0 = kz*Kc; k0 < (kz+1)*Kc; k0 += BK) {
        for (int i = tid; i < 64*BK; i += 256) {
            int m = i >> 4, k = i & 15;
            As[k][m] = (m < M) ? A[(size_t)m*K + k0 + k] : 0.f;
        }
        for (int i = tid; i < BK*64; i += 256) {
            int k = i >> 6, n = i & 63;
            Bs[k][n] = W[(size_t)(k0+k)*N + n0 + n];
        }
        __syncthreads();
        #pragma unroll
        for (int k = 0; k < BK; k++) {
            float a[4], b[4];
            #pragma unroll
            for (int i = 0; i < 4; i++) a[i] = As[k][tr*4+i];
            #pragma unroll
            for (int j = 0; j < 4; j++) b[j] = Bs[k][tc*4+j];
            #pragma unroll
            for (int i = 0; i < 4; i++)
                #pragma unroll
                for (int j = 0; j < 4; j++) acc[i][j] += a[i]*b[j];
        }
        __syncthreads();
    }
    #pragma unroll
    for (int i = 0; i < 4; i++) {
        int m = tr*4 + i;
        if (m >= M) continue;
        #pragma unroll
        for (int j = 0; j < 4; j++)
            part[((size_t)kz*M + m)*N + n0 + tc*4 + j] = acc[i][j];
    }
}

template<int ACT>
__global__ void k_small_epi(const float* __restrict__ part, const float* __restrict__ bias,
                            float* __restrict__ C, int M, int N, int KS)
{
    int idx = blockIdx.x*256 + threadIdx.x;
    if (idx >= M*N) return;
    int n = idx % N;
    float s = 0.f;
    for (int kz = 0; kz < KS; kz++) s += part[(size_t)kz*M*N + idx];
    s += bias[n];
    if (ACT == 1) s = tanhf(s);
    C[idx] = s;
}

// ---------------- tiny glo diff-square GEMM ----------------
__global__ void gemm_diffsq_glo(const float* __restrict__ X, const float* __restrict__ Y,
                                const float* __restrict__ W, const float* __restrict__ bias,
                                float* __restrict__ Cbase, int M, int N, int K)
{
    const int BM = 64, BN = 64, BK = 16;
    int c = blockIdx.z;
    const float* Yp = Y + (size_t)c*K;
    __shared__ float As[BK][BM];
    __shared__ float Bs[BK][BN];
    int tid = threadIdx.x;
    int tr = tid >> 4, tc = tid & 15;
    int m0 = blockIdx.y * BM, n0 = blockIdx.x * BN;
    float acc[4][4] = {};
    for (int k0 = 0; k0 < K; k0 += BK) {
        #pragma unroll
        for (int i = tid; i < BM*BK; i += 256) {
            int m = i >> 4, k = i & 15;
            float v = 0.f;
            if (m0 + m < M) {
                float d = X[(size_t)(m0+m)*K + k0 + k] - Yp[k0 + k];
                v = d * d;
            }
            As[k][m] = v;
        }
        #pragma unroll
        for (int i = tid; i < BK*BN; i += 256) {
            int k = i >> 6, n = i & 63;
            Bs[k][n] = W[(size_t)(k0+k)*N + n0 + n];
        }
        __syncthreads();
        #pragma unroll
        for (int k = 0; k < BK; k++) {
            float a[4], b[4];
            #pragma unroll
            for (int i = 0; i < 4; i++) a[i] = As[k][tr*4+i];
            #pragma unroll
            for (int j = 0; j < 4; j++) b[j] = Bs[k][tc*4+j];
            #pragma unroll
            for (int i = 0; i < 4; i++)
                #pragma unroll
                for (int j = 0; j < 4; j++) acc[i][j] += a[i]*b[j];
        }
        __syncthreads();
    }
    #pragma unroll
    for (int i = 0; i < 4; i++) {
        int m = m0 + tr*4 + i;
        if (m >= M) continue;
        #pragma unroll
        for (int j = 0; j < 4; j++) {
            int n = n0 + tc*4 + j;
            float v = fmaxf(acc[i][j] + bias[n], 0.f);
            Cbase[(size_t)c*M*N + (size_t)m*N + n] = v;
        }
    }
}

// ---------------- small kernels ----------------
__global__ void k_imgave(const float* __restrict__ img) {
    int i = blockIdx.x*blockDim.x + threadIdx.x;
    int b = i >> 10, d = i & 1023;
    float s = 0.f;
    for (int r = 0; r < NR; r++) s += img[((size_t)b*NR + r)*ND + d];
    g_imgave[i] = s * (1.f / NR);
}

__global__ void k_bnstats() {
    int r = blockIdx.x;
    __shared__ float red[256], red2[256];
    float s = 0.f, ss = 0.f;
    for (int i = threadIdx.x; i < NB*ND; i += 256) {
        int b = i >> 10, d = i & 1023;
        float v = g_h[((size_t)b*NR + r)*ND + d];
        s += v; ss += v*v;
    }
    red[threadIdx.x] = s; red2[threadIdx.x] = ss; __syncthreads();
    for (int st = 128; st > 0; st >>= 1) {
        if (threadIdx.x < st) { red[threadIdx.x] += red[threadIdx.x+st]; red2[threadIdx.x] += red2[threadIdx.x+st]; }
        __syncthreads();
    }
    if (threadIdx.x == 0) {
        float mu = red[0] / (float)(NB*ND);
        g_bnmu[r] = mu;
        g_bnvar[r] = red2[0] / (float)(NB*ND) - mu*mu;
    }
}

__global__ void k_gbn(const float* __restrict__ gamma, const float* __restrict__ beta) {
    int d = blockIdx.x*blockDim.x + threadIdx.x;
    float s = 0.f, ss = 0.f;
    for (int b = 0; b < NB; b++) { float v = g_g[(size_t)b*ND + d]; s += v; ss += v*v; }
    float mu = s / NB;
    float var = ss / NB - mu*mu;
    float inv = rsqrtf(var + BNEPS);
    float ga = gamma[d], be = beta[d];
    for (int b = 0; b < NB; b++) {
        float v = g_g[(size_t)b*ND + d];
        g_g[(size_t)b*ND + d] = tanhf((v - mu)*inv*ga + be);
    }
}

__global__ void k_wraw(const float* __restrict__ vcw, const float* __restrict__ vcb,
                       const float* __restrict__ lg, const float* __restrict__ lb) {
    int br = blockIdx.x;
    int b = br / NR, r = br % NR;
    __shared__ float red[256];
    float mu = g_bnmu[r], inv = rsqrtf(g_bnvar[r] + BNEPS);
    float ga = lg[r], be = lb[r];
    float s = 0.f;
    for (int d = threadIdx.x; d < ND; d += 256) {
        float le = tanhf((g_h[(size_t)br*ND + d] - mu)*inv*ga + be);
        s += le * g_g[(size_t)b*ND + d] * vcw[d];
    }
    float tot = blockReduceSum256(s, red);
    if (threadIdx.x == 0) g_wraw[br] = tot + vcb[0];
}

__global__ void k_newglobal(const float* __restrict__ img) {
    int b = blockIdx.x;
    __shared__ float w[NR];
    __shared__ float red[256];
    __shared__ float invn;
    if (threadIdx.x == 0) {
        float mx = -1e30f;
        for (int r = 0; r < NR; r++) mx = fmaxf(mx, g_wraw[b*NR + r]);
        float sum = 0.f;
        for (int r = 0; r < NR; r++) { w[r] = expf(g_wraw[b*NR + r] - mx); sum += w[r]; }
        float is = 1.f / sum;
        for (int r = 0; r < NR; r++) w[r] *= is;
    }
    __syncthreads();
    float ssq = 0.f;
    for (int d = threadIdx.x; d < ND; d += 256) {
        float s = 0.f;
        for (int r = 0; r < NR; r++) s += w[r] * img[((size_t)b*NR + r)*ND + d];
        g_imgglo[(size_t)b*ND + d] = s;
        ssq += s*s;
    }
    float tot = blockReduceSum256(ssq, red);
    if (threadIdx.x == 0) {
        float nrm = sqrtf(tot) + EPSL;
        g_normglo[b] = nrm;
        invn = 1.f / nrm;
    }
    __syncthreads();
    for (int d = threadIdx.x; d < ND; d += 256) g_imgglo[(size_t)b*ND + d] *= invn;
}

__global__ void k_imgpar(const float* __restrict__ img, const int* __restrict__ adjs) {
    int br = blockIdx.x;
    int b = br / NR, r = br % NR;
    __shared__ int eff[NPART];
    __shared__ float wg[NPART];
    if (threadIdx.x == 0) {
        int cnt = 0;
        const int* row = adjs + (size_t)b*NR*NR + (size_t)r*NR;
        for (int j = 0; j < NR && cnt < NPART; j++)
            if (row[j] == 1) eff[cnt++] = j;
        for (; cnt < NPART; cnt++) eff[cnt] = r;
        float v[NPART], mx = -1e30f;
        for (int k = 0; k < NPART; k++) { v[k] = g_wraw[b*NR + eff[k]]; mx = fmaxf(mx, v[k]); }
        float sum = 0.f;
        for (int k = 0; k < NPART; k++) { v[k] = expf(v[k] - mx); sum += v[k]; }
        float is = 1.f / sum;
        for (int k = 0; k < NPART; k++) wg[k] = v[k]*is;
    }
    __syncthreads();
    float invn = 1.f / g_normglo[b];
    for (int d = threadIdx.x; d < ND; d += 256) {
        float s = 0.f;
        #pragma unroll
        for (int k = 0; k < NPART; k++) s += wg[k] * img[((size_t)b*NR + eff[k])*ND + d];
        g_imgpar[(size_t)br*ND + d] = s * invn;
    }
}

__global__ void k_capave(const float* __restrict__ cap) {
    int i = blockIdx.x*blockDim.x + threadIdx.x;
    int c = i >> 10, d = i & 1023;
    float s = 0.f;
    for (int n = 0; n < NWD; n++) s += cap[((size_t)c*NWD + n)*ND + d];
    g_capave[i] = s * (1.f / NWD);
}

__global__ void k_capglo(const float* __restrict__ cap, const float* __restrict__ tsacw,
                         const float* __restrict__ tsacb) {
    int c = blockIdx.x;
    __shared__ float red[256];
    __shared__ float cw[NWD];
    __shared__ float invn;
    float gw[4];
    #pragma unroll
    for (int i = 0; i < 4; i++) {
        int d = threadIdx.x + i*256;
        gw[i] = g_ge[(size_t)c*ND + d] * tsacw[d];
    }
    for (int n = 0; n < NWD; n++) {
        float s = 0.f;
        #pragma unroll
        for (int i = 0; i < 4; i++) {
            int d = threadIdx.x + i*256;
            s += g_le[((size_t)c*NWD + n)*ND + d] * gw[i];
        }
        float tot = blockReduceSum256(s, red);
        if (threadIdx.x == 0) cw[n] = tot + tsacb[0];
    }
    __syncthreads();
    if (threadIdx.x == 0) {
        float mx = -1e30f;
        for (int n = 0; n < NWD; n++) mx = fmaxf(mx, cw[n]);
        float sum = 0.f;
        for (int n = 0; n < NWD; n++) { cw[n] = expf(cw[n] - mx); sum += cw[n]; }
        float is = 1.f / sum;
        for (int n = 0; n < NWD; n++) cw[n] *= is;
    }
    __syncthreads();
    float ssq = 0.f;
    #pragma unroll
    for (int i = 0; i < 4; i++) {
        int d = threadIdx.x + i*256;
        float s = 0.f;
        for (int n = 0; n < NWD; n++) s += cw[n] * cap[((size_t)c*NWD + n)*ND + d];
        g_capglo[(size_t)c*ND + d] = s;
        ssq += s*s;
    }
    float tot = blockReduceSum256(ssq, red);
    if (threadIdx.x == 0) invn = 1.f / (sqrtf(tot) + EPSL);
    __syncthreads();
    #pragma unroll
    for (int i = 0; i < 4; i++) {
        int d = threadIdx.x + i*256;
        g_capglo[(size_t)c*ND + d] *= invn;
    }
}

__global__ void k_attnfuse() {
    int cb = blockIdx.x;
    int c = cb / NB, b = cb % NB;
    __shared__ float sA[NWD*NR];
    __shared__ float nrm[NWD];
    const float* raw = g_attnraw + (size_t)c*NWD*NB*NR;
    for (int i = threadIdx.x; i < NWD*NR; i += 256) {
        int n = i / NR, r = i % NR;
        float v = raw[(size_t)n*NB*NR + (size_t)b*NR + r];
        v = (v > 0.f) ? v : 0.1f*v;
        sA[i] = v;
    }
    __syncthreads();
    if (threadIdx.x < NWD) {
        int n = threadIdx.x;
        float s = 0.f;
        for (int r = 0; r < NR; r++) { float v = sA[n*NR + r]; s += v*v; }
        nrm[n] = 1.f / (sqrtf(s) + EPSL);
    }
    __syncthreads();
    if (threadIdx.x < NR) {
        int r = threadIdx.x;
        float vals[NWD];
        float mx = -1e30f;
        for (int n = 0; n < NWD; n++) {
            float v = SMOOTHF * sA[n*NR + r] * nrm[n];
            vals[n] = v;
            mx = fmaxf(mx, v);
        }
        float sum = 0.f;
        for (int n = 0; n < NWD; n++) { vals[n] = expf(vals[n] - mx); sum += vals[n]; }
        float is = 1.f / sum;
        float* outp = g_attnT + ((size_t)cb*NR + r)*NWD;
        for (int n = 0; n < NWD; n++) outp[n] = vals[n]*is;
    }
}

__global__ void k_ctx(const float* __restrict__ cap) {
    int cb = blockIdx.x;
    int c = cb / NB;
    __shared__ float sT[NR*NWD];
    const float* at = g_attnT + (size_t)cb*NR*NWD;
    for (int i = threadIdx.x; i < NR*NWD; i += 256) sT[i] = at[i];
    __syncthreads();
    float* outp = g_ctx + (size_t)cb*NR*ND;
    for (int it = 0; it < 4; it++) {
        int d = threadIdx.x + it*256;
        float acc[NR];
        #pragma unroll
        for (int r = 0; r < NR; r++) acc[r] = 0.f;
        for (int n = 0; n < NWD; n++) {
            float cv = cap[((size_t)c*NWD + n)*ND + d];
            #pragma unroll
            for (int r = 0; r < NR; r++) acc[r] += sT[r*NWD + n] * cv;
        }
        for (int r = 0; r < NR; r++) outp[(size_t)r*ND + d] = acc[r];
    }
}

__global__ void k_ctxssq() {
    int row = blockIdx.x * 8 + (threadIdx.x >> 5);
    int lane = threadIdx.x & 31;
    const float* p = g_ctx + (size_t)row * ND;
    float s = 0.f;
    #pragma unroll
    for (int i = 0; i < 8; i++) {
        float4 v = *(const float4*)(p + lane*4 + i*128);
        s += v.x*v.x + v.y*v.y + v.z*v.z + v.w*v.w;
    }
    s = warpReduceSum(s);
    if (lane == 0) g_ctxinv[row] = 1.f / (sqrtf(s) + EPSL);
}

__global__ void k_rownorm(float* __restrict__ X, int L) {
    size_t row = blockIdx.x;
    float* p = X + row*(size_t)L;
    __shared__ float red[256];
    __shared__ float invn;
    float s = 0.f;
    for (int i = threadIdx.x; i < L; i += 256) { float v = p[i]; s += v*v; }
    float tot = blockReduceSum256(s, red);
    if (threadIdx.x == 0) invn = 1.f / (sqrtf(tot) + EPSL);
    __syncthreads();
    for (int i = threadIdx.x; i < L; i += 256) p[i] *= invn;
}

// finalize: warp-parallel over r, simpar row-norm fused
__global__ void k_finalize(const float* __restrict__ simw, const float* __restrict__ simb,
                           const float* __restrict__ lng, const float* __restrict__ lnb,
                           float* __restrict__ out, size_t out2off) {
    int cb = blockIdx.x;
    int tid = threadIdx.x;
    int lane = tid & 31, warp = tid >> 5;
    const float* sg = out + out2off + (size_t)cb*NS;
    __shared__ float sSgw[NS];
    __shared__ float wv[NR];
    __shared__ float mv[2];
    float sgv = sg[tid];
    sSgw[tid] = sgv * simw[tid];
    __syncthreads();
    const float* sp = g_simpar + (size_t)cb*NR*NS;
    for (int r = warp; r < NR; r += 8) {
        const float* row = sp + (size_t)r*NS;
        float dot = 0.f, ss = 0.f;
        #pragma unroll
        for (int i = 0; i < 8; i++) {
            int c = lane + i*32;
            float v = row[c];
            dot += v * sSgw[c];
            ss += v * v;
        }
        dot = warpReduceSum(dot);
        ss = warpReduceSum(ss);
        if (lane == 0) wv[r] = dot / (sqrtf(ss) + EPSL) + simb[0];
    }
    __syncthreads();
    if (tid == 0) {
        float m = 0.f;
        for (int r = 0; r < NR; r++) m += wv[r];
        m /= NR;
        float v = 0.f;
        for (int r = 0; r < NR; r++) { float d = wv[r] - m; v += d*d; }
        v /= NR;
        mv[0] = m; mv[1] = rsqrtf(v + LNEPS);
    }
    __syncthreads();
    if (tid < NR) {
        int r = tid;
        float z = (wv[r] - mv[0])*mv[1]*lng[r] + lnb[r];
        wv[r] = 1.f / (1.f + expf(-z));
    }
    __syncthreads();
    float* ob = out + (size_t)cb*37*NS;
    ob[tid] = sgv;
    for (int r = 0; r < NR; r++) ob[(size_t)(1+r)*NS + tid] *= wv[r];
}

// ---------------- host ----------------
extern "C" void kernel_launch(void* const* d_in, const int* in_sizes, int n_in,
                              void* d_out, int out_size) {
    (void)in_sizes; (void)n_in; (void)out_size;
    const float* img    = (const float*)d_in[0];
    const float* cap    = (const float*)d_in[1];
    const int*   adjs   = (const int*)d_in[3];
    const float* tsa_lw = (const float*)d_in[5];
    const float* tsa_lb = (const float*)d_in[6];
    const float* tsa_gw = (const float*)d_in[7];
    const float* tsa_gb = (const float*)d_in[8];
    const float* tsa_cw = (const float*)d_in[9];
    const float* tsa_cb = (const float*)d_in[10];
    const float* vl_w   = (const float*)d_in[11];
    const float* vl_b   = (const float*)d_in[12];
    const float* vbn_lg = (const float*)d_in[13];
    const float* vbn_lb = (const float*)d_in[14];
    const float* vg_w   = (const float*)d_in[15];
    const float* vg_b   = (const float*)d_in[16];
    const float* vbn_gg = (const float*)d_in[17];
    const float* vbn_gb = (const float*)d_in[18];
    const float* vc_w   = (const float*)d_in[19];
    const float* vc_b   = (const float*)d_in[20];
    const float* loc_w  = (const float*)d_in[21];
    const float* loc_b  = (const float*)d_in[22];
    const float* par_w  = (const float*)d_in[23];
    const float* par_b  = (const float*)d_in[24];
    const float* glo_w  = (const float*)d_in[25];
    const float* glo_b  = (const float*)d_in[26];
    const float* sim_w  = (const float*)d_in[27];
    const float* sim_b  = (const float*)d_in[28];
    const float* ln_g   = (const float*)d_in[29];
    const float* ln_b   = (const float*)d_in[30];
    float* out = (float*)d_out;

    static bool inited = false;
    static float *p_h, *p_imgave, *p_g, *p_ge, *p_le, *p_attnraw,
                 *p_ctx, *p_ctxinv, *p_imgpar, *p_imgglo, *p_capglo, *p_simpar, *p_part, *p_capave;
    static __nv_bfloat16 *p_wth, *p_wtl, *p_imgh, *p_imgl, *p_caph, *p_capl, *p_wbh, *p_wbl;
    if (!inited) {
        cudaGetSymbolAddress((void**)&p_h, g_h);
        cudaGetSymbolAddress((void**)&p_imgave, g_imgave);
        cudaGetSymbolAddress((void**)&p_g, g_g);
        cudaGetSymbolAddress((void**)&p_ge, g_ge);
        cudaGetSymbolAddress((void**)&p_le, g_le);
        cudaGetSymbolAddress((void**)&p_attnraw, g_attnraw);
        cudaGetSymbolAddress((void**)&p_ctx, g_ctx);
        cudaGetSymbolAddress((void**)&p_ctxinv, g_ctxinv);
        cudaGetSymbolAddress((void**)&p_imgpar, g_imgpar);
        cudaGetSymbolAddress((void**)&p_imgglo, g_imgglo);
        cudaGetSymbolAddress((void**)&p_capglo, g_capglo);
        cudaGetSymbolAddress((void**)&p_simpar, g_simpar);
        cudaGetSymbolAddress((void**)&p_part, g_part);
        cudaGetSymbolAddress((void**)&p_capave, g_capave);
        cudaGetSymbolAddress((void**)&p_wth, g_wth);
        cudaGetSymbolAddress((void**)&p_wtl, g_wtl);
        cudaGetSymbolAddress((void**)&p_imgh, g_imgh);
        cudaGetSymbolAddress((void**)&p_imgl, g_imgl);
        cudaGetSymbolAddress((void**)&p_caph, g_caph);
        cudaGetSymbolAddress((void**)&p_capl, g_capl);
        cudaGetSymbolAddress((void**)&p_wbh, g_wbh);
        cudaGetSymbolAddress((void**)&p_wbl, g_wbl);
        cudaFuncSetAttribute(hmma_gemm<0>, cudaFuncAttributeMaxDynamicSharedMemorySize, GS_TOTAL);
        cudaFuncSetAttribute(hmma_gemm<1>, cudaFuncAttributeMaxDynamicSharedMemorySize, GS_TOTAL);
        cudaFuncSetAttribute(hmma_diffsq<0>, cudaFuncAttributeMaxDynamicSharedMemorySize, DS_TOTAL);
        cudaFuncSetAttribute(hmma_diffsq<1>, cudaFuncAttributeMaxDynamicSharedMemorySize, DS_TOTAL);
        inited = true;
    }

    const size_t out2off = (size_t)NCAP*NB*37*NS;
    float* out2 = out + out2off;

    // ---- operand splits ----
    k_split<<<(NB*NR*ND+255)/256, 256>>>(img, p_imgh, p_imgl, NB*NR*ND);
    k_split<<<(NCAP*NWD*ND+255)/256, 256>>>(cap, p_caph, p_capl, NCAP*NWD*ND);
    k_wsplitT<<<(ND*ND+255)/256, 256>>>(vl_w,   p_wbh,         p_wbl,         ND, ND);
    k_wsplitT<<<(ND*ND+255)/256, 256>>>(tsa_lw, p_wbh + ND*ND, p_wbl + ND*ND, ND, ND);
    k_wsplitT<<<(NS*ND+255)/256, 256>>>(loc_w,  p_wth,         p_wtl,         NS, ND);
    k_wsplitT<<<(NS*ND+255)/256, 256>>>(par_w,  p_wth + NS*ND, p_wtl + NS*ND, NS, ND);

    // ---- caption-independent ----
    k_imgave<<<256, 256>>>(img);
    hmma_gemm<0><<<dim3(8, 18), 256, GS_TOTAL>>>(p_imgh, p_imgl, p_wbh, p_wbl, vl_b, p_h, ND, ND);
    k_bnstats<<<NR, 256>>>();
    gemm_small_part<<<dim3(16, 8), 256>>>(p_imgave, vg_w, p_part, NB, ND, ND);
    k_small_epi<0><<<(NB*ND+255)/256, 256>>>(p_part, vg_b, p_g, NB, ND, 8);
    k_gbn<<<4, 256>>>(vbn_gg, vbn_gb);
    k_wraw<<<NB*NR, 256>>>(vc_w, vc_b, vbn_lg, vbn_lb);
    k_newglobal<<<NB, 256>>>(img);
    k_imgpar<<<NB*NR, 256>>>(img, adjs);

    // ---- caption side ----
    k_capave<<<128, 256>>>(cap);
    hmma_gemm<1><<<dim3(8, 10), 256, GS_TOTAL>>>(p_caph, p_capl, p_wbh + ND*ND, p_wbl + ND*ND,
                                                 tsa_lb, p_le, ND, ND);
    gemm_small_part<<<dim3(16, 8), 256>>>(p_capave, tsa_gw, p_part, NCAP, ND, ND);
    k_small_epi<1><<<(NCAP*ND+255)/256, 256>>>(p_part, tsa_gb, p_ge, NCAP, ND, 8);
    k_capglo<<<NCAP, 256>>>(cap, tsa_cw, tsa_cb);

    hmma_gemm<0><<<dim3(18, 10), 256, GS_TOTAL>>>(p_caph, p_capl, p_imgh, p_imgl,
                                                  nullptr, p_attnraw, NB*NR, ND);
    k_attnfuse<<<NCAP*NB, 256>>>();
    k_ctx<<<NCAP*NB, 256>>>(cap);
    k_ctxssq<<<NCAP*NB*NR/8, 256>>>();

    // ---- heavy diff-square GEMMs (pipelined HMMA split-bf16) ----
    hmma_diffsq<0><<<dim3(18, NCAP), 256, DS_TOTAL>>>(p_ctx, img, p_ctxinv, p_wth, p_wtl, loc_b, out);
    hmma_diffsq<1><<<dim3(18, NCAP), 256, DS_TOTAL>>>(p_imgpar, p_capglo, nullptr,
                                                      p_wth + NS*ND, p_wtl + NS*ND, par_b, p_simpar);

    // sim_glo (tiny, fp32)
    gemm_diffsq_glo<<<dim3(4, 1, NCAP), 256>>>(p_imgglo, p_capglo, glo_w, glo_b, out2, NB, NS, ND);
    k_rownorm<<<NCAP*NB, 256>>>(out2, NS);

    // ---- finalize ----
    k_finalize<<<NCAP*NB, 256>>>(sim_w, sim_b, ln_g, ln_b, out, out2off);
}

// round 12
// speedup vs baseline: 5.2478x; 1.2734x over previous
#include <cuda_runtime.h>
#include <cuda_bf16.h>
#include <cstdint>
#include <stdint.h>
#include <math.h>

#define NB 64
#define NR 36
#define ND 1024
#define NCAP 32
#define NWD 40
#define NS 256
#define NPART 5
#define EPSL 1e-8f
#define BNEPS 1e-5f
#define LNEPS 1e-5f
#define SMOOTHF 9.0f

typedef unsigned long long ull;

// ---------------- scratch ----------------
__device__ float g_h[NB*NR*ND];
__device__ float g_imgave[NB*ND];
__device__ float g_bnmu[NR];
__device__ float g_bnvar[NR];
__device__ float g_g[NB*ND];
__device__ float g_wraw[NB*NR];
__device__ float g_imgglo[NB*ND];
__device__ float g_normglo[NB];
__device__ float g_imgpar[NB*NR*ND];
__device__ float g_capave[NCAP*ND];
__device__ float g_le[NCAP*NWD*ND];
__device__ float g_ge[NCAP*ND];
__device__ float g_capglo[NCAP*ND];
__device__ float g_attnraw[(size_t)NCAP*NWD*NB*NR];
__device__ float g_ctx[(size_t)NCAP*NB*NR*ND];
__device__ float g_ctxinv[NCAP*NB*NR];
__device__ float g_simpar[(size_t)NCAP*NB*NR*NS];
__device__ float g_part[8*64*1024];
__device__ __nv_bfloat16 g_wth[2][NS*ND];
__device__ __nv_bfloat16 g_wtl[2][NS*ND];
__device__ __nv_bfloat16 g_imgh[NB*NR*ND], g_imgl[NB*NR*ND];
__device__ __nv_bfloat16 g_caph[NCAP*NWD*ND], g_capl[NCAP*NWD*ND];
__device__ __nv_bfloat16 g_wbh[2][ND*ND], g_wbl[2][ND*ND];
__device__ __nv_bfloat16 g_attnTh[(size_t)NCAP*NB*NR*64], g_attnTl[(size_t)NCAP*NB*NR*64];
__device__ __nv_bfloat16 g_capTh[(size_t)NCAP*ND*64], g_capTl[(size_t)NCAP*ND*64];

// ---------------- helpers ----------------
__device__ __forceinline__ uint32_t smem_u32(const void* p) {
    uint32_t a;
    asm("{ .reg .u64 t; cvta.to.shared.u64 t, %1; cvt.u32.u64 %0, t; }" : "=r"(a) : "l"(p));
    return a;
}

__device__ __forceinline__ void cp_async16(uint32_t dst, const void* src) {
    asm volatile("cp.async.cg.shared.global [%0], [%1], 16;" :: "r"(dst), "l"(src));
}
#define CP_COMMIT() asm volatile("cp.async.commit_group;")
#define CP_WAIT0()  asm volatile("cp.async.wait_group 0;")
#define CP_WAIT1()  asm volatile("cp.async.wait_group 1;")

__device__ __forceinline__ float blockReduceSum256(float v, float* red) {
    int tid = threadIdx.x;
    red[tid] = v; __syncthreads();
    #pragma unroll
    for (int s = 128; s > 0; s >>= 1) {
        if (tid < s) red[tid] += red[tid + s];
        __syncthreads();
    }
    float r = red[0]; __syncthreads();
    return r;
}

__device__ __forceinline__ float warpReduceSum(float v) {
    v += __shfl_xor_sync(0xffffffffu, v, 16);
    v += __shfl_xor_sync(0xffffffffu, v, 8);
    v += __shfl_xor_sync(0xffffffffu, v, 4);
    v += __shfl_xor_sync(0xffffffffu, v, 2);
    v += __shfl_xor_sync(0xffffffffu, v, 1);
    return v;
}

#define LDSM4(r0, r1, r2, r3, addr) \
    asm volatile("ldmatrix.sync.aligned.m8n8.x4.shared.b16 {%0,%1,%2,%3}, [%4];" \
        : "=r"(r0), "=r"(r1), "=r"(r2), "=r"(r3) : "r"(addr))

#define MMA_BF16(d, a, b) \
    asm volatile("mma.sync.aligned.m16n8k16.row.col.f32.bf16.bf16.f32 " \
        "{%0,%1,%2,%3}, {%4,%5,%6,%7}, {%8,%9}, {%0,%1,%2,%3};" \
        : "+f"((d)[0]), "+f"((d)[1]), "+f"((d)[2]), "+f"((d)[3]) \
        : "r"((a)[0]), "r"((a)[1]), "r"((a)[2]), "r"((a)[3]), "r"((b)[0]), "r"((b)[1]))

// ---------------- split kernels ----------------
__global__ void k_split(const float* __restrict__ X, __nv_bfloat16* __restrict__ H,
                        __nv_bfloat16* __restrict__ L, int total) {
    int idx = blockIdx.x * 256 + threadIdx.x;
    if (idx >= total) return;
    float v = X[idx];
    __nv_bfloat16 h = __float2bfloat16(v);
    H[idx] = h;
    L[idx] = __float2bfloat16(v - __bfloat162float(h));
}

__global__ void k_wsplitT(const float* __restrict__ W, __nv_bfloat16* __restrict__ H,
                          __nv_bfloat16* __restrict__ L, int Ncols, int K) {
    int idx = blockIdx.x * 256 + threadIdx.x;
    if (idx >= Ncols * K) return;
    int n = idx / K, k = idx - n * K;
    float w = W[(size_t)k * Ncols + n];
    __nv_bfloat16 h = __float2bfloat16(w);
    H[idx] = h;
    L[idx] = __float2bfloat16(w - __bfloat162float(h));
}

// capT: [c][d][k<64], padded words
__global__ void k_capT(const float* __restrict__ cap) {
    int idx = blockIdx.x * 256 + threadIdx.x;   // 32*1024*64
    int k = idx & 63, n = (idx >> 6) & 1023, c = idx >> 16;
    float v = (k < NWD) ? cap[((size_t)c*NWD + k)*ND + n] : 0.f;
    __nv_bfloat16 h = __float2bfloat16(v);
    g_capTh[idx] = h;
    g_capTl[idx] = __float2bfloat16(v - __bfloat162float(h));
}

#define APAD 40
#define GS_STAGE 40960
#define GS_TOTAL (2*GS_STAGE)
#define DS_AH 0
#define DS_AL 10240
#define DS_BH 20480
#define DS_BL 61440
#define DS_RED 102400
#define DS_INV 103424
#define DS_TOTAL 103680

// ============ generic HMMA GEMM, cp.async double-buffered, optional batch ============
template<int ACT>
__global__ void __launch_bounds__(256)
hmma_gemm(const __nv_bfloat16* __restrict__ Ah, const __nv_bfloat16* __restrict__ Al,
          const __nv_bfloat16* __restrict__ Bh, const __nv_bfloat16* __restrict__ Bl,
          const float* __restrict__ bias, float* __restrict__ C, int N, int K,
          size_t strideA, size_t strideB, size_t strideC)
{
    extern __shared__ char smem[];
    uint32_t sb = smem_u32(smem);
    int tid = threadIdx.x, lane = tid & 31, warp = tid >> 5;
    int mw = warp >> 2, nw = warp & 3;
    int n0 = blockIdx.x * 128, m0 = blockIdx.y * 128;
    size_t zA = (size_t)blockIdx.z * strideA;
    size_t zB = (size_t)blockIdx.z * strideB;
    C += (size_t)blockIdx.z * strideC;
    const __nv_bfloat16* Ah0 = Ah + zA + (size_t)m0 * K;
    const __nv_bfloat16* Al0 = Al + zA + (size_t)m0 * K;
    const __nv_bfloat16* Bh0 = Bh + zB + (size_t)n0 * K;
    const __nv_bfloat16* Bl0 = Bl + zB + (size_t)n0 * K;

    float acc[4][4][4];
    #pragma unroll
    for (int i = 0; i < 4; i++)
        #pragma unroll
        for (int j = 0; j < 4; j++)
            #pragma unroll
            for (int e = 0; e < 4; e++) acc[i][j][e] = 0.f;

    int a_row = mw*64 + (lane & 15);
    int a_col8 = (lane >> 4) * 8;
    int b_row = nw*32 + (lane >> 4)*8 + (lane & 7);
    int b_col8 = ((lane >> 3) & 1) * 8;
    const int NCH = K / 32;

    auto issue = [&](int ch, int stage) {
        int k0 = ch * 32;
        uint32_t base = sb + stage * GS_STAGE;
        #pragma unroll
        for (int i = 0; i < 2; i++) {
            int slot = tid + i*256;
            int row = slot >> 2, c = slot & 3;
            uint32_t so = (uint32_t)(row*APAD + c*8) * 2;
            size_t src = (size_t)row*K + k0 + c*8;
            cp_async16(base + 0     + so, Ah0 + src);
            cp_async16(base + 10240 + so, Al0 + src);
            cp_async16(base + 20480 + so, Bh0 + src);
            cp_async16(base + 30720 + so, Bl0 + src);
        }
    };

    issue(0, 0); CP_COMMIT();
    for (int ch = 0; ch < NCH; ch++) {
        int stage = ch & 1;
        if (ch + 1 < NCH) { issue(ch + 1, stage ^ 1); CP_COMMIT(); CP_WAIT1(); }
        else CP_WAIT0();
        __syncthreads();
        uint32_t aA = sb + stage * GS_STAGE;
        uint32_t aAl2 = aA + 10240, aB = aA + 20480, aBl2 = aA + 30720;
        #pragma unroll
        for (int k16 = 0; k16 < 2; k16++) {
            uint32_t bh[4][2], bl[4][2];
            #pragma unroll
            for (int half = 0; half < 2; half++) {
                uint32_t off = (uint32_t)((b_row + half*16)*APAD + k16*16 + b_col8) * 2;
                uint32_t r0, r1, r2, r3;
                LDSM4(r0, r1, r2, r3, aB + off);
                bh[half*2+0][0] = r0; bh[half*2+0][1] = r1;
                bh[half*2+1][0] = r2; bh[half*2+1][1] = r3;
                LDSM4(r0, r1, r2, r3, aBl2 + off);
                bl[half*2+0][0] = r0; bl[half*2+0][1] = r1;
                bl[half*2+1][0] = r2; bl[half*2+1][1] = r3;
            }
            #pragma unroll
            for (int mt = 0; mt < 4; mt++) {
                uint32_t ah[4], al[4];
                uint32_t off = (uint32_t)((a_row + mt*16)*APAD + k16*16 + a_col8) * 2;
                LDSM4(ah[0], ah[1], ah[2], ah[3], aA + off);
                LDSM4(al[0], al[1], al[2], al[3], aAl2 + off);
                #pragma unroll
                for (int nt = 0; nt < 4; nt++) {
                    MMA_BF16(acc[mt][nt], ah, bh[nt]);
                    MMA_BF16(acc[mt][nt], ah, bl[nt]);
                    MMA_BF16(acc[mt][nt], al, bh[nt]);
                }
            }
        }
        __syncthreads();
    }

    #pragma unroll
    for (int mt = 0; mt < 4; mt++) {
        int mA = m0 + mw*64 + mt*16 + (lane >> 2);
        int mB = mA + 8;
        float* dA = C + (size_t)mA * N;
        float* dB = C + (size_t)mB * N;
        #pragma unroll
        for (int nt = 0; nt < 4; nt++) {
            int n = n0 + nw*32 + nt*8 + (lane & 3)*2;
            float b0 = 0.f, b1 = 0.f;
            if (bias) { b0 = bias[n]; b1 = bias[n+1]; }
            float v0 = acc[mt][nt][0] + b0, v1 = acc[mt][nt][1] + b1;
            float v2 = acc[mt][nt][2] + b0, v3 = acc[mt][nt][3] + b1;
            if (ACT == 1) { v0 = tanhf(v0); v1 = tanhf(v1); v2 = tanhf(v2); v3 = tanhf(v3); }
            *(float2*)&dA[n] = make_float2(v0, v1);
            *(float2*)&dB[n] = make_float2(v2, v3);
        }
    }
}

// ============ HMMA diff-square GEMM, full-N tile, pipelined ============
template<int MODE>
__global__ void __launch_bounds__(256)
hmma_diffsq(const float* __restrict__ X, const float* __restrict__ Y,
            const float* __restrict__ rowinv,
            const __nv_bfloat16* __restrict__ Bh, const __nv_bfloat16* __restrict__ Bl,
            const float* __restrict__ bias, float* __restrict__ outp)
{
    extern __shared__ char smem[];
    uint32_t sb = smem_u32(smem);
    float* sred = (float*)(smem + DS_RED);
    float* sinv = (float*)(smem + DS_INV);
    int tid = threadIdx.x;
    int lane = tid & 31, warp = tid >> 5;
    int mw = warp >> 2, nw = warp & 3;
    int m0 = blockIdx.x * 128, z = blockIdx.y;

    const float* Xp = (MODE == 0) ? X + ((size_t)z*2304 + m0)*ND : X + (size_t)m0*ND;
    const float* Yp = (MODE == 0) ? Y + (size_t)m0*ND : Y + (size_t)z*ND;
    const float* invp = (MODE == 0) ? rowinv + (size_t)z*2304 + m0 : nullptr;

    float acc[4][8][4];
    #pragma unroll
    for (int i = 0; i < 4; i++)
        #pragma unroll
        for (int j = 0; j < 8; j++)
            #pragma unroll
            for (int e = 0; e < 4; e++) acc[i][j][e] = 0.f;

    int a_row = mw*64 + (lane & 15);
    int a_col8 = (lane >> 4) * 8;
    int b_row = nw*64 + (lane >> 4)*8 + (lane & 7);
    int b_col8 = ((lane >> 3) & 1) * 8;

    int arow[4], aq[4];
    float ivr[4];
    #pragma unroll
    for (int i = 0; i < 4; i++) {
        int slot = tid + i*256;
        arow[i] = slot >> 3; aq[i] = slot & 7;
        ivr[i] = (MODE == 0) ? invp[arow[i]] : 1.f;
    }

    float4 xr[4], yr[4];
    auto load_regs = [&](int ch) {
        int k0 = ch * 32;
        #pragma unroll
        for (int i = 0; i < 4; i++) {
            size_t off = (size_t)arow[i]*ND + k0 + aq[i]*4;
            xr[i] = *(const float4*)(Xp + off);
            if (MODE == 0) yr[i] = *(const float4*)(Yp + off);
            else           yr[i] = *(const float4*)(Yp + k0 + aq[i]*4);
        }
    };
    auto issueB = [&](int ch, int stage) {
        int k0 = ch * 32;
        uint32_t bh = sb + DS_BH + stage*20480;
        uint32_t bl = sb + DS_BL + stage*20480;
        #pragma unroll
        for (int i = 0; i < 4; i++) {
            int slot = tid + i*256;
            int row = slot >> 2, c = slot & 3;
            uint32_t so = (uint32_t)(row*APAD + c*8) * 2;
            size_t src = (size_t)row*ND + k0 + c*8;
            cp_async16(bh + so, Bh + src);
            cp_async16(bl + so, Bl + src);
        }
    };

    load_regs(0);
    issueB(0, 0); CP_COMMIT();

    for (int ch = 0; ch < 32; ch++) {
        int stage = ch & 1;
        #pragma unroll
        for (int i = 0; i < 4; i++) {
            float iv = ivr[i];
            float d0, d1, d2, d3;
            if (MODE == 0) {
                d0 = xr[i].x*iv - yr[i].x; d1 = xr[i].y*iv - yr[i].y;
                d2 = xr[i].z*iv - yr[i].z; d3 = xr[i].w*iv - yr[i].w;
            } else {
                d0 = xr[i].x - yr[i].x; d1 = xr[i].y - yr[i].y;
                d2 = xr[i].z - yr[i].z; d3 = xr[i].w - yr[i].w;
            }
            float a0 = d0*d0, a1 = d1*d1, a2 = d2*d2, a3 = d3*d3;
            __nv_bfloat162 h01 = __floats2bfloat162_rn(a0, a1);
            __nv_bfloat162 h23 = __floats2bfloat162_rn(a2, a3);
            float r0 = a0 - __bfloat162float(h01.x);
            float r1 = a1 - __bfloat162float(h01.y);
            float r2 = a2 - __bfloat162float(h23.x);
            float r3 = a3 - __bfloat162float(h23.y);
            __nv_bfloat162 l01 = __floats2bfloat162_rn(r0, r1);
            __nv_bfloat162 l23 = __floats2bfloat162_rn(r2, r3);
            uint32_t so = (uint32_t)(arow[i]*APAD + aq[i]*4) * 2;
            *(uint2*)(smem + DS_AH + so) = make_uint2(*(uint32_t*)&h01, *(uint32_t*)&h23);
            *(uint2*)(smem + DS_AL + so) = make_uint2(*(uint32_t*)&l01, *(uint32_t*)&l23);
        }
        if (ch < 31) {
            load_regs(ch + 1);
            issueB(ch + 1, stage ^ 1); CP_COMMIT();
            CP_WAIT1();
        } else {
            CP_WAIT0();
        }
        __syncthreads();
        uint32_t aAh = sb + DS_AH, aAl = sb + DS_AL;
        uint32_t aBh = sb + DS_BH + stage*20480;
        uint32_t aBl = sb + DS_BL + stage*20480;
        #pragma unroll
        for (int k16 = 0; k16 < 2; k16++) {
            uint32_t bh[8][2], bl[8][2];
            #pragma unroll
            for (int p = 0; p < 4; p++) {
                uint32_t off = (uint32_t)((b_row + p*16)*APAD + k16*16 + b_col8) * 2;
                uint32_t r0, r1, r2, r3;
                LDSM4(r0, r1, r2, r3, aBh + off);
                bh[p*2+0][0] = r0; bh[p*2+0][1] = r1;
                bh[p*2+1][0] = r2; bh[p*2+1][1] = r3;
                LDSM4(r0, r1, r2, r3, aBl + off);
                bl[p*2+0][0] = r0; bl[p*2+0][1] = r1;
                bl[p*2+1][0] = r2; bl[p*2+1][1] = r3;
            }
            #pragma unroll
            for (int mt = 0; mt < 4; mt++) {
                uint32_t ah[4], al[4];
                uint32_t off = (uint32_t)((a_row + mt*16)*APAD + k16*16 + a_col8) * 2;
                LDSM4(ah[0], ah[1], ah[2], ah[3], aAh + off);
                LDSM4(al[0], al[1], al[2], al[3], aAl + off);
                #pragma unroll
                for (int nt = 0; nt < 8; nt++) {
                    MMA_BF16(acc[mt][nt], ah, bh[nt]);
                    MMA_BF16(acc[mt][nt], ah, bl[nt]);
                    MMA_BF16(acc[mt][nt], al, bh[nt]);
                }
            }
        }
        __syncthreads();
    }

    #pragma unroll
    for (int mt = 0; mt < 4; mt++) {
        int lmA = mw*64 + mt*16 + (lane >> 2);
        int lmB = lmA + 8;
        int mA = m0 + lmA, mB = m0 + lmB;
        float vA[8][2], vB[8][2];
        float ssqA = 0.f, ssqB = 0.f;
        #pragma unroll
        for (int nt = 0; nt < 8; nt++) {
            int n = nw*64 + nt*8 + (lane & 3)*2;
            float b0 = bias[n], b1 = bias[n+1];
            vA[nt][0] = fmaxf(acc[mt][nt][0] + b0, 0.f);
            vA[nt][1] = fmaxf(acc[mt][nt][1] + b1, 0.f);
            vB[nt][0] = fmaxf(acc[mt][nt][2] + b0, 0.f);
            vB[nt][1] = fmaxf(acc[mt][nt][3] + b1, 0.f);
            if (MODE == 0) {
                ssqA += vA[nt][0]*vA[nt][0] + vA[nt][1]*vA[nt][1];
                ssqB += vB[nt][0]*vB[nt][0] + vB[nt][1]*vB[nt][1];
            }
        }
        float invA = 1.f, invB = 1.f;
        if (MODE == 0) {
            ssqA += __shfl_xor_sync(0xffffffffu, ssqA, 1);
            ssqA += __shfl_xor_sync(0xffffffffu, ssqA, 2);
            ssqB += __shfl_xor_sync(0xffffffffu, ssqB, 1);
            ssqB += __shfl_xor_sync(0xffffffffu, ssqB, 2);
            if ((lane & 3) == 0) {
                sred[nw*64 + mw*32 + (lane >> 2)] = ssqA;
                sred[nw*64 + mw*32 + 16 + (lane >> 2)] = ssqB;
            }
            __syncthreads();
            if (tid < 64) {
                float s = sred[0*64 + tid] + sred[1*64 + tid] + sred[2*64 + tid] + sred[3*64 + tid];
                sinv[tid] = 1.f / (sqrtf(s) + EPSL);
            }
            __syncthreads();
            invA = sinv[mw*32 + (lane >> 2)];
            invB = sinv[mw*32 + 16 + (lane >> 2)];
        }
        float* dA;
        float* dB;
        if (MODE == 0) {
            int bA = mA / NR, rA2 = mA % NR;
            int bB = mB / NR, rB2 = mB % NR;
            dA = outp + (((size_t)z*NB + bA)*37 + 1 + rA2)*NS;
            dB = outp + (((size_t)z*NB + bB)*37 + 1 + rB2)*NS;
        } else {
            dA = outp + ((size_t)z*2304 + mA)*NS;
            dB = outp + ((size_t)z*2304 + mB)*NS;
        }
        #pragma unroll
        for (int nt = 0; nt < 8; nt++) {
            int n = nw*64 + nt*8 + (lane & 3)*2;
            *(float2*)&dA[n] = make_float2(vA[nt][0]*invA, vA[nt][1]*invA);
            *(float2*)&dB[n] = make_float2(vB[nt][0]*invB, vB[nt][1]*invB);
        }
        if (MODE == 0) __syncthreads();
    }
}

// ============ small-M GEMM via split-K ============
__global__ void gemm_small_part(const float* __restrict__ A, const float* __restrict__ W,
                                float* __restrict__ part, int M, int N, int K)
{
    const int BK = 16;
    __shared__ float As[BK][64];
    __shared__ float Bs[BK][64];
    int tid = threadIdx.x, tr = tid >> 4, tc = tid & 15;
    int n0 = blockIdx.x * 64;
    int KS = gridDim.y;
    int Kc = K / KS;
    int kz = blockIdx.y;
    float acc[4][4] = {};
    for (int k0 = kz*Kc; k0 < (kz+1)*Kc; k0 += BK) {
        for (int i = tid; i < 64*BK; i += 256) {
            int m = i >> 4, k = i & 15;
            As[k][m] = (m < M) ? A[(size_t)m*K + k0 + k] : 0.f;
        }
        for (int i = tid; i < BK*64; i += 256) {
            int k = i >> 6, n = i & 63;
            Bs[k][n] = W[(size_t)(k0+k)*N + n0 + n];
        }
        __syncthreads();
        #pragma unroll
        for (int k = 0; k < BK; k++) {
            float a[4], b[4];
            #pragma unroll
            for (int i = 0; i < 4; i++) a[i] = As[k][tr*4+i];
            #pragma unroll
            for (int j = 0; j < 4; j++) b[j] = Bs[k][tc*4+j];
            #pragma unroll
            for (int i = 0; i < 4; i++)
                #pragma unroll
                for (int j = 0; j < 4; j++) acc[i][j] += a[i]*b[j];
        }
        __syncthreads();
    }
    #pragma unroll
    for (int i = 0; i < 4; i++) {
        int m = tr*4 + i;
        if (m >= M) continue;
        #pragma unroll
        for (int j = 0; j < 4; j++)
            part[((size_t)kz*M + m)*N + n0 + tc*4 + j] = acc[i][j];
    }
}

template<int ACT>
__global__ void k_small_epi(const float* __restrict__ part, const float* __restrict__ bias,
                            float* __restrict__ C, int M, int N, int KS)
{
    int idx = blockIdx.x*256 + threadIdx.x;
    if (idx >= M*N) return;
    int n = idx % N;
    float s = 0.f;
    for (int kz = 0; kz < KS; kz++) s += part[(size_t)kz*M*N + idx];
    s += bias[n];
    if (ACT == 1) s = tanhf(s);
    C[idx] = s;
}

// ---------------- tiny glo diff-square GEMM ----------------
__global__ void gemm_diffsq_glo(const float* __restrict__ X, const float* __restrict__ Y,
                                const float* __restrict__ W, const float* __restrict__ bias,
                                float* __restrict__ Cbase, int M, int N, int K)
{
    const int BM = 64, BN = 64, BK = 16;
    int c = blockIdx.z;
    const float* Yp = Y + (size_t)c*K;
    __shared__ float As[BK][BM];
    __shared__ float Bs[BK][BN];
    int tid = threadIdx.x;
    int tr = tid >> 4, tc = tid & 15;
    int m0 = blockIdx.y * BM, n0 = blockIdx.x * BN;
    float acc[4][4] = {};
    for (int k0 = 0; k0 < K; k0 += BK) {
        #pragma unroll
        for (int i = tid; i < BM*BK; i += 256) {
            int m = i >> 4, k = i & 15;
            float v = 0.f;
            if (m0 + m < M) {
                float d = X[(size_t)(m0+m)*K + k0 + k] - Yp[k0 + k];
                v = d * d;
            }
            As[k][m] = v;
        }
        #pragma unroll
        for (int i = tid; i < BK*BN; i += 256) {
            int k = i >> 6, n = i & 63;
            Bs[k][n] = W[(size_t)(k0+k)*N + n0 + n];
        }
        __syncthreads();
        #pragma unroll
        for (int k = 0; k < BK; k++) {
            float a[4], b[4];
            #pragma unroll
            for (int i = 0; i < 4; i++) a[i] = As[k][tr*4+i];
            #pragma unroll
            for (int j = 0; j < 4; j++) b[j] = Bs[k][tc*4+j];
            #pragma unroll
            for (int i = 0; i < 4; i++)
                #pragma unroll
                for (int j = 0; j < 4; j++) acc[i][j] += a[i]*b[j];
        }
        __syncthreads();
    }
    #pragma unroll
    for (int i = 0; i < 4; i++) {
        int m = m0 + tr*4 + i;
        if (m >= M) continue;
        #pragma unroll
        for (int j = 0; j < 4; j++) {
            int n = n0 + tc*4 + j;
            float v = fmaxf(acc[i][j] + bias[n], 0.f);
            Cbase[(size_t)c*M*N + (size_t)m*N + n] = v;
        }
    }
}

// ---------------- small kernels ----------------
__global__ void k_imgave(const float* __restrict__ img) {
    int i = blockIdx.x*blockDim.x + threadIdx.x;
    int b = i >> 10, d = i & 1023;
    float s = 0.f;
    for (int r = 0; r < NR; r++) s += img[((size_t)b*NR + r)*ND + d];
    g_imgave[i] = s * (1.f / NR);
}

__global__ void k_bnstats() {
    int r = blockIdx.x;
    __shared__ float red[256], red2[256];
    float s = 0.f, ss = 0.f;
    for (int i = threadIdx.x; i < NB*ND; i += 256) {
        int b = i >> 10, d = i & 1023;
        float v = g_h[((size_t)b*NR + r)*ND + d];
        s += v; ss += v*v;
    }
    red[threadIdx.x] = s; red2[threadIdx.x] = ss; __syncthreads();
    for (int st = 128; st > 0; st >>= 1) {
        if (threadIdx.x < st) { red[threadIdx.x] += red[threadIdx.x+st]; red2[threadIdx.x] += red2[threadIdx.x+st]; }
        __syncthreads();
    }
    if (threadIdx.x == 0) {
        float mu = red[0] / (float)(NB*ND);
        g_bnmu[r] = mu;
        g_bnvar[r] = red2[0] / (float)(NB*ND) - mu*mu;
    }
}

__global__ void k_gbn(const float* __restrict__ gamma, const float* __restrict__ beta) {
    int d = blockIdx.x*blockDim.x + threadIdx.x;
    float s = 0.f, ss = 0.f;
    for (int b = 0; b < NB; b++) { float v = g_g[(size_t)b*ND + d]; s += v; ss += v*v; }
    float mu = s / NB;
    float var = ss / NB - mu*mu;
    float inv = rsqrtf(var + BNEPS);
    float ga = gamma[d], be = beta[d];
    for (int b = 0; b < NB; b++) {
        float v = g_g[(size_t)b*ND + d];
        g_g[(size_t)b*ND + d] = tanhf((v - mu)*inv*ga + be);
    }
}

__global__ void k_wraw(const float* __restrict__ vcw, const float* __restrict__ vcb,
                       const float* __restrict__ lg, const float* __restrict__ lb) {
    int br = blockIdx.x;
    int b = br / NR, r = br % NR;
    __shared__ float red[256];
    float mu = g_bnmu[r], inv = rsqrtf(g_bnvar[r] + BNEPS);
    float ga = lg[r], be = lb[r];
    float s = 0.f;
    for (int d = threadIdx.x; d < ND; d += 256) {
        float le = tanhf((g_h[(size_t)br*ND + d] - mu)*inv*ga + be);
        s += le * g_g[(size_t)b*ND + d] * vcw[d];
    }
    float tot = blockReduceSum256(s, red);
    if (threadIdx.x == 0) g_wraw[br] = tot + vcb[0];
}

__global__ void k_newglobal(const float* __restrict__ img) {
    int b = blockIdx.x;
    __shared__ float w[NR];
    __shared__ float red[256];
    __shared__ float invn;
    if (threadIdx.x == 0) {
        float mx = -1e30f;
        for (int r = 0; r < NR; r++) mx = fmaxf(mx, g_wraw[b*NR + r]);
        float sum = 0.f;
        for (int r = 0; r < NR; r++) { w[r] = expf(g_wraw[b*NR + r] - mx); sum += w[r]; }
        float is = 1.f / sum;
        for (int r = 0; r < NR; r++) w[r] *= is;
    }
    __syncthreads();
    float ssq = 0.f;
    for (int d = threadIdx.x; d < ND; d += 256) {
        float s = 0.f;
        for (int r = 0; r < NR; r++) s += w[r] * img[((size_t)b*NR + r)*ND + d];
        g_imgglo[(size_t)b*ND + d] = s;
        ssq += s*s;
    }
    float tot = blockReduceSum256(ssq, red);
    if (threadIdx.x == 0) {
        float nrm = sqrtf(tot) + EPSL;
        g_normglo[b] = nrm;
        invn = 1.f / nrm;
    }
    __syncthreads();
    for (int d = threadIdx.x; d < ND; d += 256) g_imgglo[(size_t)b*ND + d] *= invn;
}

__global__ void k_imgpar(const float* __restrict__ img, const int* __restrict__ adjs) {
    int br = blockIdx.x;
    int b = br / NR, r = br % NR;
    __shared__ int eff[NPART];
    __shared__ float wg[NPART];
    if (threadIdx.x == 0) {
        int cnt = 0;
        const int* row = adjs + (size_t)b*NR*NR + (size_t)r*NR;
        for (int j = 0; j < NR && cnt < NPART; j++)
            if (row[j] == 1) eff[cnt++] = j;
        for (; cnt < NPART; cnt++) eff[cnt] = r;
        float v[NPART], mx = -1e30f;
        for (int k = 0; k < NPART; k++) { v[k] = g_wraw[b*NR + eff[k]]; mx = fmaxf(mx, v[k]); }
        float sum = 0.f;
        for (int k = 0; k < NPART; k++) { v[k] = expf(v[k] - mx); sum += v[k]; }
        float is = 1.f / sum;
        for (int k = 0; k < NPART; k++) wg[k] = v[k]*is;
    }
    __syncthreads();
    float invn = 1.f / g_normglo[b];
    for (int d = threadIdx.x; d < ND; d += 256) {
        float s = 0.f;
        #pragma unroll
        for (int k = 0; k < NPART; k++) s += wg[k] * img[((size_t)b*NR + eff[k])*ND + d];
        g_imgpar[(size_t)br*ND + d] = s * invn;
    }
}

__global__ void k_capave(const float* __restrict__ cap) {
    int i = blockIdx.x*blockDim.x + threadIdx.x;
    int c = i >> 10, d = i & 1023;
    float s = 0.f;
    for (int n = 0; n < NWD; n++) s += cap[((size_t)c*NWD + n)*ND + d];
    g_capave[i] = s * (1.f / NWD);
}

__global__ void k_capglo(const float* __restrict__ cap, const float* __restrict__ tsacw,
                         const float* __restrict__ tsacb) {
    int c = blockIdx.x;
    __shared__ float red[256];
    __shared__ float cw[NWD];
    __shared__ float invn;
    float gw[4];
    #pragma unroll
    for (int i = 0; i < 4; i++) {
        int d = threadIdx.x + i*256;
        gw[i] = g_ge[(size_t)c*ND + d] * tsacw[d];
    }
    for (int n = 0; n < NWD; n++) {
        float s = 0.f;
        #pragma unroll
        for (int i = 0; i < 4; i++) {
            int d = threadIdx.x + i*256;
            s += g_le[((size_t)c*NWD + n)*ND + d] * gw[i];
        }
        float tot = blockReduceSum256(s, red);
        if (threadIdx.x == 0) cw[n] = tot + tsacb[0];
    }
    __syncthreads();
    if (threadIdx.x == 0) {
        float mx = -1e30f;
        for (int n = 0; n < NWD; n++) mx = fmaxf(mx, cw[n]);
        float sum = 0.f;
        for (int n = 0; n < NWD; n++) { cw[n] = expf(cw[n] - mx); sum += cw[n]; }
        float is = 1.f / sum;
        for (int n = 0; n < NWD; n++) cw[n] *= is;
    }
    __syncthreads();
    float ssq = 0.f;
    #pragma unroll
    for (int i = 0; i < 4; i++) {
        int d = threadIdx.x + i*256;
        float s = 0.f;
        for (int n = 0; n < NWD; n++) s += cw[n] * cap[((size_t)c*NWD + n)*ND + d];
        g_capglo[(size_t)c*ND + d] = s;
        ssq += s*s;
    }
    float tot = blockReduceSum256(ssq, red);
    if (threadIdx.x == 0) invn = 1.f / (sqrtf(tot) + EPSL);
    __syncthreads();
    #pragma unroll
    for (int i = 0; i < 4; i++) {
        int d = threadIdx.x + i*256;
        g_capglo[(size_t)c*ND + d] *= invn;
    }
}

// attnfuse: writes split-bf16 padded attnT [c][b*36+r][64]
__global__ void k_attnfuse() {
    int cb = blockIdx.x;
    int c = cb / NB, b = cb % NB;
    __shared__ float sA[NWD*NR];
    __shared__ float nrm[NWD];
    const float* raw = g_attnraw + (size_t)c*NWD*NB*NR;
    for (int i = threadIdx.x; i < NWD*NR; i += 256) {
        int n = i / NR, r = i % NR;
        float v = raw[(size_t)n*NB*NR + (size_t)b*NR + r];
        v = (v > 0.f) ? v : 0.1f*v;
        sA[i] = v;
    }
    __syncthreads();
    if (threadIdx.x < NWD) {
        int n = threadIdx.x;
        float s = 0.f;
        for (int r = 0; r < NR; r++) { float v = sA[n*NR + r]; s += v*v; }
        nrm[n] = 1.f / (sqrtf(s) + EPSL);
    }
    __syncthreads();
    if (threadIdx.x < NR) {
        int r = threadIdx.x;
        float vals[NWD];
        float mx = -1e30f;
        for (int n = 0; n < NWD; n++) {
            float v = SMOOTHF * sA[n*NR + r] * nrm[n];
            vals[n] = v;
            mx = fmaxf(mx, v);
        }
        float sum = 0.f;
        for (int n = 0; n < NWD; n++) { vals[n] = expf(vals[n] - mx); sum += vals[n]; }
        float is = 1.f / sum;
        size_t base = ((size_t)cb*NR + r) * 64;
        for (int n = 0; n < 64; n++) {
            float w = (n < NWD) ? vals[n]*is : 0.f;
            __nv_bfloat16 h = __float2bfloat16(w);
            g_attnTh[base + n] = h;
            g_attnTl[base + n] = __float2bfloat16(w - __bfloat162float(h));
        }
    }
}

__global__ void k_ctxssq() {
    int row = blockIdx.x * 8 + (threadIdx.x >> 5);
    int lane = threadIdx.x & 31;
    const float* p = g_ctx + (size_t)row * ND;
    float s = 0.f;
    #pragma unroll
    for (int i = 0; i < 8; i++) {
        float4 v = *(const float4*)(p + lane*4 + i*128);
        s += v.x*v.x + v.y*v.y + v.z*v.z + v.w*v.w;
    }
    s = warpReduceSum(s);
    if (lane == 0) g_ctxinv[row] = 1.f / (sqrtf(s) + EPSL);
}

__global__ void k_rownorm(float* __restrict__ X, int L) {
    size_t row = blockIdx.x;
    float* p = X + row*(size_t)L;
    __shared__ float red[256];
    __shared__ float invn;
    float s = 0.f;
    for (int i = threadIdx.x; i < L; i += 256) { float v = p[i]; s += v*v; }
    float tot = blockReduceSum256(s, red);
    if (threadIdx.x == 0) invn = 1.f / (sqrtf(tot) + EPSL);
    __syncthreads();
    for (int i = threadIdx.x; i < L; i += 256) p[i] *= invn;
}

__global__ void k_finalize(const float* __restrict__ simw, const float* __restrict__ simb,
                           const float* __restrict__ lng, const float* __restrict__ lnb,
                           float* __restrict__ out, size_t out2off) {
    int cb = blockIdx.x;
    int tid = threadIdx.x;
    int lane = tid & 31, warp = tid >> 5;
    const float* sg = out + out2off + (size_t)cb*NS;
    __shared__ float sSgw[NS];
    __shared__ float wv[NR];
    __shared__ float mv[2];
    float sgv = sg[tid];
    sSgw[tid] = sgv * simw[tid];
    __syncthreads();
    const float* sp = g_simpar + (size_t)cb*NR*NS;
    for (int r = warp; r < NR; r += 8) {
        const float* row = sp + (size_t)r*NS;
        float dot = 0.f, ss = 0.f;
        #pragma unroll
        for (int i = 0; i < 8; i++) {
            int c = lane + i*32;
            float v = row[c];
            dot += v * sSgw[c];
            ss += v * v;
        }
        dot = warpReduceSum(dot);
        ss = warpReduceSum(ss);
        if (lane == 0) wv[r] = dot / (sqrtf(ss) + EPSL) + simb[0];
    }
    __syncthreads();
    if (tid == 0) {
        float m = 0.f;
        for (int r = 0; r < NR; r++) m += wv[r];
        m /= NR;
        float v = 0.f;
        for (int r = 0; r < NR; r++) { float d = wv[r] - m; v += d*d; }
        v /= NR;
        mv[0] = m; mv[1] = rsqrtf(v + LNEPS);
    }
    __syncthreads();
    if (tid < NR) {
        int r = tid;
        float z = (wv[r] - mv[0])*mv[1]*lng[r] + lnb[r];
        wv[r] = 1.f / (1.f + expf(-z));
    }
    __syncthreads();
    float* ob = out + (size_t)cb*37*NS;
    ob[tid] = sgv;
    for (int r = 0; r < NR; r++) ob[(size_t)(1+r)*NS + tid] *= wv[r];
}

// ---------------- host ----------------
extern "C" void kernel_launch(void* const* d_in, const int* in_sizes, int n_in,
                              void* d_out, int out_size) {
    (void)in_sizes; (void)n_in; (void)out_size;
    const float* img    = (const float*)d_in[0];
    const float* cap    = (const float*)d_in[1];
    const int*   adjs   = (const int*)d_in[3];
    const float* tsa_lw = (const float*)d_in[5];
    const float* tsa_lb = (const float*)d_in[6];
    const float* tsa_gw = (const float*)d_in[7];
    const float* tsa_gb = (const float*)d_in[8];
    const float* tsa_cw = (const float*)d_in[9];
    const float* tsa_cb = (const float*)d_in[10];
    const float* vl_w   = (const float*)d_in[11];
    const float* vl_b   = (const float*)d_in[12];
    const float* vbn_lg = (const float*)d_in[13];
    const float* vbn_lb = (const float*)d_in[14];
    const float* vg_w   = (const float*)d_in[15];
    const float* vg_b   = (const float*)d_in[16];
    const float* vbn_gg = (const float*)d_in[17];
    const float* vbn_gb = (const float*)d_in[18];
    const float* vc_w   = (const float*)d_in[19];
    const float* vc_b   = (const float*)d_in[20];
    const float* loc_w  = (const float*)d_in[21];
    const float* loc_b  = (const float*)d_in[22];
    const float* par_w  = (const float*)d_in[23];
    const float* par_b  = (const float*)d_in[24];
    const float* glo_w  = (const float*)d_in[25];
    const float* glo_b  = (const float*)d_in[26];
    const float* sim_w  = (const float*)d_in[27];
    const float* sim_b  = (const float*)d_in[28];
    const float* ln_g   = (const float*)d_in[29];
    const float* ln_b   = (const float*)d_in[30];
    float* out = (float*)d_out;

    static bool inited = false;
    static float *p_h, *p_imgave, *p_g, *p_ge, *p_le, *p_attnraw,
                 *p_ctx, *p_ctxinv, *p_imgpar, *p_imgglo, *p_capglo, *p_simpar, *p_part, *p_capave;
    static __nv_bfloat16 *p_wth, *p_wtl, *p_imgh, *p_imgl, *p_caph, *p_capl, *p_wbh, *p_wbl,
                         *p_attnTh, *p_attnTl, *p_capTh, *p_capTl;
    static cudaStream_t s1;
    static cudaEvent_t evFork, evJoin;
    if (!inited) {
        cudaGetSymbolAddress((void**)&p_h, g_h);
        cudaGetSymbolAddress((void**)&p_imgave, g_imgave);
        cudaGetSymbolAddress((void**)&p_g, g_g);
        cudaGetSymbolAddress((void**)&p_ge, g_ge);
        cudaGetSymbolAddress((void**)&p_le, g_le);
        cudaGetSymbolAddress((void**)&p_attnraw, g_attnraw);
        cudaGetSymbolAddress((void**)&p_ctx, g_ctx);
        cudaGetSymbolAddress((void**)&p_ctxinv, g_ctxinv);
        cudaGetSymbolAddress((void**)&p_imgpar, g_imgpar);
        cudaGetSymbolAddress((void**)&p_imgglo, g_imgglo);
        cudaGetSymbolAddress((void**)&p_capglo, g_capglo);
        cudaGetSymbolAddress((void**)&p_simpar, g_simpar);
        cudaGetSymbolAddress((void**)&p_part, g_part);
        cudaGetSymbolAddress((void**)&p_capave, g_capave);
        cudaGetSymbolAddress((void**)&p_wth, g_wth);
        cudaGetSymbolAddress((void**)&p_wtl, g_wtl);
        cudaGetSymbolAddress((void**)&p_imgh, g_imgh);
        cudaGetSymbolAddress((void**)&p_imgl, g_imgl);
        cudaGetSymbolAddress((void**)&p_caph, g_caph);
        cudaGetSymbolAddress((void**)&p_capl, g_capl);
        cudaGetSymbolAddress((void**)&p_wbh, g_wbh);
        cudaGetSymbolAddress((void**)&p_wbl, g_wbl);
        cudaGetSymbolAddress((void**)&p_attnTh, g_attnTh);
        cudaGetSymbolAddress((void**)&p_attnTl, g_attnTl);
        cudaGetSymbolAddress((void**)&p_capTh, g_capTh);
        cudaGetSymbolAddress((void**)&p_capTl, g_capTl);
        cudaFuncSetAttribute(hmma_gemm<0>, cudaFuncAttributeMaxDynamicSharedMemorySize, GS_TOTAL);
        cudaFuncSetAttribute(hmma_gemm<1>, cudaFuncAttributeMaxDynamicSharedMemorySize, GS_TOTAL);
        cudaFuncSetAttribute(hmma_diffsq<0>, cudaFuncAttributeMaxDynamicSharedMemorySize, DS_TOTAL);
        cudaFuncSetAttribute(hmma_diffsq<1>, cudaFuncAttributeMaxDynamicSharedMemorySize, DS_TOTAL);
        cudaStreamCreateWithFlags(&s1, cudaStreamNonBlocking);
        cudaEventCreateWithFlags(&evFork, cudaEventDisableTiming);
        cudaEventCreateWithFlags(&evJoin, cudaEventDisableTiming);
        inited = true;
    }

    const size_t out2off = (size_t)NCAP*NB*37*NS;
    float* out2 = out + out2off;

    // ---- early launches, ordered so ncu (-s 5 -c 1) profiles hmma_gemm(h) ----
    k_split<<<(NB*NR*ND+255)/256, 256>>>(img, p_imgh, p_imgl, NB*NR*ND);                 // 1
    k_wsplitT<<<(ND*ND+255)/256, 256>>>(vl_w, p_wbh, p_wbl, ND, ND);                     // 2
    k_split<<<(NCAP*NWD*ND+255)/256, 256>>>(cap, p_caph, p_capl, NCAP*NWD*ND);           // 3
    k_wsplitT<<<(ND*ND+255)/256, 256>>>(tsa_lw, p_wbh + ND*ND, p_wbl + ND*ND, ND, ND);   // 4
    k_imgave<<<256, 256>>>(img);                                                         // 5
    hmma_gemm<0><<<dim3(8, 18), 256, GS_TOTAL>>>(p_imgh, p_imgl, p_wbh, p_wbl,
                                                 vl_b, p_h, ND, ND, 0, 0, 0);            // 6
    k_wsplitT<<<(NS*ND+255)/256, 256>>>(loc_w, p_wth,         p_wtl,         NS, ND);
    k_wsplitT<<<(NS*ND+255)/256, 256>>>(par_w, p_wth + NS*ND, p_wtl + NS*ND, NS, ND);
    k_capT<<<(NCAP*ND*64+255)/256, 256>>>(cap);

    // ---- caption-independent ----
    k_bnstats<<<NR, 256>>>();
    gemm_small_part<<<dim3(16, 8), 256>>>(p_imgave, vg_w, p_part, NB, ND, ND);
    k_small_epi<0><<<(NB*ND+255)/256, 256>>>(p_part, vg_b, p_g, NB, ND, 8);
    k_gbn<<<4, 256>>>(vbn_gg, vbn_gb);
    k_wraw<<<NB*NR, 256>>>(vc_w, vc_b, vbn_lg, vbn_lb);
    k_newglobal<<<NB, 256>>>(img);
    k_imgpar<<<NB*NR, 256>>>(img, adjs);

    // ---- caption side ----
    k_capave<<<128, 256>>>(cap);
    hmma_gemm<1><<<dim3(8, 10), 256, GS_TOTAL>>>(p_caph, p_capl, p_wbh + ND*ND, p_wbl + ND*ND,
                                                 tsa_lb, p_le, ND, ND, 0, 0, 0);
    gemm_small_part<<<dim3(16, 8), 256>>>(p_capave, tsa_gw, p_part, NCAP, ND, ND);
    k_small_epi<1><<<(NCAP*ND+255)/256, 256>>>(p_part, tsa_gb, p_ge, NCAP, ND, 8);
    k_capglo<<<NCAP, 256>>>(cap, tsa_cw, tsa_cb);

    // ---- fork: independent branch on s1 (simpar + sim_glo) ----
    cudaEventRecord(evFork, 0);
    cudaStreamWaitEvent(s1, evFork, 0);
    hmma_diffsq<1><<<dim3(18, NCAP), 256, DS_TOTAL, s1>>>(p_imgpar, p_capglo, nullptr,
                                                          p_wth + NS*ND, p_wtl + NS*ND, par_b, p_simpar);
    gemm_diffsq_glo<<<dim3(4, 1, NCAP), 256, 0, s1>>>(p_imgglo, p_capglo, glo_w, glo_b, out2, NB, NS, ND);
    k_rownorm<<<NCAP*NB, 256, 0, s1>>>(out2, NS);
    cudaEventRecord(evJoin, s1);

    // ---- main branch: attn -> ctx -> diffsq0 ----
    hmma_gemm<0><<<dim3(18, 10), 256, GS_TOTAL>>>(p_caph, p_capl, p_imgh, p_imgl,
                                                  nullptr, p_attnraw, NB*NR, ND, 0, 0, 0);
    k_attnfuse<<<NCAP*NB, 256>>>();
    // ctx = attnT @ capT per caption (batched, K=64)
    hmma_gemm<0><<<dim3(8, 18, NCAP), 256, GS_TOTAL>>>(p_attnTh, p_attnTl, p_capTh, p_capTl,
                                                       nullptr, p_ctx, ND, 64,
                                                       (size_t)2304*64, (size_t)ND*64, (size_t)2304*ND);
    k_ctxssq<<<NCAP*NB*NR/8, 256>>>();
    hmma_diffsq<0><<<dim3(18, NCAP), 256, DS_TOTAL>>>(p_ctx, img, p_ctxinv, p_wth, p_wtl, loc_b, out);

    // ---- join + finalize ----
    cudaStreamWaitEvent(0, evJoin, 0);
    k_finalize<<<NCAP*NB, 256>>>(sim_w, sim_b, ln_g, ln_b, out, out2off);
}